// round 8
// baseline (speedup 1.0000x reference)
#include <cuda_runtime.h>
#include <cuda_bf16.h>
#include <cuda_fp16.h>
#include <math.h>
#include <stdint.h>

#define T 2048
#define H 1024
#define NH 8
#define NKV 2
#define HD 128
#define NE 16
#define QKV_N 1536
#define FDIM 1024
#define PAD_ROWS 10240

typedef __nv_bfloat16 bf16;
typedef __nv_bfloat162 bf162;
typedef __half f16;

// ---------------- fp32 scratch ----------------------------------------------
__device__ float g_resid[T * H];
__device__ float g_h[T * H];
__device__ float g_qkv[T * QKV_N];
__device__ float g_scores[(size_t)NH * T * T];
__device__ float g_gu[(size_t)PAD_ROWS * 2048];
__device__ float g_logits[T * NE];
__device__ int   g_cnt[NE];
__device__ int   g_poff[NE];
__device__ int   g_ptok[NE * T];
__device__ float g_pw[NE * T];

// ---------------- bf16 hi/lo operand buffers (router-critical path) ----------
__device__ bf16 g_hh[T * H],  g_hl[T * H];
__device__ bf16 g_qh[T * NH * HD], g_ql[T * NH * HD];
__device__ bf16 g_kh[T * NKV * HD], g_kl[T * NKV * HD];
__device__ bf16 g_vh[T * NKV * HD], g_vl[T * NKV * HD];
__device__ bf16 g_ph[(size_t)NH * T * T], g_pl[(size_t)NH * T * T];
__device__ bf16 g_ch[T * 1024], g_cl[T * 1024];
__device__ bf16 g_wqkvh[H * QKV_N], g_wqkvl[H * QKV_N];
__device__ bf16 g_wdh[H * H], g_wdl[H * H];

// ---------------- fp16 operands (post-routing path, 2-term) ------------------
__device__ f16 g_h2h[T * H], g_h2l[T * H];
__device__ f16 g_ash[T * FDIM], g_asl[T * FDIM];
__device__ f16 g_amh[(size_t)PAD_ROWS * 1024], g_aml[(size_t)PAD_ROWS * 1024];
__device__ f16 g_w13f[(size_t)NE * H * 2048];
__device__ f16 g_w2f[(size_t)NE * FDIM * H];
__device__ f16 g_wsguf[H * 2048];
__device__ f16 g_wsdf[FDIM * H];

// ---------------- helpers ----------------------------------------------------
__device__ __forceinline__ void split_bf(float v, bf16& h, bf16& l) {
    h = __float2bfloat16(v);
    l = __float2bfloat16(v - __bfloat162float(h));
}
__device__ __forceinline__ void split2(float a, float b, bf162& h2, bf162& l2) {
    bf16 ha, la, hb, lb;
    split_bf(a, ha, la);
    split_bf(b, hb, lb);
    h2 = bf162{ha, hb};
    l2 = bf162{la, lb};
}
__device__ __forceinline__ void split_f16(float v, f16& h, f16& l) {
    h = __float2half(v);
    l = __float2half(v - __half2float(h));
}
__device__ __forceinline__ void mma16816(float* c, const uint32_t* a,
                                         const uint32_t* b) {
    asm volatile(
        "mma.sync.aligned.m16n8k16.row.col.f32.bf16.bf16.f32 "
        "{%0,%1,%2,%3}, {%4,%5,%6,%7}, {%8,%9}, {%0,%1,%2,%3};\n"
        : "+f"(c[0]), "+f"(c[1]), "+f"(c[2]), "+f"(c[3])
        : "r"(a[0]), "r"(a[1]), "r"(a[2]), "r"(a[3]), "r"(b[0]), "r"(b[1]));
}
__device__ __forceinline__ void mma16816f(float* c, const uint32_t* a,
                                          const uint32_t* b) {
    asm volatile(
        "mma.sync.aligned.m16n8k16.row.col.f32.f16.f16.f32 "
        "{%0,%1,%2,%3}, {%4,%5,%6,%7}, {%8,%9}, {%0,%1,%2,%3};\n"
        : "+f"(c[0]), "+f"(c[1]), "+f"(c[2]), "+f"(c[3])
        : "r"(a[0]), "r"(a[1]), "r"(a[2]), "r"(a[3]), "r"(b[0]), "r"(b[1]));
}
template <int N> __device__ __forceinline__ void cp_wait() {
    asm volatile("cp.async.wait_group %0;\n" ::"n"(N));
}
__device__ __forceinline__ void cp16(const void* src, void* dst) {
    uint32_t d = (uint32_t)__cvta_generic_to_shared(dst);
    asm volatile("cp.async.ca.shared.global [%0], [%1], 16;\n" ::"r"(d),
                 "l"(src));
}
__device__ __forceinline__ void ldm4(uint32_t& r0, uint32_t& r1, uint32_t& r2,
                                     uint32_t& r3, uint32_t addr) {
    asm volatile(
        "ldmatrix.sync.aligned.m8n8.x4.shared.b16 {%0,%1,%2,%3}, [%4];\n"
        : "=r"(r0), "=r"(r1), "=r"(r2), "=r"(r3)
        : "r"(addr));
}
__device__ __forceinline__ void ldm4t(uint32_t& r0, uint32_t& r1, uint32_t& r2,
                                      uint32_t& r3, uint32_t addr) {
    asm volatile(
        "ldmatrix.sync.aligned.m8n8.x4.trans.shared.b16 {%0,%1,%2,%3}, [%4];\n"
        : "=r"(r0), "=r"(r1), "=r"(r2), "=r"(r3)
        : "r"(addr));
}

// ---------------- GEMM cores: 512 threads, 16 warps, warp tile 32x32 ---------
#define SROW 40
#define BROW 264
#define BROW16 136
#define NSTAGE 3
#define TA_HALVES (128 * SROW)
#define TBN_HALVES (128 * SROW)
#define TBT_HALVES (16 * BROW)
#define TBT16_HALVES (16 * BROW16)
#define GSMEM_NT ((NSTAGE * (TA_HALVES + TBN_HALVES)) * 2)
#define GSMEM_TR ((NSTAGE * (TA_HALVES + TBT_HALVES)) * 2)
#define GSMEM_16 ((NSTAGE * (TA_HALVES + TBT16_HALVES)) * 2)

// ---- non-trans bf16 3-term core (k_scores) ----------------------------------
template <class FA, class FB>
__device__ __forceinline__ void gemm_core_nt(
    const bf16* __restrict__ Ah, const bf16* __restrict__ Al,
    const bf16* __restrict__ Bh, const bf16* __restrict__ Bl, FA rowA, FB rowB,
    int ktiles, float (&acc)[2][4][4]) {
    extern __shared__ __align__(16) bf16 smem[];
    bf16* sA = smem;
    bf16* sB = smem + NSTAGE * TA_HALVES;
    const int tid = threadIdx.x, lane = tid & 31, warp = tid >> 5;
    const int wm = (warp >> 2) * 32, wn = (warp & 3) * 32;

#pragma unroll
    for (int a = 0; a < 2; a++)
#pragma unroll
        for (int b = 0; b < 4; b++)
#pragma unroll
            for (int r = 0; r < 4; r++) acc[a][b][r] = 0.f;

    auto stage = [&](int kt, int s) {
        bf16* dA = sA + s * TA_HALVES;
        bf16* dB = sB + s * TBN_HALVES;
        int i = tid;  // 512 segs each, one per thread
        int row = i >> 2, c = i & 3;
        int koff = kt * 16 + (c & 1) * 8;
        cp16((c < 2 ? Ah : Al) + rowA(row) + koff, dA + row * SROW + c * 8);
        cp16((c < 2 ? Bh : Bl) + rowB(row) + koff, dB + row * SROW + c * 8);
        asm volatile("cp.async.commit_group;\n");
    };

    const int arow = ((lane >> 3) & 1) * 8 + (lane & 7);
    const int acol = (lane >> 4) * 8;
    const int brow = ((lane >> 4) & 1) * 8 + (lane & 7);
    const int bcol = ((lane >> 3) & 1) * 8;

    auto compute = [&](int s) {
        const bf16* A = sA + s * TA_HALVES;
        const bf16* B = sB + s * TBN_HALVES;
        uint32_t fah[2][4], fal[2][4], fbh[4][2], fbl[4][2];
#pragma unroll
        for (int mt = 0; mt < 2; mt++) {
            uint32_t ad = (uint32_t)__cvta_generic_to_shared(
                A + (wm + mt * 16 + arow) * SROW + acol);
            ldm4(fah[mt][0], fah[mt][1], fah[mt][2], fah[mt][3], ad);
            ldm4(fal[mt][0], fal[mt][1], fal[mt][2], fal[mt][3], ad + 32);
        }
#pragma unroll
        for (int p = 0; p < 2; p++) {
            uint32_t bd = (uint32_t)__cvta_generic_to_shared(
                B + (wn + p * 16 + brow) * SROW + bcol);
            ldm4(fbh[2 * p][0], fbh[2 * p][1], fbh[2 * p + 1][0],
                 fbh[2 * p + 1][1], bd);
            ldm4(fbl[2 * p][0], fbl[2 * p][1], fbl[2 * p + 1][0],
                 fbl[2 * p + 1][1], bd + 32);
        }
#pragma unroll
        for (int nt = 0; nt < 4; nt++)
#pragma unroll
            for (int mt = 0; mt < 2; mt++) {
                mma16816(acc[mt][nt], fah[mt], fbh[nt]);
                mma16816(acc[mt][nt], fal[mt], fbh[nt]);
                mma16816(acc[mt][nt], fah[mt], fbl[nt]);
            }
    };

    stage(0, 0);
    if (ktiles > 1) stage(1, 1);
    for (int kt = 0; kt < ktiles; kt++) {
        if (kt + 2 <= ktiles) cp_wait<1>();
        else cp_wait<0>();
        __syncthreads();
        if (kt + 2 < ktiles) stage(kt + 2, (kt + 2) % 3);
        compute(kt % 3);
    }
}

// ---- trans bf16 3-term core --------------------------------------------------
template <class FA>
__device__ __forceinline__ void gemm_core_tr(
    const bf16* __restrict__ Ah, const bf16* __restrict__ Al, FA rowA,
    const bf16* __restrict__ Bh, const bf16* __restrict__ Bl, int ldb,
    int ktiles, float (&acc)[2][4][4]) {
    extern __shared__ __align__(16) bf16 smem[];
    bf16* sA = smem;
    bf16* sB = smem + NSTAGE * TA_HALVES;
    const int tid = threadIdx.x, lane = tid & 31, warp = tid >> 5;
    const int wm = (warp >> 2) * 32, wn = (warp & 3) * 32;

#pragma unroll
    for (int a = 0; a < 2; a++)
#pragma unroll
        for (int b = 0; b < 4; b++)
#pragma unroll
            for (int r = 0; r < 4; r++) acc[a][b][r] = 0.f;

    auto stage = [&](int kt, int s) {
        bf16* dA = sA + s * TA_HALVES;
        bf16* dB = sB + s * TBT_HALVES;
        int i = tid;
        {   // A: 512 segs
            int row = i >> 2, c = i & 3;
            int koff = kt * 16 + (c & 1) * 8;
            cp16((c < 2 ? Ah : Al) + rowA(row) + koff, dA + row * SROW + c * 8);
        }
        {   // B: 512 segs (16 k-rows x 32 segs)
            int brw = i >> 5, sub = i & 31;
            int half = sub >> 4, nseg = sub & 15;
            const bf16* bsrc =
                (half ? Bl : Bh) + (size_t)(kt * 16 + brw) * ldb + nseg * 8;
            cp16(bsrc, dB + brw * BROW + half * 128 + nseg * 8);
        }
        asm volatile("cp.async.commit_group;\n");
    };

    const int arow = ((lane >> 3) & 1) * 8 + (lane & 7);
    const int acol = (lane >> 4) * 8;
    const int tkrow = (lane & 7) + ((lane >> 3) & 1) * 8;
    const int tnoff = (lane >> 4) * 8;

    auto compute = [&](int s) {
        const bf16* A = sA + s * TA_HALVES;
        const bf16* B = sB + s * TBT_HALVES;
        uint32_t fah[2][4], fal[2][4], fbh[4][2], fbl[4][2];
#pragma unroll
        for (int mt = 0; mt < 2; mt++) {
            uint32_t ad = (uint32_t)__cvta_generic_to_shared(
                A + (wm + mt * 16 + arow) * SROW + acol);
            ldm4(fah[mt][0], fah[mt][1], fah[mt][2], fah[mt][3], ad);
            ldm4(fal[mt][0], fal[mt][1], fal[mt][2], fal[mt][3], ad + 32);
        }
#pragma unroll
        for (int p = 0; p < 2; p++) {
            uint32_t bd = (uint32_t)__cvta_generic_to_shared(
                B + tkrow * BROW + wn + p * 16 + tnoff);
            ldm4t(fbh[2 * p][0], fbh[2 * p][1], fbh[2 * p + 1][0],
                  fbh[2 * p + 1][1], bd);
            ldm4t(fbl[2 * p][0], fbl[2 * p][1], fbl[2 * p + 1][0],
                  fbl[2 * p + 1][1], bd + 256);
        }
#pragma unroll
        for (int nt = 0; nt < 4; nt++)
#pragma unroll
            for (int mt = 0; mt < 2; mt++) {
                mma16816(acc[mt][nt], fah[mt], fbh[nt]);
                mma16816(acc[mt][nt], fal[mt], fbh[nt]);
                mma16816(acc[mt][nt], fah[mt], fbl[nt]);
            }
    };

    stage(0, 0);
    if (ktiles > 1) stage(1, 1);
    for (int kt = 0; kt < ktiles; kt++) {
        if (kt + 2 <= ktiles) cp_wait<1>();
        else cp_wait<0>();
        __syncthreads();
        if (kt + 2 < ktiles) stage(kt + 2, (kt + 2) % 3);
        compute(kt % 3);
    }
}

// ---- trans fp16 2-term core ----------------------------------------------------
template <class FA>
__device__ __forceinline__ void gemm_core_16(
    const f16* __restrict__ Ah, const f16* __restrict__ Al, FA rowA,
    const f16* __restrict__ Bf, int ldb, int ktiles, float (&acc)[2][4][4]) {
    extern __shared__ __align__(16) bf16 smem[];
    f16* sA = reinterpret_cast<f16*>(smem);
    f16* sB = sA + NSTAGE * TA_HALVES;
    const int tid = threadIdx.x, lane = tid & 31, warp = tid >> 5;
    const int wm = (warp >> 2) * 32, wn = (warp & 3) * 32;

#pragma unroll
    for (int a = 0; a < 2; a++)
#pragma unroll
        for (int b = 0; b < 4; b++)
#pragma unroll
            for (int r = 0; r < 4; r++) acc[a][b][r] = 0.f;

    auto stage = [&](int kt, int s) {
        f16* dA = sA + s * TA_HALVES;
        f16* dB = sB + s * TBT16_HALVES;
        int i = tid;
        {
            int row = i >> 2, c = i & 3;
            int koff = kt * 16 + (c & 1) * 8;
            cp16((c < 2 ? Ah : Al) + rowA(row) + koff, dA + row * SROW + c * 8);
        }
        if (i < 256) {
            int brw = i >> 4, nseg = i & 15;
            const f16* bsrc = Bf + (size_t)(kt * 16 + brw) * ldb + nseg * 8;
            cp16(bsrc, dB + brw * BROW16 + nseg * 8);
        }
        asm volatile("cp.async.commit_group;\n");
    };

    const int arow = ((lane >> 3) & 1) * 8 + (lane & 7);
    const int acol = (lane >> 4) * 8;
    const int tkrow = (lane & 7) + ((lane >> 3) & 1) * 8;
    const int tnoff = (lane >> 4) * 8;

    auto compute = [&](int s) {
        const f16* A = sA + s * TA_HALVES;
        const f16* B = sB + s * TBT16_HALVES;
        uint32_t fah[2][4], fal[2][4], fb[4][2];
#pragma unroll
        for (int mt = 0; mt < 2; mt++) {
            uint32_t ad = (uint32_t)__cvta_generic_to_shared(
                A + (wm + mt * 16 + arow) * SROW + acol);
            ldm4(fah[mt][0], fah[mt][1], fah[mt][2], fah[mt][3], ad);
            ldm4(fal[mt][0], fal[mt][1], fal[mt][2], fal[mt][3], ad + 32);
        }
#pragma unroll
        for (int p = 0; p < 2; p++) {
            uint32_t bd = (uint32_t)__cvta_generic_to_shared(
                B + tkrow * BROW16 + wn + p * 16 + tnoff);
            ldm4t(fb[2 * p][0], fb[2 * p][1], fb[2 * p + 1][0],
                  fb[2 * p + 1][1], bd);
        }
#pragma unroll
        for (int nt = 0; nt < 4; nt++)
#pragma unroll
            for (int mt = 0; mt < 2; mt++) {
                mma16816f(acc[mt][nt], fah[mt], fb[nt]);
                mma16816f(acc[mt][nt], fal[mt], fb[nt]);
            }
    };

    stage(0, 0);
    if (ktiles > 1) stage(1, 1);
    for (int kt = 0; kt < ktiles; kt++) {
        if (kt + 2 <= ktiles) cp_wait<1>();
        else cp_wait<0>();
        __syncthreads();
        if (kt + 2 < ktiles) stage(kt + 2, (kt + 2) % 3);
        compute(kt % 3);
    }
}

// epilogue iterator (16 warps, 32x32 per warp)
template <class F>
__device__ __forceinline__ void epi128(float (&acc)[2][4][4], F f) {
    const int lane = threadIdx.x & 31, warp = threadIdx.x >> 5;
    const int wm = (warp >> 2) * 32, wn = (warp & 3) * 32;
    const int gid = lane >> 2, tc = lane & 3;
#pragma unroll
    for (int mt = 0; mt < 2; mt++)
#pragma unroll
        for (int nt = 0; nt < 4; nt++)
#pragma unroll
            for (int r = 0; r < 4; r++) {
                int row = wm + mt * 16 + gid + ((r >> 1) << 3);
                int col = wn + nt * 8 + tc * 2 + (r & 1);
                f(row, col, acc[mt][nt][r]);
            }
}

// ---------------- streaming splits --------------------------------------------
__global__ void k_split(const float* __restrict__ src, bf16* __restrict__ dh,
                        bf16* __restrict__ dl, int n8) {
    int i = blockIdx.x * 256 + threadIdx.x;
    if (i >= n8) return;
    const float4* s4 = reinterpret_cast<const float4*>(src) + i * 2;
    float4 a = s4[0], b = s4[1];
    bf16 hbuf[8], lbuf[8];
    split_bf(a.x, hbuf[0], lbuf[0]);
    split_bf(a.y, hbuf[1], lbuf[1]);
    split_bf(a.z, hbuf[2], lbuf[2]);
    split_bf(a.w, hbuf[3], lbuf[3]);
    split_bf(b.x, hbuf[4], lbuf[4]);
    split_bf(b.y, hbuf[5], lbuf[5]);
    split_bf(b.z, hbuf[6], lbuf[6]);
    split_bf(b.w, hbuf[7], lbuf[7]);
    reinterpret_cast<uint4*>(dh)[i] = *reinterpret_cast<uint4*>(hbuf);
    reinterpret_cast<uint4*>(dl)[i] = *reinterpret_cast<uint4*>(lbuf);
}

__global__ void k_split16(const float* __restrict__ src, f16* __restrict__ d,
                          int n8) {
    int i = blockIdx.x * 256 + threadIdx.x;
    if (i >= n8) return;
    const float4* s4 = reinterpret_cast<const float4*>(src) + i * 2;
    float4 a = s4[0], b = s4[1];
    f16 buf[8];
    buf[0] = __float2half(a.x);
    buf[1] = __float2half(a.y);
    buf[2] = __float2half(a.z);
    buf[3] = __float2half(a.w);
    buf[4] = __float2half(b.x);
    buf[5] = __float2half(b.y);
    buf[6] = __float2half(b.z);
    buf[7] = __float2half(b.w);
    reinterpret_cast<uint4*>(d)[i] = *reinterpret_cast<uint4*>(buf);
}

__global__ void k_split_v() {
    int i = blockIdx.x * 256 + threadIdx.x;
    if (i >= T * 256 / 8) return;
    int t = i >> 5, j = (i & 31) * 8;
    const float* src = g_qkv + (size_t)t * QKV_N + (NH + NKV) * HD + j;
    float4 a = *reinterpret_cast<const float4*>(src);
    float4 b = *reinterpret_cast<const float4*>(src + 4);
    bf16 hbuf[8], lbuf[8];
    split_bf(a.x, hbuf[0], lbuf[0]);
    split_bf(a.y, hbuf[1], lbuf[1]);
    split_bf(a.z, hbuf[2], lbuf[2]);
    split_bf(a.w, hbuf[3], lbuf[3]);
    split_bf(b.x, hbuf[4], lbuf[4]);
    split_bf(b.y, hbuf[5], lbuf[5]);
    split_bf(b.z, hbuf[6], lbuf[6]);
    split_bf(b.w, hbuf[7], lbuf[7]);
    size_t o = (size_t)t * (NKV * HD) + j;
    *reinterpret_cast<uint4*>(g_vh + o) = *reinterpret_cast<uint4*>(hbuf);
    *reinterpret_cast<uint4*>(g_vl + o) = *reinterpret_cast<uint4*>(lbuf);
}

// ---------------- generic bf16 GEMM (trans-B) ----------------------------------
__global__ __launch_bounds__(512) void k_gemm(
    const bf16* __restrict__ Ah, const bf16* __restrict__ Al, int sa,
    const bf16* __restrict__ Bh, const bf16* __restrict__ Bl, int ldb,
    float* __restrict__ C, int ldc, int ktiles, const float* __restrict__ addm) {
    const int rb = blockIdx.y * 128, cb = blockIdx.x * 128;
    float acc[2][4][4];
    gemm_core_tr(
        Ah, Al, [&](int m) { return (size_t)(rb + m) * sa; }, Bh + cb, Bl + cb,
        ldb, ktiles, acc);
    epi128(acc, [&](int r, int c, float v) {
        size_t idx = (size_t)(rb + r) * ldc + cb + c;
        if (addm) v += addm[idx];
        C[idx] = v;
    });
}

// ---------------- generic fp16 GEMM (trans-B, 2-term) ---------------------------
__global__ __launch_bounds__(512) void k_gemm16(
    const f16* __restrict__ Ah, const f16* __restrict__ Al, int sa,
    const f16* __restrict__ Bf, int ldb, float* __restrict__ C, int ldc,
    int ktiles) {
    const int rb = blockIdx.y * 128, cb = blockIdx.x * 128;
    float acc[2][4][4];
    gemm_core_16(
        Ah, Al, [&](int m) { return (size_t)(rb + m) * sa; }, Bf + cb, ldb,
        ktiles, acc);
    epi128(acc, [&](int r, int c, float v) {
        C[(size_t)(rb + r) * ldc + cb + c] = v;
    });
}

// ---------------- add + rmsnorm (ln1) ------------------------------------------
__global__ void k_add_rms1(const float* __restrict__ hs,
                           const float* __restrict__ res,
                           const float* __restrict__ w) {
    const int t = blockIdx.x, tid = threadIdx.x;
    float2 x[2];
    float ss = 0.f;
#pragma unroll
    for (int i = 0; i < 2; i++) {
        int c = (tid + i * 256) * 2;
        float2 a = *reinterpret_cast<const float2*>(hs + (size_t)t * H + c);
        float2 b = *reinterpret_cast<const float2*>(res + (size_t)t * H + c);
        float2 v = {a.x + b.x, a.y + b.y};
        *reinterpret_cast<float2*>(g_resid + (size_t)t * H + c) = v;
        x[i] = v;
        ss += v.x * v.x + v.y * v.y;
    }
    __shared__ float red[256];
    red[tid] = ss;
    __syncthreads();
    for (int s = 128; s > 0; s >>= 1) {
        if (tid < s) red[tid] += red[tid + s];
        __syncthreads();
    }
    float r = rsqrtf(red[0] / (float)H + 1e-6f);
#pragma unroll
    for (int i = 0; i < 2; i++) {
        int c = (tid + i * 256) * 2;
        bf162 h2, l2;
        split2(x[i].x * r * w[c], x[i].y * r * w[c + 1], h2, l2);
        *reinterpret_cast<bf162*>(g_hh + (size_t)t * H + c) = h2;
        *reinterpret_cast<bf162*>(g_hl + (size_t)t * H + c) = l2;
    }
}

// ---------------- rmsnorm (ln2) --------------------------------------------------
__global__ void k_rms2(const float* __restrict__ resid2,
                       const float* __restrict__ w) {
    const int t = blockIdx.x, tid = threadIdx.x;
    float2 x[2];
    float ss = 0.f;
#pragma unroll
    for (int i = 0; i < 2; i++) {
        int c = (tid + i * 256) * 2;
        float2 v = *reinterpret_cast<const float2*>(resid2 + (size_t)t * H + c);
        x[i] = v;
        ss += v.x * v.x + v.y * v.y;
    }
    __shared__ float red[256];
    red[tid] = ss;
    __syncthreads();
    for (int s = 128; s > 0; s >>= 1) {
        if (tid < s) red[tid] += red[tid + s];
        __syncthreads();
    }
    float r = rsqrtf(red[0] / (float)H + 1e-6f);
#pragma unroll
    for (int i = 0; i < 2; i++) {
        int c = (tid + i * 256) * 2;
        float v0 = x[i].x * r * w[c], v1 = x[i].y * r * w[c + 1];
        *reinterpret_cast<float2*>(g_h + (size_t)t * H + c) = float2{v0, v1};
        f16 h0, l0, h1, l1;
        split_f16(v0, h0, l0);
        split_f16(v1, h1, l1);
        *reinterpret_cast<__half2*>(g_h2h + (size_t)t * H + c) =
            __halves2half2(h0, h1);
        *reinterpret_cast<__half2*>(g_h2l + (size_t)t * H + c) =
            __halves2half2(l0, l1);
    }
}

// ---------------- per-head rmsnorm + rope ----------------------------------------
__global__ void k_qknorm_rope(const int* __restrict__ pos_ids,
                              const float* __restrict__ qnw,
                              const float* __restrict__ knw) {
    const int t = blockIdx.x, hh = blockIdx.y, d = threadIdx.x;
    const float* src;
    const float* w;
    bf16 *dh, *dl;
    if (hh < NH) {
        src = g_qkv + (size_t)t * QKV_N + hh * HD;
        w = qnw;
        dh = g_qh + ((size_t)t * NH + hh) * HD;
        dl = g_ql + ((size_t)t * NH + hh) * HD;
    } else {
        int kk = hh - NH;
        src = g_qkv + (size_t)t * QKV_N + NH * HD + kk * HD;
        w = knw;
        dh = g_kh + ((size_t)t * NKV + kk) * HD;
        dl = g_kl + ((size_t)t * NKV + kk) * HD;
    }
    float x = src[d];
    float ss = x * x;
#pragma unroll
    for (int o = 16; o > 0; o >>= 1) ss += __shfl_xor_sync(0xffffffffu, ss, o);
    __shared__ float wsum[4];
    if ((d & 31) == 0) wsum[d >> 5] = ss;
    __syncthreads();
    ss = wsum[0] + wsum[1] + wsum[2] + wsum[3];
    float xn = x * rsqrtf(ss / (float)HD + 1e-6f) * w[d];
    __shared__ float xb[HD];
    xb[d] = xn;
    __syncthreads();
    int p = pos_ids[t];
    if (d < 64) {
        float inv = powf(10000.f, -(float)d / 64.f);
        float ang = (float)p * inv;
        float c = cosf(ang), s = sinf(ang);
        float x1 = xb[d], x2 = xb[d + 64];
        split_bf(x1 * c - x2 * s, dh[d], dl[d]);
        split_bf(x2 * c + x1 * s, dh[d + 64], dl[d + 64]);
    }
}

// ---------------- attention scores -----------------------------------------------
__global__ __launch_bounds__(512) void k_scores() {
    const int jt = blockIdx.x, it = blockIdx.y, h = blockIdx.z;
    if (jt > it) return;
    float acc[2][4][4];
    gemm_core_nt(
        g_qh, g_ql, g_kh, g_kl,
        [&](int m) { return ((size_t)(it * 128 + m) * NH + h) * HD; },
        [&](int n) { return ((size_t)(jt * 128 + n) * NKV + (h >> 2)) * HD; },
        HD / 16, acc);
    const float scale = 0.08838834764831845f;
    float* S = g_scores + (size_t)h * T * T;
    epi128(acc, [&](int r, int c, float v) {
        int i = it * 128 + r;
        int j = jt * 128 + c;
        S[(size_t)i * T + j] = (j <= i) ? v * scale : -3.0e38f;
    });
}

// ---------------- row softmax -> bf16 P -------------------------------------------
__global__ void k_softmax() {
    const int i = blockIdx.x, h = blockIdx.y, tid = threadIdx.x;
    const float4* S4 =
        reinterpret_cast<const float4*>(g_scores + ((size_t)h * T + i) * T);
    bf162* Ph = reinterpret_cast<bf162*>(g_ph + ((size_t)h * T + i) * T);
    bf162* Pl = reinterpret_cast<bf162*>(g_pl + ((size_t)h * T + i) * T);
    const int n4 = (((i >> 7) + 1) << 7) >> 2;
    __shared__ float4 buf[T / 4];
    __shared__ float red[256];
    float mx = -3.4e38f;
    for (int j = tid; j < n4; j += 256) {
        float4 v = S4[j];
        buf[j] = v;
        mx = fmaxf(fmaxf(mx, fmaxf(v.x, v.y)), fmaxf(v.z, v.w));
    }
    red[tid] = mx;
    __syncthreads();
    for (int s = 128; s > 0; s >>= 1) {
        if (tid < s) red[tid] = fmaxf(red[tid], red[tid + s]);
        __syncthreads();
    }
    mx = red[0];
    __syncthreads();
    float sm = 0.f;
    for (int j = tid; j < n4; j += 256) {
        float4 v = buf[j];
        v.x = expf(v.x - mx);
        v.y = expf(v.y - mx);
        v.z = expf(v.z - mx);
        v.w = expf(v.w - mx);
        buf[j] = v;
        sm += v.x + v.y + v.z + v.w;
    }
    red[tid] = sm;
    __syncthreads();
    for (int s = 128; s > 0; s >>= 1) {
        if (tid < s) red[tid] += red[tid + s];
        __syncthreads();
    }
    float inv = 1.f / red[0];
    for (int j = tid; j < n4; j += 256) {
        float4 v = buf[j];
        bf162 h0, l0, h1, l1;
        split2(v.x * inv, v.y * inv, h0, l0);
        split2(v.z * inv, v.w * inv, h1, l1);
        Ph[j * 2] = h0;
        Ph[j * 2 + 1] = h1;
        Pl[j * 2] = l0;
        Pl[j * 2 + 1] = l1;
    }
}

// ---------------- ctx = P @ V --------------------------------------------------
__global__ __launch_bounds__(512) void k_ctx() {
    const int it = blockIdx.y, h = blockIdx.z;
    float acc[2][4][4];
    const int cb = (h >> 2) * 128;
    gemm_core_tr(
        g_ph, g_pl, [&](int m) { return ((size_t)h * T + it * 128 + m) * T; },
        g_vh + cb, g_vl + cb, NKV * HD, (it + 1) * 8, acc);
    epi128(acc, [&](int r, int c, float v) {
        size_t o = (size_t)(it * 128 + r) * (NH * HD) + h * HD + c;
        split_bf(v, g_ch[o], g_cl[o]);
    });
}

// ---------------- gate logits ----------------------------------------------------
__global__ void k_gate(const float* __restrict__ gw) {
    const int t = blockIdx.x, tid = threadIdx.x;
    const int e = tid & 15, seg = tid >> 4;
    const float* hr = g_h + (size_t)t * H;
    float s = 0.f;
    for (int k = seg * 128; k < seg * 128 + 128; k++) s += hr[k] * gw[k * NE + e];
    __shared__ float red[128];
    red[tid] = s;
    __syncthreads();
    if (tid < NE) {
        float v = 0.f;
        for (int g = 0; g < 8; g++) v += red[g * 16 + tid];
        g_logits[t * NE + tid] = v;
    }
}

// ---------------- routing --------------------------------------------------------
__global__ void k_zero_cnt() {
    if (threadIdx.x < NE) g_cnt[threadIdx.x] = 0;
}

__global__ void k_route(const float* __restrict__ bias) {
    const int t = blockIdx.x * 256 + threadIdx.x;
    if (t >= T) return;
    float sig[NE], sfc[NE];
#pragma unroll
    for (int e = 0; e < NE; e++) {
        float l = g_logits[t * NE + e];
        sig[e] = 1.f / (1.f + expf(-l));
        sfc[e] = sig[e] + bias[e];
    }
    float gs[4];
#pragma unroll
    for (int g = 0; g < 4; g++) {
        float m1 = -3.4e38f, m2 = -3.4e38f;
#pragma unroll
        for (int i = 0; i < 4; i++) {
            float v = sfc[g * 4 + i];
            if (v > m1) { m2 = m1; m1 = v; }
            else if (v > m2) m2 = v;
        }
        gs[g] = m1 + m2;
    }
    int g1 = 0;
    for (int g = 1; g < 4; g++) if (gs[g] > gs[g1]) g1 = g;
    int g2 = -1;
    for (int g = 0; g < 4; g++) {
        if (g == g1) continue;
        if (g2 < 0 || gs[g] > gs[g2]) g2 = g;
    }
    bool allowed[NE];
#pragma unroll
    for (int e = 0; e < NE; e++) {
        int g = e >> 2;
        allowed[e] = (g == g1) || (g == g2);
    }
    int sel[4];
    bool picked[NE];
#pragma unroll
    for (int e = 0; e < NE; e++) picked[e] = false;
    float wsum = 0.f;
#pragma unroll
    for (int it = 0; it < 4; it++) {
        int bi = -1;
        float bv = -3.4e38f;
        for (int e = 0; e < NE; e++) {
            if (!allowed[e] || picked[e]) continue;
            if (sfc[e] > bv) { bv = sfc[e]; bi = e; }
        }
        picked[bi] = true;
        sel[it] = bi;
        wsum += sig[bi];
    }
    float inv = 1.f / (wsum + 1e-20f);
#pragma unroll
    for (int it = 0; it < 4; it++) {
        int e = sel[it];
        int pos = atomicAdd(&g_cnt[e], 1);
        g_ptok[e * T + pos] = t;
        g_pw[e * T + pos] = sig[e] * inv;
    }
}

__global__ void k_offsets() {
    if (threadIdx.x == 0) {
        int run = 0;
        for (int e = 0; e < NE; e++) {
            g_poff[e] = run;
            run += ((g_cnt[e] + 127) / 128) * 128;
        }
    }
}

// ---------------- MoE gu (fp16 2-term) --------------------------------------------
__global__ __launch_bounds__(512) void k_moe_gu() {
    const int e = blockIdx.z, rt = blockIdx.y, bn = blockIdx.x;
    const int cnt = g_cnt[e];
    if (rt * 128 >= cnt) return;
    const int off = g_poff[e];
    const int* ptok = g_ptok + e * T;
    const int cb = bn * 128;
    float acc[2][4][4];
    gemm_core_16(
        g_h2h, g_h2l,
        [&](int m) {
            int lr = rt * 128 + m;
            int tok = ptok[lr < cnt ? lr : cnt - 1];
            return (size_t)tok * H;
        },
        g_w13f + (size_t)e * H * 2048 + cb, 2048, H / 16, acc);
    epi128(acc, [&](int r, int c, float v) {
        size_t row = (size_t)off + rt * 128 + r;
        g_gu[row * 2048 + cb + c] = v;
    });
}

// ---------------- MoE act -> fp16 split --------------------------------------------
__global__ void k_moe_act() {
    const int e = blockIdx.y, rt = blockIdx.x;
    const int cnt = g_cnt[e];
    if (rt * 128 >= cnt) return;
    const int off = g_poff[e];
    for (int i = threadIdx.x; i < 128 * (FDIM / 2); i += 256) {
        int r = i / (FDIM / 2), fp = i % (FDIM / 2);
        if (rt * 128 + r >= cnt) continue;
        size_t row = (size_t)off + rt * 128 + r;
        float2 g = *reinterpret_cast<const float2*>(&g_gu[row * 2048 + fp * 2]);
        float2 u =
            *reinterpret_cast<const float2*>(&g_gu[row * 2048 + FDIM + fp * 2]);
        float a0 = g.x / (1.f + expf(-g.x)) * u.x;
        float a1 = g.y / (1.f + expf(-g.y)) * u.y;
        f16 h0, l0, h1, l1;
        split_f16(a0, h0, l0);
        split_f16(a1, h1, l1);
        *reinterpret_cast<__half2*>(&g_amh[row * FDIM + fp * 2]) =
            __halves2half2(h0, h1);
        *reinterpret_cast<__half2*>(&g_aml[row * FDIM + fp * 2]) =
            __halves2half2(l0, l1);
    }
}

// ---------------- MoE y, scatter-add (fp16 2-term) ----------------------------------
__global__ __launch_bounds__(512) void k_moe_y(float* __restrict__ outp) {
    const int e = blockIdx.z, rt = blockIdx.y, bn = blockIdx.x;
    const int cnt = g_cnt[e];
    if (rt * 128 >= cnt) return;
    const int off = g_poff[e];
    const int cb = bn * 128;
    float acc[2][4][4];
    gemm_core_16(
        g_amh, g_aml,
        [&](int m) { return ((size_t)off + rt * 128 + m) * FDIM; },
        g_w2f + (size_t)e * FDIM * H + cb, H, FDIM / 16, acc);
    epi128(acc, [&](int r, int c, float v) {
        int lr = rt * 128 + r;
        if (lr >= cnt) return;
        int tok = g_ptok[e * T + lr];
        float w = 2.0f * g_pw[e * T + lr];
        atomicAdd(&outp[(size_t)tok * H + cb + c], w * v);
    });
}

// ---------------- shared-expert activation -> fp16 split ----------------------------
__global__ void k_act_shared() {
    const int t = blockIdx.x;
    for (int fp = threadIdx.x; fp < FDIM / 2; fp += 256) {
        float2 g =
            *reinterpret_cast<const float2*>(&g_scores[(size_t)t * 2048 + fp * 2]);
        float2 u = *reinterpret_cast<const float2*>(
            &g_scores[(size_t)t * 2048 + FDIM + fp * 2]);
        float a0 = g.x / (1.f + expf(-g.x)) * u.x;
        float a1 = g.y / (1.f + expf(-g.y)) * u.y;
        f16 h0, l0, h1, l1;
        split_f16(a0, h0, l0);
        split_f16(a1, h1, l1);
        *reinterpret_cast<__half2*>(&g_ash[(size_t)t * FDIM + fp * 2]) =
            __halves2half2(h0, h1);
        *reinterpret_cast<__half2*>(&g_asl[(size_t)t * FDIM + fp * 2]) =
            __halves2half2(l0, l1);
    }
}

// ---------------- launch -------------------------------------------------------------
extern "C" void kernel_launch(void* const* d_in, const int* in_sizes, int n_in,
                              void* d_out, int out_size) {
    const float* hs = (const float*)d_in[0];
    const float* res = (const float*)d_in[1];
    const int* pos = (const int*)d_in[2];
    const float* ln1_w = (const float*)d_in[3];
    const float* qkv_w = (const float*)d_in[4];
    const float* qnorm_w = (const float*)d_in[5];
    const float* knorm_w = (const float*)d_in[6];
    const float* dense_w = (const float*)d_in[7];
    const float* ln2_w = (const float*)d_in[8];
    const float* gate_w = (const float*)d_in[9];
    const float* expert_bias = (const float*)d_in[10];
    const float* w13 = (const float*)d_in[11];
    const float* w2 = (const float*)d_in[12];
    const float* ws_gate_up = (const float*)d_in[13];
    const float* ws_down = (const float*)d_in[14];

    float* out_mlp = (float*)d_out;
    float* out_resid2 = (float*)d_out + (size_t)T * H;

    float* p_resid;  cudaGetSymbolAddress((void**)&p_resid, g_resid);
    float* p_qkv;    cudaGetSymbolAddress((void**)&p_qkv, g_qkv);
    float* p_scores; cudaGetSymbolAddress((void**)&p_scores, g_scores);
    bf16 *p_hh, *p_hl, *p_wqkvh, *p_wqkvl, *p_wdh, *p_wdl, *p_ch, *p_cl;
    f16 *p_h2h, *p_h2l, *p_ash, *p_asl, *p_w13f, *p_w2f, *p_wsguf, *p_wsdf;
    cudaGetSymbolAddress((void**)&p_hh, g_hh);
    cudaGetSymbolAddress((void**)&p_hl, g_hl);
    cudaGetSymbolAddress((void**)&p_wqkvh, g_wqkvh);
    cudaGetSymbolAddress((void**)&p_wqkvl, g_wqkvl);
    cudaGetSymbolAddress((void**)&p_wdh, g_wdh);
    cudaGetSymbolAddress((void**)&p_wdl, g_wdl);
    cudaGetSymbolAddress((void**)&p_ch, g_ch);
    cudaGetSymbolAddress((void**)&p_cl, g_cl);
    cudaGetSymbolAddress((void**)&p_h2h, g_h2h);
    cudaGetSymbolAddress((void**)&p_h2l, g_h2l);
    cudaGetSymbolAddress((void**)&p_ash, g_ash);
    cudaGetSymbolAddress((void**)&p_asl, g_asl);
    cudaGetSymbolAddress((void**)&p_w13f, g_w13f);
    cudaGetSymbolAddress((void**)&p_w2f, g_w2f);
    cudaGetSymbolAddress((void**)&p_wsguf, g_wsguf);
    cudaGetSymbolAddress((void**)&p_wsdf, g_wsdf);

    static bool attrs_set = false;
    if (!attrs_set) {
        cudaFuncSetAttribute(k_gemm, cudaFuncAttributeMaxDynamicSharedMemorySize, GSMEM_TR);
        cudaFuncSetAttribute(k_scores, cudaFuncAttributeMaxDynamicSharedMemorySize, GSMEM_NT);
        cudaFuncSetAttribute(k_ctx, cudaFuncAttributeMaxDynamicSharedMemorySize, GSMEM_TR);
        cudaFuncSetAttribute(k_gemm16, cudaFuncAttributeMaxDynamicSharedMemorySize, GSMEM_16);
        cudaFuncSetAttribute(k_moe_gu, cudaFuncAttributeMaxDynamicSharedMemorySize, GSMEM_16);
        cudaFuncSetAttribute(k_moe_y, cudaFuncAttributeMaxDynamicSharedMemorySize, GSMEM_16);
        attrs_set = true;
    }

    // weight conversions
    k_split<<<(H * QKV_N / 8 + 255) / 256, 256>>>(qkv_w, p_wqkvh, p_wqkvl, H * QKV_N / 8);
    k_split<<<(H * H / 8 + 255) / 256, 256>>>(dense_w, p_wdh, p_wdl, H * H / 8);
    k_split16<<<((int)((size_t)NE * H * 2048 / 8) + 255) / 256, 256>>>(w13, p_w13f, (int)((size_t)NE * H * 2048 / 8));
    k_split16<<<((int)((size_t)NE * FDIM * H / 8) + 255) / 256, 256>>>(w2, p_w2f, (int)((size_t)NE * FDIM * H / 8));
    k_split16<<<(H * 2048 / 8 + 255) / 256, 256>>>(ws_gate_up, p_wsguf, H * 2048 / 8);
    k_split16<<<(FDIM * H / 8 + 255) / 256, 256>>>(ws_down, p_wsdf, FDIM * H / 8);

    // 1. resid + ln1
    k_add_rms1<<<T, 256>>>(hs, res, ln1_w);
    // 2. qkv
    k_gemm<<<dim3(QKV_N / 128, T / 128), 512, GSMEM_TR>>>(
        p_hh, p_hl, H, p_wqkvh, p_wqkvl, QKV_N, p_qkv, QKV_N, H / 16, nullptr);
    // 3. q/k norm+rope, V split
    k_qknorm_rope<<<dim3(T, NH + NKV), 128>>>(pos, qnorm_w, knorm_w);
    k_split_v<<<(T * 256 / 8 + 255) / 256, 256>>>();
    // 4. attention
    k_scores<<<dim3(T / 128, T / 128, NH), 512, GSMEM_NT>>>();
    k_softmax<<<dim3(T, NH), 256>>>();
    k_ctx<<<dim3(1, T / 128, NH), 512, GSMEM_TR>>>();
    // 7. resid2
    k_gemm<<<dim3(H / 128, T / 128), 512, GSMEM_TR>>>(
        p_ch, p_cl, NH * HD, p_wdh, p_wdl, H, out_resid2, H, H / 16, p_resid);
    // 8. h2
    k_rms2<<<T, 256>>>(out_resid2, ln2_w);
    // 9-10. gate + routing
    k_gate<<<T, 128>>>(gate_w);
    k_zero_cnt<<<1, 32>>>();
    k_route<<<T / 256, 256>>>(expert_bias);
    k_offsets<<<1, 32>>>();
    // 11. shared expert su
    k_gemm16<<<dim3(2048 / 128, T / 128), 512, GSMEM_16>>>(
        p_h2h, p_h2l, H, p_wsguf, 2048, p_scores, 2048, H / 16);
    // 12. shared act
    k_act_shared<<<T, 256>>>();
    // 13. mlp_out = act @ ws_down
    k_gemm16<<<dim3(H / 128, T / 128), 512, GSMEM_16>>>(
        p_ash, p_asl, FDIM, p_wsdf, H, out_mlp, H, FDIM / 16);
    // 14-16. routed experts
    k_moe_gu<<<dim3(2048 / 128, T / 128, NE), 512, GSMEM_16>>>();
    k_moe_act<<<dim3(T / 128, NE), 256>>>();
    k_moe_y<<<dim3(H / 128, T / 128, NE), 512, GSMEM_16>>>(out_mlp);

    (void)in_sizes; (void)n_in; (void)out_size;
}

// round 9
// speedup vs baseline: 1.2217x; 1.2217x over previous
#include <cuda_runtime.h>
#include <cuda_bf16.h>
#include <cuda_fp16.h>
#include <math.h>
#include <stdint.h>

#define T 2048
#define H 1024
#define NH 8
#define NKV 2
#define HD 128
#define NE 16
#define QKV_N 1536
#define FDIM 1024
#define PAD_ROWS 10240

typedef __nv_bfloat16 bf16;
typedef __nv_bfloat162 bf162;
typedef __half f16;

// ---------------- fp32 scratch ----------------------------------------------
__device__ float g_resid[T * H];
__device__ float g_h[T * H];
__device__ float g_qkv[T * QKV_N];
__device__ float g_scores[(size_t)NH * T * T];
__device__ float g_logits[T * NE];
__device__ int   g_cnt[NE];
__device__ int   g_poff[NE];
__device__ int   g_ptok[NE * T];
__device__ float g_pw[NE * T];

// ---------------- bf16 hi/lo operand buffers (router-critical path) ----------
__device__ bf16 g_hh[T * H],  g_hl[T * H];
__device__ bf16 g_qh[T * NH * HD], g_ql[T * NH * HD];
__device__ bf16 g_kh[T * NKV * HD], g_kl[T * NKV * HD];
__device__ bf16 g_vh[T * NKV * HD], g_vl[T * NKV * HD];
__device__ bf16 g_ph[(size_t)NH * T * T], g_pl[(size_t)NH * T * T];
__device__ bf16 g_ch[T * 1024], g_cl[T * 1024];
__device__ bf16 g_wqkvh[H * QKV_N], g_wqkvl[H * QKV_N];
__device__ bf16 g_wdh[H * H], g_wdl[H * H];

// ---------------- fp16 operands (post-routing path, 2-term) ------------------
__device__ f16 g_h2h[T * H], g_h2l[T * H];
__device__ f16 g_ash[T * FDIM], g_asl[T * FDIM];
__device__ f16 g_amh[(size_t)PAD_ROWS * 1024], g_aml[(size_t)PAD_ROWS * 1024];
__device__ f16 g_w13f[(size_t)NE * H * 2048];   // interleaved [g0,u0,g1,u1,...]
__device__ f16 g_w2f[(size_t)NE * FDIM * H];
__device__ f16 g_wsguf[H * 2048];               // interleaved
__device__ f16 g_wsdf[FDIM * H];

// ---------------- helpers ----------------------------------------------------
__device__ __forceinline__ void split_bf(float v, bf16& h, bf16& l) {
    h = __float2bfloat16(v);
    l = __float2bfloat16(v - __bfloat162float(h));
}
__device__ __forceinline__ void split2(float a, float b, bf162& h2, bf162& l2) {
    bf16 ha, la, hb, lb;
    split_bf(a, ha, la);
    split_bf(b, hb, lb);
    h2 = bf162{ha, hb};
    l2 = bf162{la, lb};
}
__device__ __forceinline__ void split_f16(float v, f16& h, f16& l) {
    h = __float2half(v);
    l = __float2half(v - __half2float(h));
}
__device__ __forceinline__ float silu_f(float g) {
    return g / (1.f + expf(-g));
}
__device__ __forceinline__ void mma16816(float* c, const uint32_t* a,
                                         const uint32_t* b) {
    asm volatile(
        "mma.sync.aligned.m16n8k16.row.col.f32.bf16.bf16.f32 "
        "{%0,%1,%2,%3}, {%4,%5,%6,%7}, {%8,%9}, {%0,%1,%2,%3};\n"
        : "+f"(c[0]), "+f"(c[1]), "+f"(c[2]), "+f"(c[3])
        : "r"(a[0]), "r"(a[1]), "r"(a[2]), "r"(a[3]), "r"(b[0]), "r"(b[1]));
}
__device__ __forceinline__ void mma16816f(float* c, const uint32_t* a,
                                          const uint32_t* b) {
    asm volatile(
        "mma.sync.aligned.m16n8k16.row.col.f32.f16.f16.f32 "
        "{%0,%1,%2,%3}, {%4,%5,%6,%7}, {%8,%9}, {%0,%1,%2,%3};\n"
        : "+f"(c[0]), "+f"(c[1]), "+f"(c[2]), "+f"(c[3])
        : "r"(a[0]), "r"(a[1]), "r"(a[2]), "r"(a[3]), "r"(b[0]), "r"(b[1]));
}
template <int N> __device__ __forceinline__ void cp_wait() {
    asm volatile("cp.async.wait_group %0;\n" ::"n"(N));
}
__device__ __forceinline__ void cp16(const void* src, void* dst) {
    uint32_t d = (uint32_t)__cvta_generic_to_shared(dst);
    asm volatile("cp.async.ca.shared.global [%0], [%1], 16;\n" ::"r"(d),
                 "l"(src));
}
__device__ __forceinline__ void ldm4(uint32_t& r0, uint32_t& r1, uint32_t& r2,
                                     uint32_t& r3, uint32_t addr) {
    asm volatile(
        "ldmatrix.sync.aligned.m8n8.x4.shared.b16 {%0,%1,%2,%3}, [%4];\n"
        : "=r"(r0), "=r"(r1), "=r"(r2), "=r"(r3)
        : "r"(addr));
}
__device__ __forceinline__ void ldm4t(uint32_t& r0, uint32_t& r1, uint32_t& r2,
                                      uint32_t& r3, uint32_t addr) {
    asm volatile(
        "ldmatrix.sync.aligned.m8n8.x4.trans.shared.b16 {%0,%1,%2,%3}, [%4];\n"
        : "=r"(r0), "=r"(r1), "=r"(r2), "=r"(r3)
        : "r"(addr));
}

// ---------------- GEMM cores: 256 threads, 8 warps, warp tile 64x32 ----------
#define SROW 40
#define BROW 264
#define BROW16 136
#define NSTAGE 3
#define TA_HALVES (128 * SROW)
#define TBN_HALVES (128 * SROW)
#define TBT_HALVES (16 * BROW)
#define TBT16_HALVES (16 * BROW16)
#define GSMEM_NT ((NSTAGE * (TA_HALVES + TBN_HALVES)) * 2)
#define GSMEM_TR ((NSTAGE * (TA_HALVES + TBT_HALVES)) * 2)
#define GSMEM_16 ((NSTAGE * (TA_HALVES + TBT16_HALVES)) * 2)

// ---- non-trans bf16 3-term core (k_scores) ----------------------------------
template <class FA, class FB>
__device__ __forceinline__ void gemm_core_nt(
    const bf16* __restrict__ Ah, const bf16* __restrict__ Al,
    const bf16* __restrict__ Bh, const bf16* __restrict__ Bl, FA rowA, FB rowB,
    int ktiles, float (&acc)[4][4][4]) {
    extern __shared__ __align__(16) bf16 smem[];
    bf16* sA = smem;
    bf16* sB = smem + NSTAGE * TA_HALVES;
    const int tid = threadIdx.x, lane = tid & 31, warp = tid >> 5;
    const int wm = (warp >> 2) * 64, wn = (warp & 3) * 32;

#pragma unroll
    for (int a = 0; a < 4; a++)
#pragma unroll
        for (int b = 0; b < 4; b++)
#pragma unroll
            for (int r = 0; r < 4; r++) acc[a][b][r] = 0.f;

    auto stage = [&](int kt, int s) {
        bf16* dA = sA + s * TA_HALVES;
        bf16* dB = sB + s * TBN_HALVES;
#pragma unroll
        for (int i = tid; i < 512; i += 256) {
            int row = i >> 2, c = i & 3;
            int koff = kt * 16 + (c & 1) * 8;
            cp16((c < 2 ? Ah : Al) + rowA(row) + koff, dA + row * SROW + c * 8);
            cp16((c < 2 ? Bh : Bl) + rowB(row) + koff, dB + row * SROW + c * 8);
        }
        asm volatile("cp.async.commit_group;\n");
    };

    const int arow = ((lane >> 3) & 1) * 8 + (lane & 7);
    const int acol = (lane >> 4) * 8;
    const int brow = ((lane >> 4) & 1) * 8 + (lane & 7);
    const int bcol = ((lane >> 3) & 1) * 8;

    auto compute = [&](int s) {
        const bf16* A = sA + s * TA_HALVES;
        const bf16* B = sB + s * TBN_HALVES;
        uint32_t fah[4][4], fal[4][4], fbh[4][2], fbl[4][2];
#pragma unroll
        for (int mt = 0; mt < 4; mt++) {
            uint32_t ad = (uint32_t)__cvta_generic_to_shared(
                A + (wm + mt * 16 + arow) * SROW + acol);
            ldm4(fah[mt][0], fah[mt][1], fah[mt][2], fah[mt][3], ad);
            ldm4(fal[mt][0], fal[mt][1], fal[mt][2], fal[mt][3], ad + 32);
        }
#pragma unroll
        for (int p = 0; p < 2; p++) {
            uint32_t bd = (uint32_t)__cvta_generic_to_shared(
                B + (wn + p * 16 + brow) * SROW + bcol);
            ldm4(fbh[2 * p][0], fbh[2 * p][1], fbh[2 * p + 1][0],
                 fbh[2 * p + 1][1], bd);
            ldm4(fbl[2 * p][0], fbl[2 * p][1], fbl[2 * p + 1][0],
                 fbl[2 * p + 1][1], bd + 32);
        }
        // term-outer order: consecutive MMAs never share an accumulator
#pragma unroll
        for (int nt = 0; nt < 4; nt++)
#pragma unroll
            for (int mt = 0; mt < 4; mt++) mma16816(acc[mt][nt], fah[mt], fbh[nt]);
#pragma unroll
        for (int nt = 0; nt < 4; nt++)
#pragma unroll
            for (int mt = 0; mt < 4; mt++) mma16816(acc[mt][nt], fal[mt], fbh[nt]);
#pragma unroll
        for (int nt = 0; nt < 4; nt++)
#pragma unroll
            for (int mt = 0; mt < 4; mt++) mma16816(acc[mt][nt], fah[mt], fbl[nt]);
    };

    stage(0, 0);
    if (ktiles > 1) stage(1, 1);
    for (int kt = 0; kt < ktiles; kt++) {
        if (kt + 2 <= ktiles) cp_wait<1>();
        else cp_wait<0>();
        __syncthreads();
        if (kt + 2 < ktiles) stage(kt + 2, (kt + 2) % 3);
        compute(kt % 3);
    }
}

// ---- trans bf16 3-term core ----------------------------------------------------
template <class FA>
__device__ __forceinline__ void gemm_core_tr(
    const bf16* __restrict__ Ah, const bf16* __restrict__ Al, FA rowA,
    const bf16* __restrict__ Bh, const bf16* __restrict__ Bl, int ldb,
    int ktiles, float (&acc)[4][4][4]) {
    extern __shared__ __align__(16) bf16 smem[];
    bf16* sA = smem;
    bf16* sB = smem + NSTAGE * TA_HALVES;
    const int tid = threadIdx.x, lane = tid & 31, warp = tid >> 5;
    const int wm = (warp >> 2) * 64, wn = (warp & 3) * 32;

#pragma unroll
    for (int a = 0; a < 4; a++)
#pragma unroll
        for (int b = 0; b < 4; b++)
#pragma unroll
            for (int r = 0; r < 4; r++) acc[a][b][r] = 0.f;

    auto stage = [&](int kt, int s) {
        bf16* dA = sA + s * TA_HALVES;
        bf16* dB = sB + s * TBT_HALVES;
#pragma unroll
        for (int i = tid; i < 512; i += 256) {
            int row = i >> 2, c = i & 3;
            int koff = kt * 16 + (c & 1) * 8;
            cp16((c < 2 ? Ah : Al) + rowA(row) + koff, dA + row * SROW + c * 8);
            int brw = i >> 5, sub = i & 31;
            int half = sub >> 4, nseg = sub & 15;
            const bf16* bsrc =
                (half ? Bl : Bh) + (size_t)(kt * 16 + brw) * ldb + nseg * 8;
            cp16(bsrc, dB + brw * BROW + half * 128 + nseg * 8);
        }
        asm volatile("cp.async.commit_group;\n");
    };

    const int arow = ((lane >> 3) & 1) * 8 + (lane & 7);
    const int acol = (lane >> 4) * 8;
    const int tkrow = (lane & 7) + ((lane >> 3) & 1) * 8;
    const int tnoff = (lane >> 4) * 8;

    auto compute = [&](int s) {
        const bf16* A = sA + s * TA_HALVES;
        const bf16* B = sB + s * TBT_HALVES;
        uint32_t fah[4][4], fal[4][4], fbh[4][2], fbl[4][2];
#pragma unroll
        for (int mt = 0; mt < 4; mt++) {
            uint32_t ad = (uint32_t)__cvta_generic_to_shared(
                A + (wm + mt * 16 + arow) * SROW + acol);
            ldm4(fah[mt][0], fah[mt][1], fah[mt][2], fah[mt][3], ad);
            ldm4(fal[mt][0], fal[mt][1], fal[mt][2], fal[mt][3], ad + 32);
        }
#pragma unroll
        for (int p = 0; p < 2; p++) {
            uint32_t bd = (uint32_t)__cvta_generic_to_shared(
                B + tkrow * BROW + wn + p * 16 + tnoff);
            ldm4t(fbh[2 * p][0], fbh[2 * p][1], fbh[2 * p + 1][0],
                  fbh[2 * p + 1][1], bd);
            ldm4t(fbl[2 * p][0], fbl[2 * p][1], fbl[2 * p + 1][0],
                  fbl[2 * p + 1][1], bd + 256);
        }
#pragma unroll
        for (int nt = 0; nt < 4; nt++)
#pragma unroll
            for (int mt = 0; mt < 4; mt++) mma16816(acc[mt][nt], fah[mt], fbh[nt]);
#pragma unroll
        for (int nt = 0; nt < 4; nt++)
#pragma unroll
            for (int mt = 0; mt < 4; mt++) mma16816(acc[mt][nt], fal[mt], fbh[nt]);
#pragma unroll
        for (int nt = 0; nt < 4; nt++)
#pragma unroll
            for (int mt = 0; mt < 4; mt++) mma16816(acc[mt][nt], fah[mt], fbl[nt]);
    };

    stage(0, 0);
    if (ktiles > 1) stage(1, 1);
    for (int kt = 0; kt < ktiles; kt++) {
        if (kt + 2 <= ktiles) cp_wait<1>();
        else cp_wait<0>();
        __syncthreads();
        if (kt + 2 < ktiles) stage(kt + 2, (kt + 2) % 3);
        compute(kt % 3);
    }
}

// ---- trans fp16 2-term core ------------------------------------------------------
template <class FA>
__device__ __forceinline__ void gemm_core_16(
    const f16* __restrict__ Ah, const f16* __restrict__ Al, FA rowA,
    const f16* __restrict__ Bf, int ldb, int ktiles, float (&acc)[4][4][4]) {
    extern __shared__ __align__(16) bf16 smem[];
    f16* sA = reinterpret_cast<f16*>(smem);
    f16* sB = sA + NSTAGE * TA_HALVES;
    const int tid = threadIdx.x, lane = tid & 31, warp = tid >> 5;
    const int wm = (warp >> 2) * 64, wn = (warp & 3) * 32;

#pragma unroll
    for (int a = 0; a < 4; a++)
#pragma unroll
        for (int b = 0; b < 4; b++)
#pragma unroll
            for (int r = 0; r < 4; r++) acc[a][b][r] = 0.f;

    auto stage = [&](int kt, int s) {
        f16* dA = sA + s * TA_HALVES;
        f16* dB = sB + s * TBT16_HALVES;
#pragma unroll
        for (int i = tid; i < 512; i += 256) {
            int row = i >> 2, c = i & 3;
            int koff = kt * 16 + (c & 1) * 8;
            cp16((c < 2 ? Ah : Al) + rowA(row) + koff, dA + row * SROW + c * 8);
        }
        {
            int i = tid;
            int brw = i >> 4, nseg = i & 15;
            const f16* bsrc = Bf + (size_t)(kt * 16 + brw) * ldb + nseg * 8;
            cp16(bsrc, dB + brw * BROW16 + nseg * 8);
        }
        asm volatile("cp.async.commit_group;\n");
    };

    const int arow = ((lane >> 3) & 1) * 8 + (lane & 7);
    const int acol = (lane >> 4) * 8;
    const int tkrow = (lane & 7) + ((lane >> 3) & 1) * 8;
    const int tnoff = (lane >> 4) * 8;

    auto compute = [&](int s) {
        const f16* A = sA + s * TA_HALVES;
        const f16* B = sB + s * TBT16_HALVES;
        uint32_t fah[4][4], fal[4][4], fb[4][2];
#pragma unroll
        for (int mt = 0; mt < 4; mt++) {
            uint32_t ad = (uint32_t)__cvta_generic_to_shared(
                A + (wm + mt * 16 + arow) * SROW + acol);
            ldm4(fah[mt][0], fah[mt][1], fah[mt][2], fah[mt][3], ad);
            ldm4(fal[mt][0], fal[mt][1], fal[mt][2], fal[mt][3], ad + 32);
        }
#pragma unroll
        for (int p = 0; p < 2; p++) {
            uint32_t bd = (uint32_t)__cvta_generic_to_shared(
                B + tkrow * BROW16 + wn + p * 16 + tnoff);
            ldm4t(fb[2 * p][0], fb[2 * p][1], fb[2 * p + 1][0],
                  fb[2 * p + 1][1], bd);
        }
#pragma unroll
        for (int nt = 0; nt < 4; nt++)
#pragma unroll
            for (int mt = 0; mt < 4; mt++) mma16816f(acc[mt][nt], fah[mt], fb[nt]);
#pragma unroll
        for (int nt = 0; nt < 4; nt++)
#pragma unroll
            for (int mt = 0; mt < 4; mt++) mma16816f(acc[mt][nt], fal[mt], fb[nt]);
    };

    stage(0, 0);
    if (ktiles > 1) stage(1, 1);
    for (int kt = 0; kt < ktiles; kt++) {
        if (kt + 2 <= ktiles) cp_wait<1>();
        else cp_wait<0>();
        __syncthreads();
        if (kt + 2 < ktiles) stage(kt + 2, (kt + 2) % 3);
        compute(kt % 3);
    }
}

// epilogue iterator (8 warps, 64x32)
template <class F>
__device__ __forceinline__ void epi128(float (&acc)[4][4][4], F f) {
    const int lane = threadIdx.x & 31, warp = threadIdx.x >> 5;
    const int wm = (warp >> 2) * 64, wn = (warp & 3) * 32;
    const int gid = lane >> 2, tc = lane & 3;
#pragma unroll
    for (int mt = 0; mt < 4; mt++)
#pragma unroll
        for (int nt = 0; nt < 4; nt++)
#pragma unroll
            for (int r = 0; r < 4; r++) {
                int row = wm + mt * 16 + gid + ((r >> 1) << 3);
                int col = wn + nt * 8 + tc * 2 + (r & 1);
                f(row, col, acc[mt][nt][r]);
            }
}

// fused SiLU epilogue: columns are interleaved [g,u]; each thread holds (g,u)
// pairs. f(row, act_col_local, act_value). act_col_local in [0,64).
template <class F>
__device__ __forceinline__ void epi128_silu(float (&acc)[4][4][4], F f) {
    const int lane = threadIdx.x & 31, warp = threadIdx.x >> 5;
    const int wm = (warp >> 2) * 64, wn = (warp & 3) * 32;
    const int gid = lane >> 2, tc = lane & 3;
#pragma unroll
    for (int mt = 0; mt < 4; mt++)
#pragma unroll
        for (int nt = 0; nt < 4; nt++) {
            int acol = (wn >> 1) + nt * 4 + tc;
#pragma unroll
            for (int rr = 0; rr < 2; rr++) {
                int row = wm + mt * 16 + gid + rr * 8;
                float g = acc[mt][nt][rr * 2];
                float u = acc[mt][nt][rr * 2 + 1];
                f(row, acol, silu_f(g) * u);
            }
        }
}

// ---------------- streaming splits --------------------------------------------
__global__ void k_split(const float* __restrict__ src, bf16* __restrict__ dh,
                        bf16* __restrict__ dl, int n8) {
    int i = blockIdx.x * 256 + threadIdx.x;
    if (i >= n8) return;
    const float4* s4 = reinterpret_cast<const float4*>(src) + i * 2;
    float4 a = s4[0], b = s4[1];
    bf16 hbuf[8], lbuf[8];
    split_bf(a.x, hbuf[0], lbuf[0]);
    split_bf(a.y, hbuf[1], lbuf[1]);
    split_bf(a.z, hbuf[2], lbuf[2]);
    split_bf(a.w, hbuf[3], lbuf[3]);
    split_bf(b.x, hbuf[4], lbuf[4]);
    split_bf(b.y, hbuf[5], lbuf[5]);
    split_bf(b.z, hbuf[6], lbuf[6]);
    split_bf(b.w, hbuf[7], lbuf[7]);
    reinterpret_cast<uint4*>(dh)[i] = *reinterpret_cast<uint4*>(hbuf);
    reinterpret_cast<uint4*>(dl)[i] = *reinterpret_cast<uint4*>(lbuf);
}

__global__ void k_split16(const float* __restrict__ src, f16* __restrict__ d,
                          int n8) {
    int i = blockIdx.x * 256 + threadIdx.x;
    if (i >= n8) return;
    const float4* s4 = reinterpret_cast<const float4*>(src) + i * 2;
    float4 a = s4[0], b = s4[1];
    f16 buf[8];
    buf[0] = __float2half(a.x);
    buf[1] = __float2half(a.y);
    buf[2] = __float2half(a.z);
    buf[3] = __float2half(a.w);
    buf[4] = __float2half(b.x);
    buf[5] = __float2half(b.y);
    buf[6] = __float2half(b.z);
    buf[7] = __float2half(b.w);
    reinterpret_cast<uint4*>(d)[i] = *reinterpret_cast<uint4*>(buf);
}

// interleaving fp16 convert for gate/up weights: src [K][2048] with cols
// [0,1024)=g, [1024,2048)=u  ->  dst [K][2048] with cols [g0,u0,g1,u1,...]
__global__ void k_split16i(const float* __restrict__ src, f16* __restrict__ dst) {
    const int K = H;  // 1024 rows per (expert) slab
    src += (size_t)blockIdx.z * K * 2048;
    dst += (size_t)blockIdx.z * K * 2048;
    int i = blockIdx.x * 256 + threadIdx.x;   // over K*2048/8 = 262144
    int k = i >> 8, j = i & 255;              // dest block of 8 cols
    float4 g4 = *reinterpret_cast<const float4*>(src + (size_t)k * 2048 + 4 * j);
    float4 u4 = *reinterpret_cast<const float4*>(src + (size_t)k * 2048 + 1024 + 4 * j);
    f16 buf[8];
    buf[0] = __float2half(g4.x); buf[1] = __float2half(u4.x);
    buf[2] = __float2half(g4.y); buf[3] = __float2half(u4.y);
    buf[4] = __float2half(g4.z); buf[5] = __float2half(u4.z);
    buf[6] = __float2half(g4.w); buf[7] = __float2half(u4.w);
    *reinterpret_cast<uint4*>(dst + (size_t)k * 2048 + 8 * j) =
        *reinterpret_cast<uint4*>(buf);
}

__global__ void k_split_v() {
    int i = blockIdx.x * 256 + threadIdx.x;
    if (i >= T * 256 / 8) return;
    int t = i >> 5, j = (i & 31) * 8;
    const float* src = g_qkv + (size_t)t * QKV_N + (NH + NKV) * HD + j;
    float4 a = *reinterpret_cast<const float4*>(src);
    float4 b = *reinterpret_cast<const float4*>(src + 4);
    bf16 hbuf[8], lbuf[8];
    split_bf(a.x, hbuf[0], lbuf[0]);
    split_bf(a.y, hbuf[1], lbuf[1]);
    split_bf(a.z, hbuf[2], lbuf[2]);
    split_bf(a.w, hbuf[3], lbuf[3]);
    split_bf(b.x, hbuf[4], lbuf[4]);
    split_bf(b.y, hbuf[5], lbuf[5]);
    split_bf(b.z, hbuf[6], lbuf[6]);
    split_bf(b.w, hbuf[7], lbuf[7]);
    size_t o = (size_t)t * (NKV * HD) + j;
    *reinterpret_cast<uint4*>(g_vh + o) = *reinterpret_cast<uint4*>(hbuf);
    *reinterpret_cast<uint4*>(g_vl + o) = *reinterpret_cast<uint4*>(lbuf);
}

// ---------------- generic bf16 GEMM (trans-B) ----------------------------------
__global__ __launch_bounds__(256) void k_gemm(
    const bf16* __restrict__ Ah, const bf16* __restrict__ Al, int sa,
    const bf16* __restrict__ Bh, const bf16* __restrict__ Bl, int ldb,
    float* __restrict__ C, int ldc, int ktiles, const float* __restrict__ addm) {
    const int rb = blockIdx.y * 128, cb = blockIdx.x * 128;
    float acc[4][4][4];
    gemm_core_tr(
        Ah, Al, [&](int m) { return (size_t)(rb + m) * sa; }, Bh + cb, Bl + cb,
        ldb, ktiles, acc);
    epi128(acc, [&](int r, int c, float v) {
        size_t idx = (size_t)(rb + r) * ldc + cb + c;
        if (addm) v += addm[idx];
        C[idx] = v;
    });
}

// ---------------- fp16 GEMM plain (down projections) ----------------------------
__global__ __launch_bounds__(256) void k_gemm16(
    const f16* __restrict__ Ah, const f16* __restrict__ Al, int sa,
    const f16* __restrict__ Bf, int ldb, float* __restrict__ C, int ldc,
    int ktiles) {
    const int rb = blockIdx.y * 128, cb = blockIdx.x * 128;
    float acc[4][4][4];
    gemm_core_16(
        Ah, Al, [&](int m) { return (size_t)(rb + m) * sa; }, Bf + cb, ldb,
        ktiles, acc);
    epi128(acc, [&](int r, int c, float v) {
        C[(size_t)(rb + r) * ldc + cb + c] = v;
    });
}

// ---------------- shared-expert su GEMM with fused SiLU -> fp16 act -------------
__global__ __launch_bounds__(256) void k_su() {
    const int rb = blockIdx.y * 128, cb = blockIdx.x * 128;
    float acc[4][4][4];
    gemm_core_16(
        g_h2h, g_h2l, [&](int m) { return (size_t)(rb + m) * H; },
        g_wsguf + cb, 2048, H / 16, acc);
    const int ab = cb >> 1;  // 64 act cols per CTA
    epi128_silu(acc, [&](int r, int ac, float a) {
        size_t o = (size_t)(rb + r) * FDIM + ab + ac;
        split_f16(a, g_ash[o], g_asl[o]);
    });
}

// ---------------- add + rmsnorm (ln1) ---------------------------------------------
__global__ void k_add_rms1(const float* __restrict__ hs,
                           const float* __restrict__ res,
                           const float* __restrict__ w) {
    const int t = blockIdx.x, tid = threadIdx.x;
    float2 x[2];
    float ss = 0.f;
#pragma unroll
    for (int i = 0; i < 2; i++) {
        int c = (tid + i * 256) * 2;
        float2 a = *reinterpret_cast<const float2*>(hs + (size_t)t * H + c);
        float2 b = *reinterpret_cast<const float2*>(res + (size_t)t * H + c);
        float2 v = {a.x + b.x, a.y + b.y};
        *reinterpret_cast<float2*>(g_resid + (size_t)t * H + c) = v;
        x[i] = v;
        ss += v.x * v.x + v.y * v.y;
    }
    __shared__ float red[256];
    red[tid] = ss;
    __syncthreads();
    for (int s = 128; s > 0; s >>= 1) {
        if (tid < s) red[tid] += red[tid + s];
        __syncthreads();
    }
    float r = rsqrtf(red[0] / (float)H + 1e-6f);
#pragma unroll
    for (int i = 0; i < 2; i++) {
        int c = (tid + i * 256) * 2;
        bf162 h2, l2;
        split2(x[i].x * r * w[c], x[i].y * r * w[c + 1], h2, l2);
        *reinterpret_cast<bf162*>(g_hh + (size_t)t * H + c) = h2;
        *reinterpret_cast<bf162*>(g_hl + (size_t)t * H + c) = l2;
    }
}

// ---------------- rmsnorm (ln2) -----------------------------------------------------
__global__ void k_rms2(const float* __restrict__ resid2,
                       const float* __restrict__ w) {
    const int t = blockIdx.x, tid = threadIdx.x;
    float2 x[2];
    float ss = 0.f;
#pragma unroll
    for (int i = 0; i < 2; i++) {
        int c = (tid + i * 256) * 2;
        float2 v = *reinterpret_cast<const float2*>(resid2 + (size_t)t * H + c);
        x[i] = v;
        ss += v.x * v.x + v.y * v.y;
    }
    __shared__ float red[256];
    red[tid] = ss;
    __syncthreads();
    for (int s = 128; s > 0; s >>= 1) {
        if (tid < s) red[tid] += red[tid + s];
        __syncthreads();
    }
    float r = rsqrtf(red[0] / (float)H + 1e-6f);
#pragma unroll
    for (int i = 0; i < 2; i++) {
        int c = (tid + i * 256) * 2;
        float v0 = x[i].x * r * w[c], v1 = x[i].y * r * w[c + 1];
        *reinterpret_cast<float2*>(g_h + (size_t)t * H + c) = float2{v0, v1};
        f16 h0, l0, h1, l1;
        split_f16(v0, h0, l0);
        split_f16(v1, h1, l1);
        *reinterpret_cast<__half2*>(g_h2h + (size_t)t * H + c) =
            __halves2half2(h0, h1);
        *reinterpret_cast<__half2*>(g_h2l + (size_t)t * H + c) =
            __halves2half2(l0, l1);
    }
}

// ---------------- per-head rmsnorm + rope -------------------------------------------
__global__ void k_qknorm_rope(const int* __restrict__ pos_ids,
                              const float* __restrict__ qnw,
                              const float* __restrict__ knw) {
    const int t = blockIdx.x, hh = blockIdx.y, d = threadIdx.x;
    const float* src;
    const float* w;
    bf16 *dh, *dl;
    if (hh < NH) {
        src = g_qkv + (size_t)t * QKV_N + hh * HD;
        w = qnw;
        dh = g_qh + ((size_t)t * NH + hh) * HD;
        dl = g_ql + ((size_t)t * NH + hh) * HD;
    } else {
        int kk = hh - NH;
        src = g_qkv + (size_t)t * QKV_N + NH * HD + kk * HD;
        w = knw;
        dh = g_kh + ((size_t)t * NKV + kk) * HD;
        dl = g_kl + ((size_t)t * NKV + kk) * HD;
    }
    float x = src[d];
    float ss = x * x;
#pragma unroll
    for (int o = 16; o > 0; o >>= 1) ss += __shfl_xor_sync(0xffffffffu, ss, o);
    __shared__ float wsum[4];
    if ((d & 31) == 0) wsum[d >> 5] = ss;
    __syncthreads();
    ss = wsum[0] + wsum[1] + wsum[2] + wsum[3];
    float xn = x * rsqrtf(ss / (float)HD + 1e-6f) * w[d];
    __shared__ float xb[HD];
    xb[d] = xn;
    __syncthreads();
    int p = pos_ids[t];
    if (d < 64) {
        float inv = powf(10000.f, -(float)d / 64.f);
        float ang = (float)p * inv;
        float c = cosf(ang), s = sinf(ang);
        float x1 = xb[d], x2 = xb[d + 64];
        split_bf(x1 * c - x2 * s, dh[d], dl[d]);
        split_bf(x2 * c + x1 * s, dh[d + 64], dl[d + 64]);
    }
}

// ---------------- attention scores ----------------------------------------------------
__global__ __launch_bounds__(256) void k_scores() {
    const int jt = blockIdx.x, it = blockIdx.y, h = blockIdx.z;
    if (jt > it) return;
    float acc[4][4][4];
    gemm_core_nt(
        g_qh, g_ql, g_kh, g_kl,
        [&](int m) { return ((size_t)(it * 128 + m) * NH + h) * HD; },
        [&](int n) { return ((size_t)(jt * 128 + n) * NKV + (h >> 2)) * HD; },
        HD / 16, acc);
    const float scale = 0.08838834764831845f;
    float* S = g_scores + (size_t)h * T * T;
    epi128(acc, [&](int r, int c, float v) {
        int i = it * 128 + r;
        int j = jt * 128 + c;
        S[(size_t)i * T + j] = (j <= i) ? v * scale : -3.0e38f;
    });
}

// ---------------- row softmax -> bf16 P -------------------------------------------------
__global__ void k_softmax() {
    const int i = blockIdx.x, h = blockIdx.y, tid = threadIdx.x;
    const float4* S4 =
        reinterpret_cast<const float4*>(g_scores + ((size_t)h * T + i) * T);
    bf162* Ph = reinterpret_cast<bf162*>(g_ph + ((size_t)h * T + i) * T);
    bf162* Pl = reinterpret_cast<bf162*>(g_pl + ((size_t)h * T + i) * T);
    const int n4 = (((i >> 7) + 1) << 7) >> 2;
    __shared__ float4 buf[T / 4];
    __shared__ float red[256];
    float mx = -3.4e38f;
    for (int j = tid; j < n4; j += 256) {
        float4 v = S4[j];
        buf[j] = v;
        mx = fmaxf(fmaxf(mx, fmaxf(v.x, v.y)), fmaxf(v.z, v.w));
    }
    red[tid] = mx;
    __syncthreads();
    for (int s = 128; s > 0; s >>= 1) {
        if (tid < s) red[tid] = fmaxf(red[tid], red[tid + s]);
        __syncthreads();
    }
    mx = red[0];
    __syncthreads();
    float sm = 0.f;
    for (int j = tid; j < n4; j += 256) {
        float4 v = buf[j];
        v.x = expf(v.x - mx);
        v.y = expf(v.y - mx);
        v.z = expf(v.z - mx);
        v.w = expf(v.w - mx);
        buf[j] = v;
        sm += v.x + v.y + v.z + v.w;
    }
    red[tid] = sm;
    __syncthreads();
    for (int s = 128; s > 0; s >>= 1) {
        if (tid < s) red[tid] += red[tid + s];
        __syncthreads();
    }
    float inv = 1.f / red[0];
    for (int j = tid; j < n4; j += 256) {
        float4 v = buf[j];
        bf162 h0, l0, h1, l1;
        split2(v.x * inv, v.y * inv, h0, l0);
        split2(v.z * inv, v.w * inv, h1, l1);
        Ph[j * 2] = h0;
        Ph[j * 2 + 1] = h1;
        Pl[j * 2] = l0;
        Pl[j * 2 + 1] = l1;
    }
}

// ---------------- ctx = P @ V -----------------------------------------------------------
__global__ __launch_bounds__(256) void k_ctx() {
    const int it = blockIdx.y, h = blockIdx.z;
    float acc[4][4][4];
    const int cb = (h >> 2) * 128;
    gemm_core_tr(
        g_ph, g_pl, [&](int m) { return ((size_t)h * T + it * 128 + m) * T; },
        g_vh + cb, g_vl + cb, NKV * HD, (it + 1) * 8, acc);
    epi128(acc, [&](int r, int c, float v) {
        size_t o = (size_t)(it * 128 + r) * (NH * HD) + h * HD + c;
        split_bf(v, g_ch[o], g_cl[o]);
    });
}

// ---------------- gate logits -------------------------------------------------------------
__global__ void k_gate(const float* __restrict__ gw) {
    const int t = blockIdx.x, tid = threadIdx.x;
    const int e = tid & 15, seg = tid >> 4;
    const float* hr = g_h + (size_t)t * H;
    float s = 0.f;
    for (int k = seg * 128; k < seg * 128 + 128; k++) s += hr[k] * gw[k * NE + e];
    __shared__ float red[128];
    red[tid] = s;
    __syncthreads();
    if (tid < NE) {
        float v = 0.f;
        for (int g = 0; g < 8; g++) v += red[g * 16 + tid];
        g_logits[t * NE + tid] = v;
    }
}

// ---------------- routing -------------------------------------------------------------------
__global__ void k_zero_cnt() {
    if (threadIdx.x < NE) g_cnt[threadIdx.x] = 0;
}

__global__ void k_route(const float* __restrict__ bias) {
    const int t = blockIdx.x * 256 + threadIdx.x;
    if (t >= T) return;
    float sig[NE], sfc[NE];
#pragma unroll
    for (int e = 0; e < NE; e++) {
        float l = g_logits[t * NE + e];
        sig[e] = 1.f / (1.f + expf(-l));
        sfc[e] = sig[e] + bias[e];
    }
    float gs[4];
#pragma unroll
    for (int g = 0; g < 4; g++) {
        float m1 = -3.4e38f, m2 = -3.4e38f;
#pragma unroll
        for (int i = 0; i < 4; i++) {
            float v = sfc[g * 4 + i];
            if (v > m1) { m2 = m1; m1 = v; }
            else if (v > m2) m2 = v;
        }
        gs[g] = m1 + m2;
    }
    int g1 = 0;
    for (int g = 1; g < 4; g++) if (gs[g] > gs[g1]) g1 = g;
    int g2 = -1;
    for (int g = 0; g < 4; g++) {
        if (g == g1) continue;
        if (g2 < 0 || gs[g] > gs[g2]) g2 = g;
    }
    bool allowed[NE];
#pragma unroll
    for (int e = 0; e < NE; e++) {
        int g = e >> 2;
        allowed[e] = (g == g1) || (g == g2);
    }
    int sel[4];
    bool picked[NE];
#pragma unroll
    for (int e = 0; e < NE; e++) picked[e] = false;
    float wsum = 0.f;
#pragma unroll
    for (int it = 0; it < 4; it++) {
        int bi = -1;
        float bv = -3.4e38f;
        for (int e = 0; e < NE; e++) {
            if (!allowed[e] || picked[e]) continue;
            if (sfc[e] > bv) { bv = sfc[e]; bi = e; }
        }
        picked[bi] = true;
        sel[it] = bi;
        wsum += sig[bi];
    }
    float inv = 1.f / (wsum + 1e-20f);
#pragma unroll
    for (int it = 0; it < 4; it++) {
        int e = sel[it];
        int pos = atomicAdd(&g_cnt[e], 1);
        g_ptok[e * T + pos] = t;
        g_pw[e * T + pos] = sig[e] * inv;
    }
}

__global__ void k_offsets() {
    if (threadIdx.x == 0) {
        int run = 0;
        for (int e = 0; e < NE; e++) {
            g_poff[e] = run;
            run += ((g_cnt[e] + 127) / 128) * 128;
        }
    }
}

// ---------------- MoE gu GEMM + fused SiLU -> fp16 act ------------------------------
__global__ __launch_bounds__(256) void k_moe_gu() {
    const int e = blockIdx.z, rt = blockIdx.y, bn = blockIdx.x;
    const int cnt = g_cnt[e];
    if (rt * 128 >= cnt) return;
    const int off = g_poff[e];
    const int* ptok = g_ptok + e * T;
    const int cb = bn * 128;
    float acc[4][4][4];
    gemm_core_16(
        g_h2h, g_h2l,
        [&](int m) {
            int lr = rt * 128 + m;
            int tok = ptok[lr < cnt ? lr : cnt - 1];
            return (size_t)tok * H;
        },
        g_w13f + (size_t)e * H * 2048 + cb, 2048, H / 16, acc);
    const int ab = bn * 64;
    epi128_silu(acc, [&](int r, int ac, float a) {
        size_t row = (size_t)off + rt * 128 + r;
        size_t o = row * FDIM + ab + ac;
        split_f16(a, g_amh[o], g_aml[o]);
    });
}

// ---------------- MoE y, scatter-add (fp16 2-term) -----------------------------------
__global__ __launch_bounds__(256) void k_moe_y(float* __restrict__ outp) {
    const int e = blockIdx.z, rt = blockIdx.y, bn = blockIdx.x;
    const int cnt = g_cnt[e];
    if (rt * 128 >= cnt) return;
    const int off = g_poff[e];
    const int cb = bn * 128;
    float acc[4][4][4];
    gemm_core_16(
        g_amh, g_aml,
        [&](int m) { return ((size_t)off + rt * 128 + m) * FDIM; },
        g_w2f + (size_t)e * FDIM * H + cb, H, FDIM / 16, acc);
    epi128(acc, [&](int r, int c, float v) {
        int lr = rt * 128 + r;
        if (lr >= cnt) return;
        int tok = g_ptok[e * T + lr];
        float w = 2.0f * g_pw[e * T + lr];
        atomicAdd(&outp[(size_t)tok * H + cb + c], w * v);
    });
}

// ---------------- launch -----------------------------------------------------------------
extern "C" void kernel_launch(void* const* d_in, const int* in_sizes, int n_in,
                              void* d_out, int out_size) {
    const float* hs = (const float*)d_in[0];
    const float* res = (const float*)d_in[1];
    const int* pos = (const int*)d_in[2];
    const float* ln1_w = (const float*)d_in[3];
    const float* qkv_w = (const float*)d_in[4];
    const float* qnorm_w = (const float*)d_in[5];
    const float* knorm_w = (const float*)d_in[6];
    const float* dense_w = (const float*)d_in[7];
    const float* ln2_w = (const float*)d_in[8];
    const float* gate_w = (const float*)d_in[9];
    const float* expert_bias = (const float*)d_in[10];
    const float* w13 = (const float*)d_in[11];
    const float* w2 = (const float*)d_in[12];
    const float* ws_gate_up = (const float*)d_in[13];
    const float* ws_down = (const float*)d_in[14];

    float* out_mlp = (float*)d_out;
    float* out_resid2 = (float*)d_out + (size_t)T * H;

    float* p_resid;  cudaGetSymbolAddress((void**)&p_resid, g_resid);
    float* p_qkv;    cudaGetSymbolAddress((void**)&p_qkv, g_qkv);
    bf16 *p_hh, *p_hl, *p_wqkvh, *p_wqkvl, *p_wdh, *p_wdl, *p_ch, *p_cl;
    f16 *p_ash, *p_asl, *p_w13f, *p_w2f, *p_wsguf, *p_wsdf;
    cudaGetSymbolAddress((void**)&p_hh, g_hh);
    cudaGetSymbolAddress((void**)&p_hl, g_hl);
    cudaGetSymbolAddress((void**)&p_wqkvh, g_wqkvh);
    cudaGetSymbolAddress((void**)&p_wqkvl, g_wqkvl);
    cudaGetSymbolAddress((void**)&p_wdh, g_wdh);
    cudaGetSymbolAddress((void**)&p_wdl, g_wdl);
    cudaGetSymbolAddress((void**)&p_ch, g_ch);
    cudaGetSymbolAddress((void**)&p_cl, g_cl);
    cudaGetSymbolAddress((void**)&p_ash, g_ash);
    cudaGetSymbolAddress((void**)&p_asl, g_asl);
    cudaGetSymbolAddress((void**)&p_w13f, g_w13f);
    cudaGetSymbolAddress((void**)&p_w2f, g_w2f);
    cudaGetSymbolAddress((void**)&p_wsguf, g_wsguf);
    cudaGetSymbolAddress((void**)&p_wsdf, g_wsdf);

    static bool attrs_set = false;
    if (!attrs_set) {
        cudaFuncSetAttribute(k_gemm, cudaFuncAttributeMaxDynamicSharedMemorySize, GSMEM_TR);
        cudaFuncSetAttribute(k_scores, cudaFuncAttributeMaxDynamicSharedMemorySize, GSMEM_NT);
        cudaFuncSetAttribute(k_ctx, cudaFuncAttributeMaxDynamicSharedMemorySize, GSMEM_TR);
        cudaFuncSetAttribute(k_gemm16, cudaFuncAttributeMaxDynamicSharedMemorySize, GSMEM_16);
        cudaFuncSetAttribute(k_su, cudaFuncAttributeMaxDynamicSharedMemorySize, GSMEM_16);
        cudaFuncSetAttribute(k_moe_gu, cudaFuncAttributeMaxDynamicSharedMemorySize, GSMEM_16);
        cudaFuncSetAttribute(k_moe_y, cudaFuncAttributeMaxDynamicSharedMemorySize, GSMEM_16);
        attrs_set = true;
    }

    // weight conversions
    k_split<<<(H * QKV_N / 8 + 255) / 256, 256>>>(qkv_w, p_wqkvh, p_wqkvl, H * QKV_N / 8);
    k_split<<<(H * H / 8 + 255) / 256, 256>>>(dense_w, p_wdh, p_wdl, H * H / 8);
    k_split16i<<<dim3(H * 2048 / 8 / 256, 1, NE), 256>>>(w13, p_w13f);
    k_split16<<<((int)((size_t)NE * FDIM * H / 8) + 255) / 256, 256>>>(w2, p_w2f, (int)((size_t)NE * FDIM * H / 8));
    k_split16i<<<dim3(H * 2048 / 8 / 256, 1, 1), 256>>>(ws_gate_up, p_wsguf);
    k_split16<<<(FDIM * H / 8 + 255) / 256, 256>>>(ws_down, p_wsdf, FDIM * H / 8);

    // 1. resid + ln1
    k_add_rms1<<<T, 256>>>(hs, res, ln1_w);
    // 2. qkv
    k_gemm<<<dim3(QKV_N / 128, T / 128), 256, GSMEM_TR>>>(
        p_hh, p_hl, H, p_wqkvh, p_wqkvl, QKV_N, p_qkv, QKV_N, H / 16, nullptr);
    // 3. q/k norm+rope, V split
    k_qknorm_rope<<<dim3(T, NH + NKV), 128>>>(pos, qnorm_w, knorm_w);
    k_split_v<<<(T * 256 / 8 + 255) / 256, 256>>>();
    // 4. attention
    k_scores<<<dim3(T / 128, T / 128, NH), 256, GSMEM_NT>>>();
    k_softmax<<<dim3(T, NH), 256>>>();
    k_ctx<<<dim3(1, T / 128, NH), 256, GSMEM_TR>>>();
    // 7. resid2
    k_gemm<<<dim3(H / 128, T / 128), 256, GSMEM_TR>>>(
        p_ch, p_cl, NH * HD, p_wdh, p_wdl, H, out_resid2, H, H / 16, p_resid);
    // 8. h2
    k_rms2<<<T, 256>>>(out_resid2, ln2_w);
    // 9-10. gate + routing
    k_gate<<<T, 128>>>(gate_w);
    k_zero_cnt<<<1, 32>>>();
    k_route<<<T / 256, 256>>>(expert_bias);
    k_offsets<<<1, 32>>>();
    // 11. shared expert su GEMM + fused SiLU
    k_su<<<dim3(2048 / 128, T / 128), 256, GSMEM_16>>>();
    // 13. mlp_out = act @ ws_down
    k_gemm16<<<dim3(H / 128, T / 128), 256, GSMEM_16>>>(
        p_ash, p_asl, FDIM, p_wsdf, H, out_mlp, H, FDIM / 16);
    // 14-16. routed experts (gu+SiLU fused, then down+scatter)
    k_moe_gu<<<dim3(2048 / 128, T / 128, NE), 256, GSMEM_16>>>();
    k_moe_y<<<dim3(H / 128, T / 128, NE), 256, GSMEM_16>>>(out_mlp);

    (void)in_sizes; (void)n_in; (void)out_size;
}

// round 10
// speedup vs baseline: 1.2324x; 1.0088x over previous
#include <cuda_runtime.h>
#include <cuda_bf16.h>
#include <cuda_fp16.h>
#include <math.h>
#include <stdint.h>

#define T 2048
#define H 1024
#define NH 8
#define NKV 2
#define HD 128
#define NE 16
#define QKV_N 1536
#define FDIM 1024
#define PAD_ROWS 10240

typedef __nv_bfloat16 bf16;
typedef __nv_bfloat162 bf162;
typedef __half f16;

// ---------------- fp32 scratch ----------------------------------------------
__device__ float g_resid[T * H];
__device__ float g_h[T * H];
__device__ float g_qkv[T * QKV_N];
__device__ float g_scores[(size_t)NH * T * T];
__device__ float g_logits[T * NE];
__device__ int   g_cnt[NE];
__device__ int   g_poff[NE];
__device__ int   g_ptok[NE * T];
__device__ float g_pw[NE * T];

// ---------------- bf16 hi/lo operand buffers (router-critical path) ----------
__device__ bf16 g_hh[T * H],  g_hl[T * H];
__device__ bf16 g_qh[T * NH * HD], g_ql[T * NH * HD];
__device__ bf16 g_kh[T * NKV * HD], g_kl[T * NKV * HD];
__device__ bf16 g_vh[T * NKV * HD], g_vl[T * NKV * HD];
__device__ bf16 g_ph[(size_t)NH * T * T], g_pl[(size_t)NH * T * T];
__device__ bf16 g_ch[T * 1024], g_cl[T * 1024];
__device__ bf16 g_wqkvh[H * QKV_N], g_wqkvl[H * QKV_N];
__device__ bf16 g_wdh[H * H], g_wdl[H * H];

// ---------------- fp16 operands (post-routing path, 2-term) ------------------
__device__ f16 g_h2h[T * H], g_h2l[T * H];
__device__ f16 g_ash[T * FDIM], g_asl[T * FDIM];
__device__ f16 g_amh[(size_t)PAD_ROWS * 1024], g_aml[(size_t)PAD_ROWS * 1024];
__device__ f16 g_w13f[(size_t)NE * H * 2048];   // interleaved [g0,u0,g1,u1,...]
__device__ f16 g_w2f[(size_t)NE * FDIM * H];
__device__ f16 g_wsguf[H * 2048];               // interleaved
__device__ f16 g_wsdf[FDIM * H];

// ---------------- helpers ----------------------------------------------------
__device__ __forceinline__ void split_bf(float v, bf16& h, bf16& l) {
    h = __float2bfloat16(v);
    l = __float2bfloat16(v - __bfloat162float(h));
}
__device__ __forceinline__ void split2(float a, float b, bf162& h2, bf162& l2) {
    bf16 ha, la, hb, lb;
    split_bf(a, ha, la);
    split_bf(b, hb, lb);
    h2 = bf162{ha, hb};
    l2 = bf162{la, lb};
}
__device__ __forceinline__ void split_f16(float v, f16& h, f16& l) {
    h = __float2half(v);
    l = __float2half(v - __half2float(h));
}
__device__ __forceinline__ float silu_f(float g) {
    return g / (1.f + expf(-g));
}
__device__ __forceinline__ void mma16816(float* c, const uint32_t* a,
                                         const uint32_t* b) {
    asm volatile(
        "mma.sync.aligned.m16n8k16.row.col.f32.bf16.bf16.f32 "
        "{%0,%1,%2,%3}, {%4,%5,%6,%7}, {%8,%9}, {%0,%1,%2,%3};\n"
        : "+f"(c[0]), "+f"(c[1]), "+f"(c[2]), "+f"(c[3])
        : "r"(a[0]), "r"(a[1]), "r"(a[2]), "r"(a[3]), "r"(b[0]), "r"(b[1]));
}
__device__ __forceinline__ void mma16816f(float* c, const uint32_t* a,
                                          const uint32_t* b) {
    asm volatile(
        "mma.sync.aligned.m16n8k16.row.col.f32.f16.f16.f32 "
        "{%0,%1,%2,%3}, {%4,%5,%6,%7}, {%8,%9}, {%0,%1,%2,%3};\n"
        : "+f"(c[0]), "+f"(c[1]), "+f"(c[2]), "+f"(c[3])
        : "r"(a[0]), "r"(a[1]), "r"(a[2]), "r"(a[3]), "r"(b[0]), "r"(b[1]));
}
template <int N> __device__ __forceinline__ void cp_wait() {
    asm volatile("cp.async.wait_group %0;\n" ::"n"(N));
}
__device__ __forceinline__ void cp16(const void* src, void* dst) {
    uint32_t d = (uint32_t)__cvta_generic_to_shared(dst);
    asm volatile("cp.async.ca.shared.global [%0], [%1], 16;\n" ::"r"(d),
                 "l"(src));
}
__device__ __forceinline__ void ldm4(uint32_t& r0, uint32_t& r1, uint32_t& r2,
                                     uint32_t& r3, uint32_t addr) {
    asm volatile(
        "ldmatrix.sync.aligned.m8n8.x4.shared.b16 {%0,%1,%2,%3}, [%4];\n"
        : "=r"(r0), "=r"(r1), "=r"(r2), "=r"(r3)
        : "r"(addr));
}
__device__ __forceinline__ void ldm4t(uint32_t& r0, uint32_t& r1, uint32_t& r2,
                                      uint32_t& r3, uint32_t addr) {
    asm volatile(
        "ldmatrix.sync.aligned.m8n8.x4.trans.shared.b16 {%0,%1,%2,%3}, [%4];\n"
        : "=r"(r0), "=r"(r1), "=r"(r2), "=r"(r3)
        : "r"(addr));
}

// ---------------- GEMM cores: 256 threads, 8 warps, warp tile 64x32 ----------
#define SROW 40
#define BROW 264
#define BROW16 136
#define NSTAGE 4
#define TA_HALVES (128 * SROW)
#define TBN_HALVES (128 * SROW)
#define TBT_HALVES (16 * BROW)
#define TBT16_HALVES (16 * BROW16)
#define GSMEM_NT ((NSTAGE * (TA_HALVES + TBN_HALVES)) * 2)
#define GSMEM_TR ((NSTAGE * (TA_HALVES + TBT_HALVES)) * 2)
#define GSMEM_16 ((NSTAGE * (TA_HALVES + TBT16_HALVES)) * 2)

// 4-stage pipeline driver (one barrier per k-slab)
#define PIPE4_RUN(STAGE, COMPUTE, KTILES)                         \
    do {                                                          \
        STAGE(0, 0);                                              \
        if ((KTILES) > 1) STAGE(1, 1);                            \
        if ((KTILES) > 2) STAGE(2, 2);                            \
        for (int kt = 0; kt < (KTILES); kt++) {                   \
            int rem = (KTILES) - kt - 1;                          \
            if (rem >= 2) cp_wait<2>();                           \
            else if (rem == 1) cp_wait<1>();                      \
            else cp_wait<0>();                                    \
            __syncthreads();                                      \
            if (kt + 3 < (KTILES)) STAGE(kt + 3, (kt + 3) & 3);   \
            COMPUTE(kt & 3);                                      \
        }                                                         \
    } while (0)

// ---- non-trans bf16 3-term core (k_scores) ----------------------------------
template <class FA, class FB>
__device__ __forceinline__ void gemm_core_nt(
    const bf16* __restrict__ Ah, const bf16* __restrict__ Al,
    const bf16* __restrict__ Bh, const bf16* __restrict__ Bl, FA rowA, FB rowB,
    int ktiles, float (&acc)[4][4][4]) {
    extern __shared__ __align__(16) bf16 smem[];
    bf16* sA = smem;
    bf16* sB = smem + NSTAGE * TA_HALVES;
    const int tid = threadIdx.x, lane = tid & 31, warp = tid >> 5;
    const int wm = (warp >> 2) * 64, wn = (warp & 3) * 32;

#pragma unroll
    for (int a = 0; a < 4; a++)
#pragma unroll
        for (int b = 0; b < 4; b++)
#pragma unroll
            for (int r = 0; r < 4; r++) acc[a][b][r] = 0.f;

    auto stage = [&](int kt, int s) {
        bf16* dA = sA + s * TA_HALVES;
        bf16* dB = sB + s * TBN_HALVES;
#pragma unroll
        for (int i = tid; i < 512; i += 256) {
            int row = i >> 2, c = i & 3;
            int koff = kt * 16 + (c & 1) * 8;
            cp16((c < 2 ? Ah : Al) + rowA(row) + koff, dA + row * SROW + c * 8);
            cp16((c < 2 ? Bh : Bl) + rowB(row) + koff, dB + row * SROW + c * 8);
        }
        asm volatile("cp.async.commit_group;\n");
    };

    const int arow = ((lane >> 3) & 1) * 8 + (lane & 7);
    const int acol = (lane >> 4) * 8;
    const int brow = ((lane >> 4) & 1) * 8 + (lane & 7);
    const int bcol = ((lane >> 3) & 1) * 8;

    auto compute = [&](int s) {
        const bf16* A = sA + s * TA_HALVES;
        const bf16* B = sB + s * TBN_HALVES;
        uint32_t fah[4][4], fal[4][4], fbh[4][2], fbl[4][2];
#pragma unroll
        for (int mt = 0; mt < 4; mt++) {
            uint32_t ad = (uint32_t)__cvta_generic_to_shared(
                A + (wm + mt * 16 + arow) * SROW + acol);
            ldm4(fah[mt][0], fah[mt][1], fah[mt][2], fah[mt][3], ad);
            ldm4(fal[mt][0], fal[mt][1], fal[mt][2], fal[mt][3], ad + 32);
        }
#pragma unroll
        for (int p = 0; p < 2; p++) {
            uint32_t bd = (uint32_t)__cvta_generic_to_shared(
                B + (wn + p * 16 + brow) * SROW + bcol);
            ldm4(fbh[2 * p][0], fbh[2 * p][1], fbh[2 * p + 1][0],
                 fbh[2 * p + 1][1], bd);
            ldm4(fbl[2 * p][0], fbl[2 * p][1], fbl[2 * p + 1][0],
                 fbl[2 * p + 1][1], bd + 32);
        }
#pragma unroll
        for (int nt = 0; nt < 4; nt++)
#pragma unroll
            for (int mt = 0; mt < 4; mt++) mma16816(acc[mt][nt], fah[mt], fbh[nt]);
#pragma unroll
        for (int nt = 0; nt < 4; nt++)
#pragma unroll
            for (int mt = 0; mt < 4; mt++) mma16816(acc[mt][nt], fal[mt], fbh[nt]);
#pragma unroll
        for (int nt = 0; nt < 4; nt++)
#pragma unroll
            for (int mt = 0; mt < 4; mt++) mma16816(acc[mt][nt], fah[mt], fbl[nt]);
    };

    PIPE4_RUN(stage, compute, ktiles);
}

// ---- trans bf16 3-term core ----------------------------------------------------
template <class FA>
__device__ __forceinline__ void gemm_core_tr(
    const bf16* __restrict__ Ah, const bf16* __restrict__ Al, FA rowA,
    const bf16* __restrict__ Bh, const bf16* __restrict__ Bl, int ldb,
    int ktiles, float (&acc)[4][4][4]) {
    extern __shared__ __align__(16) bf16 smem[];
    bf16* sA = smem;
    bf16* sB = smem + NSTAGE * TA_HALVES;
    const int tid = threadIdx.x, lane = tid & 31, warp = tid >> 5;
    const int wm = (warp >> 2) * 64, wn = (warp & 3) * 32;

#pragma unroll
    for (int a = 0; a < 4; a++)
#pragma unroll
        for (int b = 0; b < 4; b++)
#pragma unroll
            for (int r = 0; r < 4; r++) acc[a][b][r] = 0.f;

    auto stage = [&](int kt, int s) {
        bf16* dA = sA + s * TA_HALVES;
        bf16* dB = sB + s * TBT_HALVES;
#pragma unroll
        for (int i = tid; i < 512; i += 256) {
            int row = i >> 2, c = i & 3;
            int koff = kt * 16 + (c & 1) * 8;
            cp16((c < 2 ? Ah : Al) + rowA(row) + koff, dA + row * SROW + c * 8);
            int brw = i >> 5, sub = i & 31;
            int half = sub >> 4, nseg = sub & 15;
            const bf16* bsrc =
                (half ? Bl : Bh) + (size_t)(kt * 16 + brw) * ldb + nseg * 8;
            cp16(bsrc, dB + brw * BROW + half * 128 + nseg * 8);
        }
        asm volatile("cp.async.commit_group;\n");
    };

    const int arow = ((lane >> 3) & 1) * 8 + (lane & 7);
    const int acol = (lane >> 4) * 8;
    const int tkrow = (lane & 7) + ((lane >> 3) & 1) * 8;
    const int tnoff = (lane >> 4) * 8;

    auto compute = [&](int s) {
        const bf16* A = sA + s * TA_HALVES;
        const bf16* B = sB + s * TBT_HALVES;
        uint32_t fah[4][4], fal[4][4], fbh[4][2], fbl[4][2];
#pragma unroll
        for (int mt = 0; mt < 4; mt++) {
            uint32_t ad = (uint32_t)__cvta_generic_to_shared(
                A + (wm + mt * 16 + arow) * SROW + acol);
            ldm4(fah[mt][0], fah[mt][1], fah[mt][2], fah[mt][3], ad);
            ldm4(fal[mt][0], fal[mt][1], fal[mt][2], fal[mt][3], ad + 32);
        }
#pragma unroll
        for (int p = 0; p < 2; p++) {
            uint32_t bd = (uint32_t)__cvta_generic_to_shared(
                B + tkrow * BROW + wn + p * 16 + tnoff);
            ldm4t(fbh[2 * p][0], fbh[2 * p][1], fbh[2 * p + 1][0],
                  fbh[2 * p + 1][1], bd);
            ldm4t(fbl[2 * p][0], fbl[2 * p][1], fbl[2 * p + 1][0],
                  fbl[2 * p + 1][1], bd + 256);
        }
#pragma unroll
        for (int nt = 0; nt < 4; nt++)
#pragma unroll
            for (int mt = 0; mt < 4; mt++) mma16816(acc[mt][nt], fah[mt], fbh[nt]);
#pragma unroll
        for (int nt = 0; nt < 4; nt++)
#pragma unroll
            for (int mt = 0; mt < 4; mt++) mma16816(acc[mt][nt], fal[mt], fbh[nt]);
#pragma unroll
        for (int nt = 0; nt < 4; nt++)
#pragma unroll
            for (int mt = 0; mt < 4; mt++) mma16816(acc[mt][nt], fah[mt], fbl[nt]);
    };

    PIPE4_RUN(stage, compute, ktiles);
}

// ---- trans fp16 2-term core ------------------------------------------------------
template <class FA>
__device__ __forceinline__ void gemm_core_16(
    const f16* __restrict__ Ah, const f16* __restrict__ Al, FA rowA,
    const f16* __restrict__ Bf, int ldb, int ktiles, float (&acc)[4][4][4]) {
    extern __shared__ __align__(16) bf16 smem[];
    f16* sA = reinterpret_cast<f16*>(smem);
    f16* sB = sA + NSTAGE * TA_HALVES;
    const int tid = threadIdx.x, lane = tid & 31, warp = tid >> 5;
    const int wm = (warp >> 2) * 64, wn = (warp & 3) * 32;

#pragma unroll
    for (int a = 0; a < 4; a++)
#pragma unroll
        for (int b = 0; b < 4; b++)
#pragma unroll
            for (int r = 0; r < 4; r++) acc[a][b][r] = 0.f;

    auto stage = [&](int kt, int s) {
        f16* dA = sA + s * TA_HALVES;
        f16* dB = sB + s * TBT16_HALVES;
#pragma unroll
        for (int i = tid; i < 512; i += 256) {
            int row = i >> 2, c = i & 3;
            int koff = kt * 16 + (c & 1) * 8;
            cp16((c < 2 ? Ah : Al) + rowA(row) + koff, dA + row * SROW + c * 8);
        }
        {
            int i = tid;
            int brw = i >> 4, nseg = i & 15;
            const f16* bsrc = Bf + (size_t)(kt * 16 + brw) * ldb + nseg * 8;
            cp16(bsrc, dB + brw * BROW16 + nseg * 8);
        }
        asm volatile("cp.async.commit_group;\n");
    };

    const int arow = ((lane >> 3) & 1) * 8 + (lane & 7);
    const int acol = (lane >> 4) * 8;
    const int tkrow = (lane & 7) + ((lane >> 3) & 1) * 8;
    const int tnoff = (lane >> 4) * 8;

    auto compute = [&](int s) {
        const f16* A = sA + s * TA_HALVES;
        const f16* B = sB + s * TBT16_HALVES;
        uint32_t fah[4][4], fal[4][4], fb[4][2];
#pragma unroll
        for (int mt = 0; mt < 4; mt++) {
            uint32_t ad = (uint32_t)__cvta_generic_to_shared(
                A + (wm + mt * 16 + arow) * SROW + acol);
            ldm4(fah[mt][0], fah[mt][1], fah[mt][2], fah[mt][3], ad);
            ldm4(fal[mt][0], fal[mt][1], fal[mt][2], fal[mt][3], ad + 32);
        }
#pragma unroll
        for (int p = 0; p < 2; p++) {
            uint32_t bd = (uint32_t)__cvta_generic_to_shared(
                B + tkrow * BROW16 + wn + p * 16 + tnoff);
            ldm4t(fb[2 * p][0], fb[2 * p][1], fb[2 * p + 1][0],
                  fb[2 * p + 1][1], bd);
        }
#pragma unroll
        for (int nt = 0; nt < 4; nt++)
#pragma unroll
            for (int mt = 0; mt < 4; mt++) mma16816f(acc[mt][nt], fah[mt], fb[nt]);
#pragma unroll
        for (int nt = 0; nt < 4; nt++)
#pragma unroll
            for (int mt = 0; mt < 4; mt++) mma16816f(acc[mt][nt], fal[mt], fb[nt]);
    };

    PIPE4_RUN(stage, compute, ktiles);
}

// epilogue iterator (8 warps, 64x32)
template <class F>
__device__ __forceinline__ void epi128(float (&acc)[4][4][4], F f) {
    const int lane = threadIdx.x & 31, warp = threadIdx.x >> 5;
    const int wm = (warp >> 2) * 64, wn = (warp & 3) * 32;
    const int gid = lane >> 2, tc = lane & 3;
#pragma unroll
    for (int mt = 0; mt < 4; mt++)
#pragma unroll
        for (int nt = 0; nt < 4; nt++)
#pragma unroll
            for (int r = 0; r < 4; r++) {
                int row = wm + mt * 16 + gid + ((r >> 1) << 3);
                int col = wn + nt * 8 + tc * 2 + (r & 1);
                f(row, col, acc[mt][nt][r]);
            }
}

// fused SiLU epilogue: interleaved [g,u] columns; f(row, act_col, act)
template <class F>
__device__ __forceinline__ void epi128_silu(float (&acc)[4][4][4], F f) {
    const int lane = threadIdx.x & 31, warp = threadIdx.x >> 5;
    const int wm = (warp >> 2) * 64, wn = (warp & 3) * 32;
    const int gid = lane >> 2, tc = lane & 3;
#pragma unroll
    for (int mt = 0; mt < 4; mt++)
#pragma unroll
        for (int nt = 0; nt < 4; nt++) {
            int acol = (wn >> 1) + nt * 4 + tc;
#pragma unroll
            for (int rr = 0; rr < 2; rr++) {
                int row = wm + mt * 16 + gid + rr * 8;
                float g = acc[mt][nt][rr * 2];
                float u = acc[mt][nt][rr * 2 + 1];
                f(row, acol, silu_f(g) * u);
            }
        }
}

// ---------------- streaming splits --------------------------------------------
__global__ void k_split(const float* __restrict__ src, bf16* __restrict__ dh,
                        bf16* __restrict__ dl, int n8) {
    int i = blockIdx.x * 256 + threadIdx.x;
    if (i >= n8) return;
    const float4* s4 = reinterpret_cast<const float4*>(src) + i * 2;
    float4 a = s4[0], b = s4[1];
    bf16 hbuf[8], lbuf[8];
    split_bf(a.x, hbuf[0], lbuf[0]);
    split_bf(a.y, hbuf[1], lbuf[1]);
    split_bf(a.z, hbuf[2], lbuf[2]);
    split_bf(a.w, hbuf[3], lbuf[3]);
    split_bf(b.x, hbuf[4], lbuf[4]);
    split_bf(b.y, hbuf[5], lbuf[5]);
    split_bf(b.z, hbuf[6], lbuf[6]);
    split_bf(b.w, hbuf[7], lbuf[7]);
    reinterpret_cast<uint4*>(dh)[i] = *reinterpret_cast<uint4*>(hbuf);
    reinterpret_cast<uint4*>(dl)[i] = *reinterpret_cast<uint4*>(lbuf);
}

__global__ void k_split16(const float* __restrict__ src, f16* __restrict__ d,
                          int n8) {
    int i = blockIdx.x * 256 + threadIdx.x;
    if (i >= n8) return;
    const float4* s4 = reinterpret_cast<const float4*>(src) + i * 2;
    float4 a = s4[0], b = s4[1];
    f16 buf[8];
    buf[0] = __float2half(a.x);
    buf[1] = __float2half(a.y);
    buf[2] = __float2half(a.z);
    buf[3] = __float2half(a.w);
    buf[4] = __float2half(b.x);
    buf[5] = __float2half(b.y);
    buf[6] = __float2half(b.z);
    buf[7] = __float2half(b.w);
    reinterpret_cast<uint4*>(d)[i] = *reinterpret_cast<uint4*>(buf);
}

// interleaving fp16 convert for gate/up weights
__global__ void k_split16i(const float* __restrict__ src, f16* __restrict__ dst) {
    const int K = H;
    src += (size_t)blockIdx.z * K * 2048;
    dst += (size_t)blockIdx.z * K * 2048;
    int i = blockIdx.x * 256 + threadIdx.x;
    int k = i >> 8, j = i & 255;
    float4 g4 = *reinterpret_cast<const float4*>(src + (size_t)k * 2048 + 4 * j);
    float4 u4 = *reinterpret_cast<const float4*>(src + (size_t)k * 2048 + 1024 + 4 * j);
    f16 buf[8];
    buf[0] = __float2half(g4.x); buf[1] = __float2half(u4.x);
    buf[2] = __float2half(g4.y); buf[3] = __float2half(u4.y);
    buf[4] = __float2half(g4.z); buf[5] = __float2half(u4.z);
    buf[6] = __float2half(g4.w); buf[7] = __float2half(u4.w);
    *reinterpret_cast<uint4*>(dst + (size_t)k * 2048 + 8 * j) =
        *reinterpret_cast<uint4*>(buf);
}

__global__ void k_split_v() {
    int i = blockIdx.x * 256 + threadIdx.x;
    if (i >= T * 256 / 8) return;
    int t = i >> 5, j = (i & 31) * 8;
    const float* src = g_qkv + (size_t)t * QKV_N + (NH + NKV) * HD + j;
    float4 a = *reinterpret_cast<const float4*>(src);
    float4 b = *reinterpret_cast<const float4*>(src + 4);
    bf16 hbuf[8], lbuf[8];
    split_bf(a.x, hbuf[0], lbuf[0]);
    split_bf(a.y, hbuf[1], lbuf[1]);
    split_bf(a.z, hbuf[2], lbuf[2]);
    split_bf(a.w, hbuf[3], lbuf[3]);
    split_bf(b.x, hbuf[4], lbuf[4]);
    split_bf(b.y, hbuf[5], lbuf[5]);
    split_bf(b.z, hbuf[6], lbuf[6]);
    split_bf(b.w, hbuf[7], lbuf[7]);
    size_t o = (size_t)t * (NKV * HD) + j;
    *reinterpret_cast<uint4*>(g_vh + o) = *reinterpret_cast<uint4*>(hbuf);
    *reinterpret_cast<uint4*>(g_vl + o) = *reinterpret_cast<uint4*>(lbuf);
}

// ---------------- generic bf16 GEMM (trans-B) ----------------------------------
__global__ __launch_bounds__(256) void k_gemm(
    const bf16* __restrict__ Ah, const bf16* __restrict__ Al, int sa,
    const bf16* __restrict__ Bh, const bf16* __restrict__ Bl, int ldb,
    float* __restrict__ C, int ldc, int ktiles, const float* __restrict__ addm) {
    const int rb = blockIdx.y * 128, cb = blockIdx.x * 128;
    float acc[4][4][4];
    gemm_core_tr(
        Ah, Al, [&](int m) { return (size_t)(rb + m) * sa; }, Bh + cb, Bl + cb,
        ldb, ktiles, acc);
    epi128(acc, [&](int r, int c, float v) {
        size_t idx = (size_t)(rb + r) * ldc + cb + c;
        if (addm) v += addm[idx];
        C[idx] = v;
    });
}

// ---------------- fp16 GEMM plain (down projections) ----------------------------
__global__ __launch_bounds__(256) void k_gemm16(
    const f16* __restrict__ Ah, const f16* __restrict__ Al, int sa,
    const f16* __restrict__ Bf, int ldb, float* __restrict__ C, int ldc,
    int ktiles) {
    const int rb = blockIdx.y * 128, cb = blockIdx.x * 128;
    float acc[4][4][4];
    gemm_core_16(
        Ah, Al, [&](int m) { return (size_t)(rb + m) * sa; }, Bf + cb, ldb,
        ktiles, acc);
    epi128(acc, [&](int r, int c, float v) {
        C[(size_t)(rb + r) * ldc + cb + c] = v;
    });
}

// ---------------- shared-expert su GEMM with fused SiLU -> fp16 act -------------
__global__ __launch_bounds__(256) void k_su() {
    const int rb = blockIdx.y * 128, cb = blockIdx.x * 128;
    float acc[4][4][4];
    gemm_core_16(
        g_h2h, g_h2l, [&](int m) { return (size_t)(rb + m) * H; },
        g_wsguf + cb, 2048, H / 16, acc);
    const int ab = cb >> 1;
    epi128_silu(acc, [&](int r, int ac, float a) {
        size_t o = (size_t)(rb + r) * FDIM + ab + ac;
        split_f16(a, g_ash[o], g_asl[o]);
    });
}

// ---------------- add + rmsnorm (ln1) ---------------------------------------------
__global__ void k_add_rms1(const float* __restrict__ hs,
                           const float* __restrict__ res,
                           const float* __restrict__ w) {
    const int t = blockIdx.x, tid = threadIdx.x;
    float2 x[2];
    float ss = 0.f;
#pragma unroll
    for (int i = 0; i < 2; i++) {
        int c = (tid + i * 256) * 2;
        float2 a = *reinterpret_cast<const float2*>(hs + (size_t)t * H + c);
        float2 b = *reinterpret_cast<const float2*>(res + (size_t)t * H + c);
        float2 v = {a.x + b.x, a.y + b.y};
        *reinterpret_cast<float2*>(g_resid + (size_t)t * H + c) = v;
        x[i] = v;
        ss += v.x * v.x + v.y * v.y;
    }
    __shared__ float red[256];
    red[tid] = ss;
    __syncthreads();
    for (int s = 128; s > 0; s >>= 1) {
        if (tid < s) red[tid] += red[tid + s];
        __syncthreads();
    }
    float r = rsqrtf(red[0] / (float)H + 1e-6f);
#pragma unroll
    for (int i = 0; i < 2; i++) {
        int c = (tid + i * 256) * 2;
        bf162 h2, l2;
        split2(x[i].x * r * w[c], x[i].y * r * w[c + 1], h2, l2);
        *reinterpret_cast<bf162*>(g_hh + (size_t)t * H + c) = h2;
        *reinterpret_cast<bf162*>(g_hl + (size_t)t * H + c) = l2;
    }
}

// ---------------- rmsnorm (ln2) -----------------------------------------------------
__global__ void k_rms2(const float* __restrict__ resid2,
                       const float* __restrict__ w) {
    const int t = blockIdx.x, tid = threadIdx.x;
    float2 x[2];
    float ss = 0.f;
#pragma unroll
    for (int i = 0; i < 2; i++) {
        int c = (tid + i * 256) * 2;
        float2 v = *reinterpret_cast<const float2*>(resid2 + (size_t)t * H + c);
        x[i] = v;
        ss += v.x * v.x + v.y * v.y;
    }
    __shared__ float red[256];
    red[tid] = ss;
    __syncthreads();
    for (int s = 128; s > 0; s >>= 1) {
        if (tid < s) red[tid] += red[tid + s];
        __syncthreads();
    }
    float r = rsqrtf(red[0] / (float)H + 1e-6f);
#pragma unroll
    for (int i = 0; i < 2; i++) {
        int c = (tid + i * 256) * 2;
        float v0 = x[i].x * r * w[c], v1 = x[i].y * r * w[c + 1];
        *reinterpret_cast<float2*>(g_h + (size_t)t * H + c) = float2{v0, v1};
        f16 h0, l0, h1, l1;
        split_f16(v0, h0, l0);
        split_f16(v1, h1, l1);
        *reinterpret_cast<__half2*>(g_h2h + (size_t)t * H + c) =
            __halves2half2(h0, h1);
        *reinterpret_cast<__half2*>(g_h2l + (size_t)t * H + c) =
            __halves2half2(l0, l1);
    }
}

// ---------------- per-head rmsnorm + rope -------------------------------------------
__global__ void k_qknorm_rope(const int* __restrict__ pos_ids,
                              const float* __restrict__ qnw,
                              const float* __restrict__ knw) {
    const int t = blockIdx.x, hh = blockIdx.y, d = threadIdx.x;
    const float* src;
    const float* w;
    bf16 *dh, *dl;
    if (hh < NH) {
        src = g_qkv + (size_t)t * QKV_N + hh * HD;
        w = qnw;
        dh = g_qh + ((size_t)t * NH + hh) * HD;
        dl = g_ql + ((size_t)t * NH + hh) * HD;
    } else {
        int kk = hh - NH;
        src = g_qkv + (size_t)t * QKV_N + NH * HD + kk * HD;
        w = knw;
        dh = g_kh + ((size_t)t * NKV + kk) * HD;
        dl = g_kl + ((size_t)t * NKV + kk) * HD;
    }
    float x = src[d];
    float ss = x * x;
#pragma unroll
    for (int o = 16; o > 0; o >>= 1) ss += __shfl_xor_sync(0xffffffffu, ss, o);
    __shared__ float wsum[4];
    if ((d & 31) == 0) wsum[d >> 5] = ss;
    __syncthreads();
    ss = wsum[0] + wsum[1] + wsum[2] + wsum[3];
    float xn = x * rsqrtf(ss / (float)HD + 1e-6f) * w[d];
    __shared__ float xb[HD];
    xb[d] = xn;
    __syncthreads();
    int p = pos_ids[t];
    if (d < 64) {
        float inv = powf(10000.f, -(float)d / 64.f);
        float ang = (float)p * inv;
        float c = cosf(ang), s = sinf(ang);
        float x1 = xb[d], x2 = xb[d + 64];
        split_bf(x1 * c - x2 * s, dh[d], dl[d]);
        split_bf(x2 * c + x1 * s, dh[d + 64], dl[d + 64]);
    }
}

// ---------------- attention scores ----------------------------------------------------
__global__ __launch_bounds__(256) void k_scores() {
    const int jt = blockIdx.x, it = blockIdx.y, h = blockIdx.z;
    if (jt > it) return;
    float acc[4][4][4];
    gemm_core_nt(
        g_qh, g_ql, g_kh, g_kl,
        [&](int m) { return ((size_t)(it * 128 + m) * NH + h) * HD; },
        [&](int n) { return ((size_t)(jt * 128 + n) * NKV + (h >> 2)) * HD; },
        HD / 16, acc);
    const float scale = 0.08838834764831845f;
    float* S = g_scores + (size_t)h * T * T;
    epi128(acc, [&](int r, int c, float v) {
        int i = it * 128 + r;
        int j = jt * 128 + c;
        S[(size_t)i * T + j] = (j <= i) ? v * scale : -3.0e38f;
    });
}

// ---------------- row softmax -> bf16 P -------------------------------------------------
__global__ void k_softmax() {
    const int i = blockIdx.x, h = blockIdx.y, tid = threadIdx.x;
    const float4* S4 =
        reinterpret_cast<const float4*>(g_scores + ((size_t)h * T + i) * T);
    bf162* Ph = reinterpret_cast<bf162*>(g_ph + ((size_t)h * T + i) * T);
    bf162* Pl = reinterpret_cast<bf162*>(g_pl + ((size_t)h * T + i) * T);
    const int n4 = (((i >> 7) + 1) << 7) >> 2;
    __shared__ float4 buf[T / 4];
    __shared__ float red[256];
    float mx = -3.4e38f;
    for (int j = tid; j < n4; j += 256) {
        float4 v = S4[j];
        buf[j] = v;
        mx = fmaxf(fmaxf(mx, fmaxf(v.x, v.y)), fmaxf(v.z, v.w));
    }
    red[tid] = mx;
    __syncthreads();
    for (int s = 128; s > 0; s >>= 1) {
        if (tid < s) red[tid] = fmaxf(red[tid], red[tid + s]);
        __syncthreads();
    }
    mx = red[0];
    __syncthreads();
    float sm = 0.f;
    for (int j = tid; j < n4; j += 256) {
        float4 v = buf[j];
        v.x = expf(v.x - mx);
        v.y = expf(v.y - mx);
        v.z = expf(v.z - mx);
        v.w = expf(v.w - mx);
        buf[j] = v;
        sm += v.x + v.y + v.z + v.w;
    }
    red[tid] = sm;
    __syncthreads();
    for (int s = 128; s > 0; s >>= 1) {
        if (tid < s) red[tid] += red[tid + s];
        __syncthreads();
    }
    float inv = 1.f / red[0];
    for (int j = tid; j < n4; j += 256) {
        float4 v = buf[j];
        bf162 h0, l0, h1, l1;
        split2(v.x * inv, v.y * inv, h0, l0);
        split2(v.z * inv, v.w * inv, h1, l1);
        Ph[j * 2] = h0;
        Ph[j * 2 + 1] = h1;
        Pl[j * 2] = l0;
        Pl[j * 2 + 1] = l1;
    }
}

// ---------------- ctx = P @ V -----------------------------------------------------------
__global__ __launch_bounds__(256) void k_ctx() {
    const int it = blockIdx.y, h = blockIdx.z;
    float acc[4][4][4];
    const int cb = (h >> 2) * 128;
    gemm_core_tr(
        g_ph, g_pl, [&](int m) { return ((size_t)h * T + it * 128 + m) * T; },
        g_vh + cb, g_vl + cb, NKV * HD, (it + 1) * 8, acc);
    epi128(acc, [&](int r, int c, float v) {
        size_t o = (size_t)(it * 128 + r) * (NH * HD) + h * HD + c;
        split_bf(v, g_ch[o], g_cl[o]);
    });
}

// ---------------- gate logits -------------------------------------------------------------
__global__ void k_gate(const float* __restrict__ gw) {
    const int t = blockIdx.x, tid = threadIdx.x;
    const int e = tid & 15, seg = tid >> 4;
    const float* hr = g_h + (size_t)t * H;
    float s = 0.f;
    for (int k = seg * 128; k < seg * 128 + 128; k++) s += hr[k] * gw[k * NE + e];
    __shared__ float red[128];
    red[tid] = s;
    __syncthreads();
    if (tid < NE) {
        float v = 0.f;
        for (int g = 0; g < 8; g++) v += red[g * 16 + tid];
        g_logits[t * NE + tid] = v;
    }
}

// ---------------- routing -------------------------------------------------------------------
__global__ void k_zero_cnt() {
    if (threadIdx.x < NE) g_cnt[threadIdx.x] = 0;
}

__global__ void k_route(const float* __restrict__ bias) {
    const int t = blockIdx.x * 256 + threadIdx.x;
    if (t >= T) return;
    float sig[NE], sfc[NE];
#pragma unroll
    for (int e = 0; e < NE; e++) {
        float l = g_logits[t * NE + e];
        sig[e] = 1.f / (1.f + expf(-l));
        sfc[e] = sig[e] + bias[e];
    }
    float gs[4];
#pragma unroll
    for (int g = 0; g < 4; g++) {
        float m1 = -3.4e38f, m2 = -3.4e38f;
#pragma unroll
        for (int i = 0; i < 4; i++) {
            float v = sfc[g * 4 + i];
            if (v > m1) { m2 = m1; m1 = v; }
            else if (v > m2) m2 = v;
        }
        gs[g] = m1 + m2;
    }
    int g1 = 0;
    for (int g = 1; g < 4; g++) if (gs[g] > gs[g1]) g1 = g;
    int g2 = -1;
    for (int g = 0; g < 4; g++) {
        if (g == g1) continue;
        if (g2 < 0 || gs[g] > gs[g2]) g2 = g;
    }
    bool allowed[NE];
#pragma unroll
    for (int e = 0; e < NE; e++) {
        int g = e >> 2;
        allowed[e] = (g == g1) || (g == g2);
    }
    int sel[4];
    bool picked[NE];
#pragma unroll
    for (int e = 0; e < NE; e++) picked[e] = false;
    float wsum = 0.f;
#pragma unroll
    for (int it = 0; it < 4; it++) {
        int bi = -1;
        float bv = -3.4e38f;
        for (int e = 0; e < NE; e++) {
            if (!allowed[e] || picked[e]) continue;
            if (sfc[e] > bv) { bv = sfc[e]; bi = e; }
        }
        picked[bi] = true;
        sel[it] = bi;
        wsum += sig[bi];
    }
    float inv = 1.f / (wsum + 1e-20f);
#pragma unroll
    for (int it = 0; it < 4; it++) {
        int e = sel[it];
        int pos = atomicAdd(&g_cnt[e], 1);
        g_ptok[e * T + pos] = t;
        g_pw[e * T + pos] = sig[e] * inv;
    }
}

__global__ void k_offsets() {
    if (threadIdx.x == 0) {
        int run = 0;
        for (int e = 0; e < NE; e++) {
            g_poff[e] = run;
            run += ((g_cnt[e] + 127) / 128) * 128;
        }
    }
}

// ---------------- MoE gu GEMM + fused SiLU -> fp16 act ------------------------------
__global__ __launch_bounds__(256) void k_moe_gu() {
    const int e = blockIdx.z, rt = blockIdx.y, bn = blockIdx.x;
    const int cnt = g_cnt[e];
    if (rt * 128 >= cnt) return;
    const int off = g_poff[e];
    const int* ptok = g_ptok + e * T;
    const int cb = bn * 128;
    float acc[4][4][4];
    gemm_core_16(
        g_h2h, g_h2l,
        [&](int m) {
            int lr = rt * 128 + m;
            int tok = ptok[lr < cnt ? lr : cnt - 1];
            return (size_t)tok * H;
        },
        g_w13f + (size_t)e * H * 2048 + cb, 2048, H / 16, acc);
    const int ab = bn * 64;
    epi128_silu(acc, [&](int r, int ac, float a) {
        size_t row = (size_t)off + rt * 128 + r;
        size_t o = row * FDIM + ab + ac;
        split_f16(a, g_amh[o], g_aml[o]);
    });
}

// ---------------- MoE y, scatter-add (fp16 2-term) -----------------------------------
__global__ __launch_bounds__(256) void k_moe_y(float* __restrict__ outp) {
    const int e = blockIdx.z, rt = blockIdx.y, bn = blockIdx.x;
    const int cnt = g_cnt[e];
    if (rt * 128 >= cnt) return;
    const int off = g_poff[e];
    const int cb = bn * 128;
    float acc[4][4][4];
    gemm_core_16(
        g_amh, g_aml,
        [&](int m) { return ((size_t)off + rt * 128 + m) * FDIM; },
        g_w2f + (size_t)e * FDIM * H + cb, H, FDIM / 16, acc);
    epi128(acc, [&](int r, int c, float v) {
        int lr = rt * 128 + r;
        if (lr >= cnt) return;
        int tok = g_ptok[e * T + lr];
        float w = 2.0f * g_pw[e * T + lr];
        atomicAdd(&outp[(size_t)tok * H + cb + c], w * v);
    });
}

// ---------------- stream/event setup at static init (pre-checkpoint) ------------
struct StreamInit {
    cudaStream_t s2;
    cudaEvent_t evF, evW;
    StreamInit() {
        cudaStreamCreateWithFlags(&s2, cudaStreamNonBlocking);
        cudaEventCreateWithFlags(&evF, cudaEventDisableTiming);
        cudaEventCreateWithFlags(&evW, cudaEventDisableTiming);
    }
};
static StreamInit g_si;

// ---------------- launch -----------------------------------------------------------------
extern "C" void kernel_launch(void* const* d_in, const int* in_sizes, int n_in,
                              void* d_out, int out_size) {
    const float* hs = (const float*)d_in[0];
    const float* res = (const float*)d_in[1];
    const int* pos = (const int*)d_in[2];
    const float* ln1_w = (const float*)d_in[3];
    const float* qkv_w = (const float*)d_in[4];
    const float* qnorm_w = (const float*)d_in[5];
    const float* knorm_w = (const float*)d_in[6];
    const float* dense_w = (const float*)d_in[7];
    const float* ln2_w = (const float*)d_in[8];
    const float* gate_w = (const float*)d_in[9];
    const float* expert_bias = (const float*)d_in[10];
    const float* w13 = (const float*)d_in[11];
    const float* w2 = (const float*)d_in[12];
    const float* ws_gate_up = (const float*)d_in[13];
    const float* ws_down = (const float*)d_in[14];

    float* out_mlp = (float*)d_out;
    float* out_resid2 = (float*)d_out + (size_t)T * H;

    float* p_resid;  cudaGetSymbolAddress((void**)&p_resid, g_resid);
    float* p_qkv;    cudaGetSymbolAddress((void**)&p_qkv, g_qkv);
    bf16 *p_hh, *p_hl, *p_wqkvh, *p_wqkvl, *p_wdh, *p_wdl, *p_ch, *p_cl;
    f16 *p_ash, *p_asl, *p_w13f, *p_w2f, *p_wsguf, *p_wsdf;
    cudaGetSymbolAddress((void**)&p_hh, g_hh);
    cudaGetSymbolAddress((void**)&p_hl, g_hl);
    cudaGetSymbolAddress((void**)&p_wqkvh, g_wqkvh);
    cudaGetSymbolAddress((void**)&p_wqkvl, g_wqkvl);
    cudaGetSymbolAddress((void**)&p_wdh, g_wdh);
    cudaGetSymbolAddress((void**)&p_wdl, g_wdl);
    cudaGetSymbolAddress((void**)&p_ch, g_ch);
    cudaGetSymbolAddress((void**)&p_cl, g_cl);
    cudaGetSymbolAddress((void**)&p_ash, g_ash);
    cudaGetSymbolAddress((void**)&p_asl, g_asl);
    cudaGetSymbolAddress((void**)&p_w13f, g_w13f);
    cudaGetSymbolAddress((void**)&p_w2f, g_w2f);
    cudaGetSymbolAddress((void**)&p_wsguf, g_wsguf);
    cudaGetSymbolAddress((void**)&p_wsdf, g_wsdf);

    static bool attrs_set = false;
    if (!attrs_set) {
        cudaFuncSetAttribute(k_gemm, cudaFuncAttributeMaxDynamicSharedMemorySize, GSMEM_TR);
        cudaFuncSetAttribute(k_scores, cudaFuncAttributeMaxDynamicSharedMemorySize, GSMEM_NT);
        cudaFuncSetAttribute(k_ctx, cudaFuncAttributeMaxDynamicSharedMemorySize, GSMEM_TR);
        cudaFuncSetAttribute(k_gemm16, cudaFuncAttributeMaxDynamicSharedMemorySize, GSMEM_16);
        cudaFuncSetAttribute(k_su, cudaFuncAttributeMaxDynamicSharedMemorySize, GSMEM_16);
        cudaFuncSetAttribute(k_moe_gu, cudaFuncAttributeMaxDynamicSharedMemorySize, GSMEM_16);
        cudaFuncSetAttribute(k_moe_y, cudaFuncAttributeMaxDynamicSharedMemorySize, GSMEM_16);
        attrs_set = true;
    }

    // fork: late-needed weight conversions run on side stream, overlapping
    // the attention phase. Join before k_su / k_moe_gu.
    cudaEventRecord(g_si.evF, 0);
    cudaStreamWaitEvent(g_si.s2, g_si.evF, 0);
    k_split16i<<<dim3(H * 2048 / 8 / 256, 1, NE), 256, 0, g_si.s2>>>(w13, p_w13f);
    k_split16<<<((int)((size_t)NE * FDIM * H / 8) + 255) / 256, 256, 0, g_si.s2>>>(
        w2, p_w2f, (int)((size_t)NE * FDIM * H / 8));
    k_split16i<<<dim3(H * 2048 / 8 / 256, 1, 1), 256, 0, g_si.s2>>>(ws_gate_up, p_wsguf);
    k_split16<<<(FDIM * H / 8 + 255) / 256, 256, 0, g_si.s2>>>(ws_down, p_wsdf,
                                                               FDIM * H / 8);
    cudaEventRecord(g_si.evW, g_si.s2);

    // main stream: early weight conversions + the full chain
    k_split<<<(H * QKV_N / 8 + 255) / 256, 256>>>(qkv_w, p_wqkvh, p_wqkvl, H * QKV_N / 8);
    k_split<<<(H * H / 8 + 255) / 256, 256>>>(dense_w, p_wdh, p_wdl, H * H / 8);

    // 1. resid + ln1
    k_add_rms1<<<T, 256>>>(hs, res, ln1_w);
    // 2. qkv
    k_gemm<<<dim3(QKV_N / 128, T / 128), 256, GSMEM_TR>>>(
        p_hh, p_hl, H, p_wqkvh, p_wqkvl, QKV_N, p_qkv, QKV_N, H / 16, nullptr);
    // 3. q/k norm+rope, V split
    k_qknorm_rope<<<dim3(T, NH + NKV), 128>>>(pos, qnorm_w, knorm_w);
    k_split_v<<<(T * 256 / 8 + 255) / 256, 256>>>();
    // 4. attention
    k_scores<<<dim3(T / 128, T / 128, NH), 256, GSMEM_NT>>>();
    k_softmax<<<dim3(T, NH), 256>>>();
    k_ctx<<<dim3(1, T / 128, NH), 256, GSMEM_TR>>>();
    // 7. resid2
    k_gemm<<<dim3(H / 128, T / 128), 256, GSMEM_TR>>>(
        p_ch, p_cl, NH * HD, p_wdh, p_wdl, H, out_resid2, H, H / 16, p_resid);
    // 8. h2
    k_rms2<<<T, 256>>>(out_resid2, ln2_w);
    // 9-10. gate + routing
    k_gate<<<T, 128>>>(gate_w);
    k_zero_cnt<<<1, 32>>>();
    k_route<<<T / 256, 256>>>(expert_bias);
    k_offsets<<<1, 32>>>();

    // join side-stream weight conversions
    cudaStreamWaitEvent(0, g_si.evW, 0);

    // 11. shared expert su GEMM + fused SiLU
    k_su<<<dim3(2048 / 128, T / 128), 256, GSMEM_16>>>();
    // 13. mlp_out = act @ ws_down
    k_gemm16<<<dim3(H / 128, T / 128), 256, GSMEM_16>>>(
        p_ash, p_asl, FDIM, p_wsdf, H, out_mlp, H, FDIM / 16);
    // 14-16. routed experts (gu+SiLU fused, then down+scatter)
    k_moe_gu<<<dim3(2048 / 128, T / 128, NE), 256, GSMEM_16>>>();
    k_moe_y<<<dim3(H / 128, T / 128, NE), 256, GSMEM_16>>>(out_mlp);

    (void)in_sizes; (void)n_in; (void)out_size;
}

// round 11
// speedup vs baseline: 1.3532x; 1.0981x over previous
#include <cuda_runtime.h>
#include <cuda_bf16.h>
#include <cuda_fp16.h>
#include <math.h>
#include <stdint.h>

#define T 2048
#define H 1024
#define NH 8
#define NKV 2
#define HD 128
#define NE 16
#define QKV_N 1536
#define FDIM 1024
#define PAD_ROWS 10240

typedef __nv_bfloat16 bf16;
typedef __nv_bfloat162 bf162;
typedef __half f16;

// ---------------- fp32 scratch ----------------------------------------------
__device__ float g_resid[T * H];
__device__ float g_h[T * H];
__device__ float g_qkv[T * QKV_N];
__device__ float g_scores[(size_t)NH * T * T];
__device__ float g_ctxf[T * NH * HD];
__device__ float g_logits[T * NE];
__device__ int   g_cnt[NE];
__device__ int   g_poff[NE];
__device__ int   g_ptok[NE * T];
__device__ float g_pw[NE * T];

// ---------------- bf16 hi/lo operand buffers (router-critical path) ----------
__device__ bf16 g_hh[T * H],  g_hl[T * H];
__device__ bf16 g_qh[T * NH * HD], g_ql[T * NH * HD];
__device__ bf16 g_kh[T * NKV * HD], g_kl[T * NKV * HD];
__device__ bf16 g_vh[T * NKV * HD], g_vl[T * NKV * HD];
__device__ bf16 g_ph[(size_t)NH * T * T], g_pl[(size_t)NH * T * T];
__device__ bf16 g_ch[T * 1024], g_cl[T * 1024];
__device__ bf16 g_wqkvh[H * QKV_N], g_wqkvl[H * QKV_N];
__device__ bf16 g_wdh[H * H], g_wdl[H * H];

// ---------------- fp16 operands (post-routing path, 2-term) ------------------
__device__ f16 g_h2h[T * H], g_h2l[T * H];
__device__ f16 g_ash[T * FDIM], g_asl[T * FDIM];
__device__ f16 g_amh[(size_t)PAD_ROWS * 1024], g_aml[(size_t)PAD_ROWS * 1024];
__device__ f16 g_w13f[(size_t)NE * H * 2048];   // interleaved [g0,u0,g1,u1,...]
__device__ f16 g_w2f[(size_t)NE * FDIM * H];
__device__ f16 g_wsguf[H * 2048];               // interleaved
__device__ f16 g_wsdf[FDIM * H];

// ---------------- helpers ----------------------------------------------------
__device__ __forceinline__ void split_bf(float v, bf16& h, bf16& l) {
    h = __float2bfloat16(v);
    l = __float2bfloat16(v - __bfloat162float(h));
}
__device__ __forceinline__ void split2(float a, float b, bf162& h2, bf162& l2) {
    bf16 ha, la, hb, lb;
    split_bf(a, ha, la);
    split_bf(b, hb, lb);
    h2 = bf162{ha, hb};
    l2 = bf162{la, lb};
}
__device__ __forceinline__ void split_f16(float v, f16& h, f16& l) {
    h = __float2half(v);
    l = __float2half(v - __half2float(h));
}
__device__ __forceinline__ float silu_f(float g) {
    return g / (1.f + expf(-g));
}
__device__ __forceinline__ void mma16816(float* c, const uint32_t* a,
                                         const uint32_t* b) {
    asm volatile(
        "mma.sync.aligned.m16n8k16.row.col.f32.bf16.bf16.f32 "
        "{%0,%1,%2,%3}, {%4,%5,%6,%7}, {%8,%9}, {%0,%1,%2,%3};\n"
        : "+f"(c[0]), "+f"(c[1]), "+f"(c[2]), "+f"(c[3])
        : "r"(a[0]), "r"(a[1]), "r"(a[2]), "r"(a[3]), "r"(b[0]), "r"(b[1]));
}
__device__ __forceinline__ void mma16816f(float* c, const uint32_t* a,
                                          const uint32_t* b) {
    asm volatile(
        "mma.sync.aligned.m16n8k16.row.col.f32.f16.f16.f32 "
        "{%0,%1,%2,%3}, {%4,%5,%6,%7}, {%8,%9}, {%0,%1,%2,%3};\n"
        : "+f"(c[0]), "+f"(c[1]), "+f"(c[2]), "+f"(c[3])
        : "r"(a[0]), "r"(a[1]), "r"(a[2]), "r"(a[3]), "r"(b[0]), "r"(b[1]));
}
template <int N> __device__ __forceinline__ void cp_wait() {
    asm volatile("cp.async.wait_group %0;\n" ::"n"(N));
}
__device__ __forceinline__ void cp16(const void* src, void* dst) {
    uint32_t d = (uint32_t)__cvta_generic_to_shared(dst);
    asm volatile("cp.async.ca.shared.global [%0], [%1], 16;\n" ::"r"(d),
                 "l"(src));
}
__device__ __forceinline__ void ldm4(uint32_t& r0, uint32_t& r1, uint32_t& r2,
                                     uint32_t& r3, uint32_t addr) {
    asm volatile(
        "ldmatrix.sync.aligned.m8n8.x4.shared.b16 {%0,%1,%2,%3}, [%4];\n"
        : "=r"(r0), "=r"(r1), "=r"(r2), "=r"(r3)
        : "r"(addr));
}
__device__ __forceinline__ void ldm4t(uint32_t& r0, uint32_t& r1, uint32_t& r2,
                                      uint32_t& r3, uint32_t addr) {
    asm volatile(
        "ldmatrix.sync.aligned.m8n8.x4.trans.shared.b16 {%0,%1,%2,%3}, [%4];\n"
        : "=r"(r0), "=r"(r1), "=r"(r2), "=r"(r3)
        : "r"(addr));
}

// ---------------- GEMM cores: 256 threads, 8 warps, warp tile 64x32 ----------
#define SROW 40
#define BROW 264
#define BROW16 136
#define NSTAGE 4
#define TA_HALVES (128 * SROW)
#define TBN_HALVES (128 * SROW)
#define TBT_HALVES (16 * BROW)
#define TBT16_HALVES (16 * BROW16)
#define GSMEM_NT ((NSTAGE * (TA_HALVES + TBN_HALVES)) * 2)
#define GSMEM_TR ((NSTAGE * (TA_HALVES + TBT_HALVES)) * 2)
#define GSMEM_16 ((NSTAGE * (TA_HALVES + TBT16_HALVES)) * 2)

#define PIPE4_RUN(STAGE, COMPUTE, KTILES)                         \
    do {                                                          \
        STAGE(0, 0);                                              \
        if ((KTILES) > 1) STAGE(1, 1);                            \
        if ((KTILES) > 2) STAGE(2, 2);                            \
        for (int kt = 0; kt < (KTILES); kt++) {                   \
            int rem = (KTILES) - kt - 1;                          \
            if (rem >= 2) cp_wait<2>();                           \
            else if (rem == 1) cp_wait<1>();                      \
            else cp_wait<0>();                                    \
            __syncthreads();                                      \
            if (kt + 3 < (KTILES)) STAGE(kt + 3, (kt + 3) & 3);   \
            COMPUTE(kt & 3);                                      \
        }                                                         \
    } while (0)

// ---- non-trans bf16 3-term core (k_scores) ----------------------------------
template <class FA, class FB>
__device__ __forceinline__ void gemm_core_nt(
    const bf16* __restrict__ Ah, const bf16* __restrict__ Al,
    const bf16* __restrict__ Bh, const bf16* __restrict__ Bl, FA rowA, FB rowB,
    int ktiles, float (&acc)[4][4][4]) {
    extern __shared__ __align__(16) bf16 smem[];
    bf16* sA = smem;
    bf16* sB = smem + NSTAGE * TA_HALVES;
    const int tid = threadIdx.x, lane = tid & 31, warp = tid >> 5;
    const int wm = (warp >> 2) * 64, wn = (warp & 3) * 32;

#pragma unroll
    for (int a = 0; a < 4; a++)
#pragma unroll
        for (int b = 0; b < 4; b++)
#pragma unroll
            for (int r = 0; r < 4; r++) acc[a][b][r] = 0.f;

    auto stage = [&](int kt, int s) {
        bf16* dA = sA + s * TA_HALVES;
        bf16* dB = sB + s * TBN_HALVES;
#pragma unroll
        for (int i = tid; i < 512; i += 256) {
            int row = i >> 2, c = i & 3;
            int koff = kt * 16 + (c & 1) * 8;
            cp16((c < 2 ? Ah : Al) + rowA(row) + koff, dA + row * SROW + c * 8);
            cp16((c < 2 ? Bh : Bl) + rowB(row) + koff, dB + row * SROW + c * 8);
        }
        asm volatile("cp.async.commit_group;\n");
    };

    const int arow = ((lane >> 3) & 1) * 8 + (lane & 7);
    const int acol = (lane >> 4) * 8;
    const int brow = ((lane >> 4) & 1) * 8 + (lane & 7);
    const int bcol = ((lane >> 3) & 1) * 8;

    auto compute = [&](int s) {
        const bf16* A = sA + s * TA_HALVES;
        const bf16* B = sB + s * TBN_HALVES;
        uint32_t fah[4][4], fal[4][4], fbh[4][2], fbl[4][2];
#pragma unroll
        for (int mt = 0; mt < 4; mt++) {
            uint32_t ad = (uint32_t)__cvta_generic_to_shared(
                A + (wm + mt * 16 + arow) * SROW + acol);
            ldm4(fah[mt][0], fah[mt][1], fah[mt][2], fah[mt][3], ad);
            ldm4(fal[mt][0], fal[mt][1], fal[mt][2], fal[mt][3], ad + 32);
        }
#pragma unroll
        for (int p = 0; p < 2; p++) {
            uint32_t bd = (uint32_t)__cvta_generic_to_shared(
                B + (wn + p * 16 + brow) * SROW + bcol);
            ldm4(fbh[2 * p][0], fbh[2 * p][1], fbh[2 * p + 1][0],
                 fbh[2 * p + 1][1], bd);
            ldm4(fbl[2 * p][0], fbl[2 * p][1], fbl[2 * p + 1][0],
                 fbl[2 * p + 1][1], bd + 32);
        }
#pragma unroll
        for (int nt = 0; nt < 4; nt++)
#pragma unroll
            for (int mt = 0; mt < 4; mt++) mma16816(acc[mt][nt], fah[mt], fbh[nt]);
#pragma unroll
        for (int nt = 0; nt < 4; nt++)
#pragma unroll
            for (int mt = 0; mt < 4; mt++) mma16816(acc[mt][nt], fal[mt], fbh[nt]);
#pragma unroll
        for (int nt = 0; nt < 4; nt++)
#pragma unroll
            for (int mt = 0; mt < 4; mt++) mma16816(acc[mt][nt], fah[mt], fbl[nt]);
    };

    PIPE4_RUN(stage, compute, ktiles);
}

// ---- trans bf16 3-term core ----------------------------------------------------
template <class FA>
__device__ __forceinline__ void gemm_core_tr(
    const bf16* __restrict__ Ah, const bf16* __restrict__ Al, FA rowA,
    const bf16* __restrict__ Bh, const bf16* __restrict__ Bl, int ldb,
    int ktiles, float (&acc)[4][4][4]) {
    extern __shared__ __align__(16) bf16 smem[];
    bf16* sA = smem;
    bf16* sB = smem + NSTAGE * TA_HALVES;
    const int tid = threadIdx.x, lane = tid & 31, warp = tid >> 5;
    const int wm = (warp >> 2) * 64, wn = (warp & 3) * 32;

#pragma unroll
    for (int a = 0; a < 4; a++)
#pragma unroll
        for (int b = 0; b < 4; b++)
#pragma unroll
            for (int r = 0; r < 4; r++) acc[a][b][r] = 0.f;

    auto stage = [&](int kt, int s) {
        bf16* dA = sA + s * TA_HALVES;
        bf16* dB = sB + s * TBT_HALVES;
#pragma unroll
        for (int i = tid; i < 512; i += 256) {
            int row = i >> 2, c = i & 3;
            int koff = kt * 16 + (c & 1) * 8;
            cp16((c < 2 ? Ah : Al) + rowA(row) + koff, dA + row * SROW + c * 8);
            int brw = i >> 5, sub = i & 31;
            int half = sub >> 4, nseg = sub & 15;
            const bf16* bsrc =
                (half ? Bl : Bh) + (size_t)(kt * 16 + brw) * ldb + nseg * 8;
            cp16(bsrc, dB + brw * BROW + half * 128 + nseg * 8);
        }
        asm volatile("cp.async.commit_group;\n");
    };

    const int arow = ((lane >> 3) & 1) * 8 + (lane & 7);
    const int acol = (lane >> 4) * 8;
    const int tkrow = (lane & 7) + ((lane >> 3) & 1) * 8;
    const int tnoff = (lane >> 4) * 8;

    auto compute = [&](int s) {
        const bf16* A = sA + s * TA_HALVES;
        const bf16* B = sB + s * TBT_HALVES;
        uint32_t fah[4][4], fal[4][4], fbh[4][2], fbl[4][2];
#pragma unroll
        for (int mt = 0; mt < 4; mt++) {
            uint32_t ad = (uint32_t)__cvta_generic_to_shared(
                A + (wm + mt * 16 + arow) * SROW + acol);
            ldm4(fah[mt][0], fah[mt][1], fah[mt][2], fah[mt][3], ad);
            ldm4(fal[mt][0], fal[mt][1], fal[mt][2], fal[mt][3], ad + 32);
        }
#pragma unroll
        for (int p = 0; p < 2; p++) {
            uint32_t bd = (uint32_t)__cvta_generic_to_shared(
                B + tkrow * BROW + wn + p * 16 + tnoff);
            ldm4t(fbh[2 * p][0], fbh[2 * p][1], fbh[2 * p + 1][0],
                  fbh[2 * p + 1][1], bd);
            ldm4t(fbl[2 * p][0], fbl[2 * p][1], fbl[2 * p + 1][0],
                  fbl[2 * p + 1][1], bd + 256);
        }
#pragma unroll
        for (int nt = 0; nt < 4; nt++)
#pragma unroll
            for (int mt = 0; mt < 4; mt++) mma16816(acc[mt][nt], fah[mt], fbh[nt]);
#pragma unroll
        for (int nt = 0; nt < 4; nt++)
#pragma unroll
            for (int mt = 0; mt < 4; mt++) mma16816(acc[mt][nt], fal[mt], fbh[nt]);
#pragma unroll
        for (int nt = 0; nt < 4; nt++)
#pragma unroll
            for (int mt = 0; mt < 4; mt++) mma16816(acc[mt][nt], fah[mt], fbl[nt]);
    };

    PIPE4_RUN(stage, compute, ktiles);
}

// ---- trans fp16 2-term core ------------------------------------------------------
template <class FA>
__device__ __forceinline__ void gemm_core_16(
    const f16* __restrict__ Ah, const f16* __restrict__ Al, FA rowA,
    const f16* __restrict__ Bf, int ldb, int ktiles, float (&acc)[4][4][4]) {
    extern __shared__ __align__(16) bf16 smem[];
    f16* sA = reinterpret_cast<f16*>(smem);
    f16* sB = sA + NSTAGE * TA_HALVES;
    const int tid = threadIdx.x, lane = tid & 31, warp = tid >> 5;
    const int wm = (warp >> 2) * 64, wn = (warp & 3) * 32;

#pragma unroll
    for (int a = 0; a < 4; a++)
#pragma unroll
        for (int b = 0; b < 4; b++)
#pragma unroll
            for (int r = 0; r < 4; r++) acc[a][b][r] = 0.f;

    auto stage = [&](int kt, int s) {
        f16* dA = sA + s * TA_HALVES;
        f16* dB = sB + s * TBT16_HALVES;
#pragma unroll
        for (int i = tid; i < 512; i += 256) {
            int row = i >> 2, c = i & 3;
            int koff = kt * 16 + (c & 1) * 8;
            cp16((c < 2 ? Ah : Al) + rowA(row) + koff, dA + row * SROW + c * 8);
        }
        {
            int i = tid;
            int brw = i >> 4, nseg = i & 15;
            const f16* bsrc = Bf + (size_t)(kt * 16 + brw) * ldb + nseg * 8;
            cp16(bsrc, dB + brw * BROW16 + nseg * 8);
        }
        asm volatile("cp.async.commit_group;\n");
    };

    const int arow = ((lane >> 3) & 1) * 8 + (lane & 7);
    const int acol = (lane >> 4) * 8;
    const int tkrow = (lane & 7) + ((lane >> 3) & 1) * 8;
    const int tnoff = (lane >> 4) * 8;

    auto compute = [&](int s) {
        const f16* A = sA + s * TA_HALVES;
        const f16* B = sB + s * TBT16_HALVES;
        uint32_t fah[4][4], fal[4][4], fb[4][2];
#pragma unroll
        for (int mt = 0; mt < 4; mt++) {
            uint32_t ad = (uint32_t)__cvta_generic_to_shared(
                A + (wm + mt * 16 + arow) * SROW + acol);
            ldm4(fah[mt][0], fah[mt][1], fah[mt][2], fah[mt][3], ad);
            ldm4(fal[mt][0], fal[mt][1], fal[mt][2], fal[mt][3], ad + 32);
        }
#pragma unroll
        for (int p = 0; p < 2; p++) {
            uint32_t bd = (uint32_t)__cvta_generic_to_shared(
                B + tkrow * BROW16 + wn + p * 16 + tnoff);
            ldm4t(fb[2 * p][0], fb[2 * p][1], fb[2 * p + 1][0],
                  fb[2 * p + 1][1], bd);
        }
#pragma unroll
        for (int nt = 0; nt < 4; nt++)
#pragma unroll
            for (int mt = 0; mt < 4; mt++) mma16816f(acc[mt][nt], fah[mt], fb[nt]);
#pragma unroll
        for (int nt = 0; nt < 4; nt++)
#pragma unroll
            for (int mt = 0; mt < 4; mt++) mma16816f(acc[mt][nt], fal[mt], fb[nt]);
    };

    PIPE4_RUN(stage, compute, ktiles);
}

// epilogue iterator (8 warps, 64x32)
template <class F>
__device__ __forceinline__ void epi128(float (&acc)[4][4][4], F f) {
    const int lane = threadIdx.x & 31, warp = threadIdx.x >> 5;
    const int wm = (warp >> 2) * 64, wn = (warp & 3) * 32;
    const int gid = lane >> 2, tc = lane & 3;
#pragma unroll
    for (int mt = 0; mt < 4; mt++)
#pragma unroll
        for (int nt = 0; nt < 4; nt++)
#pragma unroll
            for (int r = 0; r < 4; r++) {
                int row = wm + mt * 16 + gid + ((r >> 1) << 3);
                int col = wn + nt * 8 + tc * 2 + (r & 1);
                f(row, col, acc[mt][nt][r]);
            }
}

// fused SiLU epilogue: interleaved [g,u] columns; f(row, act_col, act)
template <class F>
__device__ __forceinline__ void epi128_silu(float (&acc)[4][4][4], F f) {
    const int lane = threadIdx.x & 31, warp = threadIdx.x >> 5;
    const int wm = (warp >> 2) * 64, wn = (warp & 3) * 32;
    const int gid = lane >> 2, tc = lane & 3;
#pragma unroll
    for (int mt = 0; mt < 4; mt++)
#pragma unroll
        for (int nt = 0; nt < 4; nt++) {
            int acol = (wn >> 1) + nt * 4 + tc;
#pragma unroll
            for (int rr = 0; rr < 2; rr++) {
                int row = wm + mt * 16 + gid + rr * 8;
                float g = acc[mt][nt][rr * 2];
                float u = acc[mt][nt][rr * 2 + 1];
                f(row, acol, silu_f(g) * u);
            }
        }
}

// ---------------- streaming splits / zero --------------------------------------
__global__ void k_zero_buf(float* __restrict__ p, int n4) {
    int i = blockIdx.x * 256 + threadIdx.x;
    if (i < n4) reinterpret_cast<float4*>(p)[i] = float4{0.f, 0.f, 0.f, 0.f};
}

__global__ void k_split(const float* __restrict__ src, bf16* __restrict__ dh,
                        bf16* __restrict__ dl, int n8) {
    int i = blockIdx.x * 256 + threadIdx.x;
    if (i >= n8) return;
    const float4* s4 = reinterpret_cast<const float4*>(src) + i * 2;
    float4 a = s4[0], b = s4[1];
    bf16 hbuf[8], lbuf[8];
    split_bf(a.x, hbuf[0], lbuf[0]);
    split_bf(a.y, hbuf[1], lbuf[1]);
    split_bf(a.z, hbuf[2], lbuf[2]);
    split_bf(a.w, hbuf[3], lbuf[3]);
    split_bf(b.x, hbuf[4], lbuf[4]);
    split_bf(b.y, hbuf[5], lbuf[5]);
    split_bf(b.z, hbuf[6], lbuf[6]);
    split_bf(b.w, hbuf[7], lbuf[7]);
    reinterpret_cast<uint4*>(dh)[i] = *reinterpret_cast<uint4*>(hbuf);
    reinterpret_cast<uint4*>(dl)[i] = *reinterpret_cast<uint4*>(lbuf);
}

__global__ void k_split16(const float* __restrict__ src, f16* __restrict__ d,
                          int n8) {
    int i = blockIdx.x * 256 + threadIdx.x;
    if (i >= n8) return;
    const float4* s4 = reinterpret_cast<const float4*>(src) + i * 2;
    float4 a = s4[0], b = s4[1];
    f16 buf[8];
    buf[0] = __float2half(a.x);
    buf[1] = __float2half(a.y);
    buf[2] = __float2half(a.z);
    buf[3] = __float2half(a.w);
    buf[4] = __float2half(b.x);
    buf[5] = __float2half(b.y);
    buf[6] = __float2half(b.z);
    buf[7] = __float2half(b.w);
    reinterpret_cast<uint4*>(d)[i] = *reinterpret_cast<uint4*>(buf);
}

// interleaving fp16 convert for gate/up weights
__global__ void k_split16i(const float* __restrict__ src, f16* __restrict__ dst) {
    const int K = H;
    src += (size_t)blockIdx.z * K * 2048;
    dst += (size_t)blockIdx.z * K * 2048;
    int i = blockIdx.x * 256 + threadIdx.x;
    int k = i >> 8, j = i & 255;
    float4 g4 = *reinterpret_cast<const float4*>(src + (size_t)k * 2048 + 4 * j);
    float4 u4 = *reinterpret_cast<const float4*>(src + (size_t)k * 2048 + 1024 + 4 * j);
    f16 buf[8];
    buf[0] = __float2half(g4.x); buf[1] = __float2half(u4.x);
    buf[2] = __float2half(g4.y); buf[3] = __float2half(u4.y);
    buf[4] = __float2half(g4.z); buf[5] = __float2half(u4.z);
    buf[6] = __float2half(g4.w); buf[7] = __float2half(u4.w);
    *reinterpret_cast<uint4*>(dst + (size_t)k * 2048 + 8 * j) =
        *reinterpret_cast<uint4*>(buf);
}

// ---------------- qkv GEMM with fused V split --------------------------------
__global__ __launch_bounds__(256) void k_qkv() {
    const int rb = blockIdx.y * 128, cb = blockIdx.x * 128;
    float acc[4][4][4];
    gemm_core_tr(
        g_hh, g_hl, [&](int m) { return (size_t)(rb + m) * H; }, g_wqkvh + cb,
        g_wqkvl + cb, QKV_N, H / 16, acc);
    epi128(acc, [&](int r, int c, float v) {
        g_qkv[(size_t)(rb + r) * QKV_N + cb + c] = v;
        int vc = cb + c - (NH + NKV) * HD;
        if (vc >= 0) {
            size_t o = (size_t)(rb + r) * (NKV * HD) + vc;
            split_bf(v, g_vh[o], g_vl[o]);
        }
    });
}

// ---------------- generic bf16 GEMM (trans-B) ----------------------------------
__global__ __launch_bounds__(256) void k_gemm(
    const bf16* __restrict__ Ah, const bf16* __restrict__ Al, int sa,
    const bf16* __restrict__ Bh, const bf16* __restrict__ Bl, int ldb,
    float* __restrict__ C, int ldc, int ktiles, const float* __restrict__ addm) {
    const int rb = blockIdx.y * 128, cb = blockIdx.x * 128;
    float acc[4][4][4];
    gemm_core_tr(
        Ah, Al, [&](int m) { return (size_t)(rb + m) * sa; }, Bh + cb, Bl + cb,
        ldb, ktiles, acc);
    epi128(acc, [&](int r, int c, float v) {
        size_t idx = (size_t)(rb + r) * ldc + cb + c;
        if (addm) v += addm[idx];
        C[idx] = v;
    });
}

// ---------------- shared-expert su GEMM + fused SiLU ----------------------------
__global__ __launch_bounds__(256) void k_su() {
    const int rb = blockIdx.y * 128, cb = blockIdx.x * 128;
    float acc[4][4][4];
    gemm_core_16(
        g_h2h, g_h2l, [&](int m) { return (size_t)(rb + m) * H; },
        g_wsguf + cb, 2048, H / 16, acc);
    const int ab = cb >> 1;
    epi128_silu(acc, [&](int r, int ac, float a) {
        size_t o = (size_t)(rb + r) * FDIM + ab + ac;
        split_f16(a, g_ash[o], g_asl[o]);
    });
}

// ---------------- shared-expert down proj, atomic into out ----------------------
__global__ __launch_bounds__(256) void k_sdown(float* __restrict__ outp) {
    const int rb = blockIdx.y * 128, cb = blockIdx.x * 128;
    float acc[4][4][4];
    gemm_core_16(
        g_ash, g_asl, [&](int m) { return (size_t)(rb + m) * FDIM; },
        g_wsdf + cb, H, FDIM / 16, acc);
    epi128(acc, [&](int r, int c, float v) {
        atomicAdd(&outp[(size_t)(rb + r) * H + cb + c], v);
    });
}

// ---------------- add + rmsnorm (ln1) ---------------------------------------------
__global__ void k_add_rms1(const float* __restrict__ hs,
                           const float* __restrict__ res,
                           const float* __restrict__ w) {
    const int t = blockIdx.x, tid = threadIdx.x;
    float2 x[2];
    float ss = 0.f;
#pragma unroll
    for (int i = 0; i < 2; i++) {
        int c = (tid + i * 256) * 2;
        float2 a = *reinterpret_cast<const float2*>(hs + (size_t)t * H + c);
        float2 b = *reinterpret_cast<const float2*>(res + (size_t)t * H + c);
        float2 v = {a.x + b.x, a.y + b.y};
        *reinterpret_cast<float2*>(g_resid + (size_t)t * H + c) = v;
        x[i] = v;
        ss += v.x * v.x + v.y * v.y;
    }
    __shared__ float red[256];
    red[tid] = ss;
    __syncthreads();
    for (int s = 128; s > 0; s >>= 1) {
        if (tid < s) red[tid] += red[tid + s];
        __syncthreads();
    }
    float r = rsqrtf(red[0] / (float)H + 1e-6f);
#pragma unroll
    for (int i = 0; i < 2; i++) {
        int c = (tid + i * 256) * 2;
        bf162 h2, l2;
        split2(x[i].x * r * w[c], x[i].y * r * w[c + 1], h2, l2);
        *reinterpret_cast<bf162*>(g_hh + (size_t)t * H + c) = h2;
        *reinterpret_cast<bf162*>(g_hl + (size_t)t * H + c) = l2;
    }
}

// ---------------- rmsnorm (ln2) -----------------------------------------------------
__global__ void k_rms2(const float* __restrict__ resid2,
                       const float* __restrict__ w) {
    const int t = blockIdx.x, tid = threadIdx.x;
    float2 x[2];
    float ss = 0.f;
#pragma unroll
    for (int i = 0; i < 2; i++) {
        int c = (tid + i * 256) * 2;
        float2 v = *reinterpret_cast<const float2*>(resid2 + (size_t)t * H + c);
        x[i] = v;
        ss += v.x * v.x + v.y * v.y;
    }
    __shared__ float red[256];
    red[tid] = ss;
    __syncthreads();
    for (int s = 128; s > 0; s >>= 1) {
        if (tid < s) red[tid] += red[tid + s];
        __syncthreads();
    }
    float r = rsqrtf(red[0] / (float)H + 1e-6f);
#pragma unroll
    for (int i = 0; i < 2; i++) {
        int c = (tid + i * 256) * 2;
        float v0 = x[i].x * r * w[c], v1 = x[i].y * r * w[c + 1];
        *reinterpret_cast<float2*>(g_h + (size_t)t * H + c) = float2{v0, v1};
        f16 h0, l0, h1, l1;
        split_f16(v0, h0, l0);
        split_f16(v1, h1, l1);
        *reinterpret_cast<__half2*>(g_h2h + (size_t)t * H + c) =
            __halves2half2(h0, h1);
        *reinterpret_cast<__half2*>(g_h2l + (size_t)t * H + c) =
            __halves2half2(l0, l1);
    }
}

// ---------------- per-head rmsnorm + rope -------------------------------------------
__global__ void k_qknorm_rope(const int* __restrict__ pos_ids,
                              const float* __restrict__ qnw,
                              const float* __restrict__ knw) {
    const int t = blockIdx.x, hh = blockIdx.y, d = threadIdx.x;
    const float* src;
    const float* w;
    bf16 *dh, *dl;
    if (hh < NH) {
        src = g_qkv + (size_t)t * QKV_N + hh * HD;
        w = qnw;
        dh = g_qh + ((size_t)t * NH + hh) * HD;
        dl = g_ql + ((size_t)t * NH + hh) * HD;
    } else {
        int kk = hh - NH;
        src = g_qkv + (size_t)t * QKV_N + NH * HD + kk * HD;
        w = knw;
        dh = g_kh + ((size_t)t * NKV + kk) * HD;
        dl = g_kl + ((size_t)t * NKV + kk) * HD;
    }
    float x = src[d];
    float ss = x * x;
#pragma unroll
    for (int o = 16; o > 0; o >>= 1) ss += __shfl_xor_sync(0xffffffffu, ss, o);
    __shared__ float wsum[4];
    if ((d & 31) == 0) wsum[d >> 5] = ss;
    __syncthreads();
    ss = wsum[0] + wsum[1] + wsum[2] + wsum[3];
    float xn = x * rsqrtf(ss / (float)HD + 1e-6f) * w[d];
    __shared__ float xb[HD];
    xb[d] = xn;
    __syncthreads();
    int p = pos_ids[t];
    if (d < 64) {
        float inv = powf(10000.f, -(float)d / 64.f);
        float ang = (float)p * inv;
        float c = cosf(ang), s = sinf(ang);
        float x1 = xb[d], x2 = xb[d + 64];
        split_bf(x1 * c - x2 * s, dh[d], dl[d]);
        split_bf(x2 * c + x1 * s, dh[d + 64], dl[d + 64]);
    }
}

// ---------------- attention scores ----------------------------------------------------
__global__ __launch_bounds__(256) void k_scores() {
    const int jt = blockIdx.x, it = blockIdx.y, h = blockIdx.z;
    if (jt > it) return;
    float acc[4][4][4];
    gemm_core_nt(
        g_qh, g_ql, g_kh, g_kl,
        [&](int m) { return ((size_t)(it * 128 + m) * NH + h) * HD; },
        [&](int n) { return ((size_t)(jt * 128 + n) * NKV + (h >> 2)) * HD; },
        HD / 16, acc);
    const float scale = 0.08838834764831845f;
    float* S = g_scores + (size_t)h * T * T;
    epi128(acc, [&](int r, int c, float v) {
        int i = it * 128 + r;
        int j = jt * 128 + c;
        S[(size_t)i * T + j] = (j <= i) ? v * scale : -3.0e38f;
    });
}

// ---------------- row softmax -> bf16 P -------------------------------------------------
__global__ void k_softmax() {
    const int i = blockIdx.x, h = blockIdx.y, tid = threadIdx.x;
    const float4* S4 =
        reinterpret_cast<const float4*>(g_scores + ((size_t)h * T + i) * T);
    bf162* Ph = reinterpret_cast<bf162*>(g_ph + ((size_t)h * T + i) * T);
    bf162* Pl = reinterpret_cast<bf162*>(g_pl + ((size_t)h * T + i) * T);
    const int n4 = (((i >> 7) + 1) << 7) >> 2;
    __shared__ float4 buf[T / 4];
    __shared__ float red[256];
    float mx = -3.4e38f;
    for (int j = tid; j < n4; j += 256) {
        float4 v = S4[j];
        buf[j] = v;
        mx = fmaxf(fmaxf(mx, fmaxf(v.x, v.y)), fmaxf(v.z, v.w));
    }
    red[tid] = mx;
    __syncthreads();
    for (int s = 128; s > 0; s >>= 1) {
        if (tid < s) red[tid] = fmaxf(red[tid], red[tid + s]);
        __syncthreads();
    }
    mx = red[0];
    __syncthreads();
    float sm = 0.f;
    for (int j = tid; j < n4; j += 256) {
        float4 v = buf[j];
        v.x = expf(v.x - mx);
        v.y = expf(v.y - mx);
        v.z = expf(v.z - mx);
        v.w = expf(v.w - mx);
        buf[j] = v;
        sm += v.x + v.y + v.z + v.w;
    }
    red[tid] = sm;
    __syncthreads();
    for (int s = 128; s > 0; s >>= 1) {
        if (tid < s) red[tid] += red[tid + s];
        __syncthreads();
    }
    float inv = 1.f / red[0];
    for (int j = tid; j < n4; j += 256) {
        float4 v = buf[j];
        bf162 h0, l0, h1, l1;
        split2(v.x * inv, v.y * inv, h0, l0);
        split2(v.z * inv, v.w * inv, h1, l1);
        Ph[j * 2] = h0;
        Ph[j * 2 + 1] = h1;
        Pl[j * 2] = l0;
        Pl[j * 2 + 1] = l1;
    }
}

// ---------------- ctx = P @ V, balanced chunked split-K -------------------------------
__global__ __launch_bounds__(256) void k_ctx_chunk() {
    const int ck = blockIdx.x, it = blockIdx.y, h = blockIdx.z;
    if (ck > it) return;
    float acc[4][4][4];
    const int cb = (h >> 2) * 128;
    const size_t koff = (size_t)ck * 128;  // key-token offset
    gemm_core_tr(
        g_ph, g_pl,
        [&](int m) { return ((size_t)h * T + it * 128 + m) * T + koff; },
        g_vh + koff * (NKV * HD) + cb, g_vl + koff * (NKV * HD) + cb, NKV * HD,
        8, acc);
    epi128(acc, [&](int r, int c, float v) {
        atomicAdd(&g_ctxf[(size_t)(it * 128 + r) * (NH * HD) + h * HD + c], v);
    });
}

// fp32 ctx -> bf16 hi/lo
__global__ void k_ctx_split() {
    int i = blockIdx.x * 256 + threadIdx.x;
    if (i >= T * 1024 / 8) return;
    const float4* s4 = reinterpret_cast<const float4*>(g_ctxf) + i * 2;
    float4 a = s4[0], b = s4[1];
    bf16 hbuf[8], lbuf[8];
    split_bf(a.x, hbuf[0], lbuf[0]);
    split_bf(a.y, hbuf[1], lbuf[1]);
    split_bf(a.z, hbuf[2], lbuf[2]);
    split_bf(a.w, hbuf[3], lbuf[3]);
    split_bf(b.x, hbuf[4], lbuf[4]);
    split_bf(b.y, hbuf[5], lbuf[5]);
    split_bf(b.z, hbuf[6], lbuf[6]);
    split_bf(b.w, hbuf[7], lbuf[7]);
    reinterpret_cast<uint4*>(g_ch)[i] = *reinterpret_cast<uint4*>(hbuf);
    reinterpret_cast<uint4*>(g_cl)[i] = *reinterpret_cast<uint4*>(lbuf);
}

// ---------------- gate logits -------------------------------------------------------------
__global__ void k_gate(const float* __restrict__ gw) {
    const int t = blockIdx.x, tid = threadIdx.x;
    const int e = tid & 15, seg = tid >> 4;
    const float* hr = g_h + (size_t)t * H;
    float s = 0.f;
    for (int k = seg * 128; k < seg * 128 + 128; k++) s += hr[k] * gw[k * NE + e];
    __shared__ float red[128];
    red[tid] = s;
    __syncthreads();
    if (tid < NE) {
        float v = 0.f;
        for (int g = 0; g < 8; g++) v += red[g * 16 + tid];
        g_logits[t * NE + tid] = v;
    }
}

// ---------------- routing -------------------------------------------------------------------
__global__ void k_zero_cnt() {
    if (threadIdx.x < NE) g_cnt[threadIdx.x] = 0;
}

__global__ void k_route(const float* __restrict__ bias) {
    const int t = blockIdx.x * 256 + threadIdx.x;
    if (t >= T) return;
    float sig[NE], sfc[NE];
#pragma unroll
    for (int e = 0; e < NE; e++) {
        float l = g_logits[t * NE + e];
        sig[e] = 1.f / (1.f + expf(-l));
        sfc[e] = sig[e] + bias[e];
    }
    float gs[4];
#pragma unroll
    for (int g = 0; g < 4; g++) {
        float m1 = -3.4e38f, m2 = -3.4e38f;
#pragma unroll
        for (int i = 0; i < 4; i++) {
            float v = sfc[g * 4 + i];
            if (v > m1) { m2 = m1; m1 = v; }
            else if (v > m2) m2 = v;
        }
        gs[g] = m1 + m2;
    }
    int g1 = 0;
    for (int g = 1; g < 4; g++) if (gs[g] > gs[g1]) g1 = g;
    int g2 = -1;
    for (int g = 0; g < 4; g++) {
        if (g == g1) continue;
        if (g2 < 0 || gs[g] > gs[g2]) g2 = g;
    }
    bool allowed[NE];
#pragma unroll
    for (int e = 0; e < NE; e++) {
        int g = e >> 2;
        allowed[e] = (g == g1) || (g == g2);
    }
    int sel[4];
    bool picked[NE];
#pragma unroll
    for (int e = 0; e < NE; e++) picked[e] = false;
    float wsum = 0.f;
#pragma unroll
    for (int it = 0; it < 4; it++) {
        int bi = -1;
        float bv = -3.4e38f;
        for (int e = 0; e < NE; e++) {
            if (!allowed[e] || picked[e]) continue;
            if (sfc[e] > bv) { bv = sfc[e]; bi = e; }
        }
        picked[bi] = true;
        sel[it] = bi;
        wsum += sig[bi];
    }
    float inv = 1.f / (wsum + 1e-20f);
#pragma unroll
    for (int it = 0; it < 4; it++) {
        int e = sel[it];
        int pos = atomicAdd(&g_cnt[e], 1);
        g_ptok[e * T + pos] = t;
        g_pw[e * T + pos] = sig[e] * inv;
    }
}

__global__ void k_offsets() {
    if (threadIdx.x == 0) {
        int run = 0;
        for (int e = 0; e < NE; e++) {
            g_poff[e] = run;
            run += ((g_cnt[e] + 127) / 128) * 128;
        }
    }
}

// ---------------- MoE gu GEMM + fused SiLU -> fp16 act ------------------------------
__global__ __launch_bounds__(256) void k_moe_gu() {
    const int e = blockIdx.z, rt = blockIdx.y, bn = blockIdx.x;
    const int cnt = g_cnt[e];
    if (rt * 128 >= cnt) return;
    const int off = g_poff[e];
    const int* ptok = g_ptok + e * T;
    const int cb = bn * 128;
    float acc[4][4][4];
    gemm_core_16(
        g_h2h, g_h2l,
        [&](int m) {
            int lr = rt * 128 + m;
            int tok = ptok[lr < cnt ? lr : cnt - 1];
            return (size_t)tok * H;
        },
        g_w13f + (size_t)e * H * 2048 + cb, 2048, H / 16, acc);
    const int ab = bn * 64;
    epi128_silu(acc, [&](int r, int ac, float a) {
        size_t row = (size_t)off + rt * 128 + r;
        size_t o = row * FDIM + ab + ac;
        split_f16(a, g_amh[o], g_aml[o]);
    });
}

// ---------------- MoE y, scatter-add (fp16 2-term) -----------------------------------
__global__ __launch_bounds__(256) void k_moe_y(float* __restrict__ outp) {
    const int e = blockIdx.z, rt = blockIdx.y, bn = blockIdx.x;
    const int cnt = g_cnt[e];
    if (rt * 128 >= cnt) return;
    const int off = g_poff[e];
    const int cb = bn * 128;
    float acc[4][4][4];
    gemm_core_16(
        g_amh, g_aml,
        [&](int m) { return ((size_t)off + rt * 128 + m) * FDIM; },
        g_w2f + (size_t)e * FDIM * H + cb, H, FDIM / 16, acc);
    epi128(acc, [&](int r, int c, float v) {
        int lr = rt * 128 + r;
        if (lr >= cnt) return;
        int tok = g_ptok[e * T + lr];
        float w = 2.0f * g_pw[e * T + lr];
        atomicAdd(&outp[(size_t)tok * H + cb + c], w * v);
    });
}

// ---------------- stream/event setup at static init (pre-checkpoint) ------------
struct StreamInit {
    cudaStream_t s2;
    cudaEvent_t evF, evW, evR, evS;
    StreamInit() {
        cudaStreamCreateWithFlags(&s2, cudaStreamNonBlocking);
        cudaEventCreateWithFlags(&evF, cudaEventDisableTiming);
        cudaEventCreateWithFlags(&evW, cudaEventDisableTiming);
        cudaEventCreateWithFlags(&evR, cudaEventDisableTiming);
        cudaEventCreateWithFlags(&evS, cudaEventDisableTiming);
    }
};
static StreamInit g_si;

// ---------------- launch -----------------------------------------------------------------
extern "C" void kernel_launch(void* const* d_in, const int* in_sizes, int n_in,
                              void* d_out, int out_size) {
    const float* hs = (const float*)d_in[0];
    const float* res = (const float*)d_in[1];
    const int* pos = (const int*)d_in[2];
    const float* ln1_w = (const float*)d_in[3];
    const float* qkv_w = (const float*)d_in[4];
    const float* qnorm_w = (const float*)d_in[5];
    const float* knorm_w = (const float*)d_in[6];
    const float* dense_w = (const float*)d_in[7];
    const float* ln2_w = (const float*)d_in[8];
    const float* gate_w = (const float*)d_in[9];
    const float* expert_bias = (const float*)d_in[10];
    const float* w13 = (const float*)d_in[11];
    const float* w2 = (const float*)d_in[12];
    const float* ws_gate_up = (const float*)d_in[13];
    const float* ws_down = (const float*)d_in[14];

    float* out_mlp = (float*)d_out;
    float* out_resid2 = (float*)d_out + (size_t)T * H;

    float* p_resid;  cudaGetSymbolAddress((void**)&p_resid, g_resid);
    float* p_ctxf;   cudaGetSymbolAddress((void**)&p_ctxf, g_ctxf);
    bf16 *p_wqkvh, *p_wqkvl, *p_wdh, *p_wdl, *p_ch, *p_cl;
    f16 *p_w13f, *p_w2f, *p_wsguf, *p_wsdf;
    cudaGetSymbolAddress((void**)&p_wqkvh, g_wqkvh);
    cudaGetSymbolAddress((void**)&p_wqkvl, g_wqkvl);
    cudaGetSymbolAddress((void**)&p_wdh, g_wdh);
    cudaGetSymbolAddress((void**)&p_wdl, g_wdl);
    cudaGetSymbolAddress((void**)&p_ch, g_ch);
    cudaGetSymbolAddress((void**)&p_cl, g_cl);
    cudaGetSymbolAddress((void**)&p_w13f, g_w13f);
    cudaGetSymbolAddress((void**)&p_w2f, g_w2f);
    cudaGetSymbolAddress((void**)&p_wsguf, g_wsguf);
    cudaGetSymbolAddress((void**)&p_wsdf, g_wsdf);

    static bool attrs_set = false;
    if (!attrs_set) {
        cudaFuncSetAttribute(k_qkv, cudaFuncAttributeMaxDynamicSharedMemorySize, GSMEM_TR);
        cudaFuncSetAttribute(k_gemm, cudaFuncAttributeMaxDynamicSharedMemorySize, GSMEM_TR);
        cudaFuncSetAttribute(k_scores, cudaFuncAttributeMaxDynamicSharedMemorySize, GSMEM_NT);
        cudaFuncSetAttribute(k_ctx_chunk, cudaFuncAttributeMaxDynamicSharedMemorySize, GSMEM_TR);
        cudaFuncSetAttribute(k_su, cudaFuncAttributeMaxDynamicSharedMemorySize, GSMEM_16);
        cudaFuncSetAttribute(k_sdown, cudaFuncAttributeMaxDynamicSharedMemorySize, GSMEM_16);
        cudaFuncSetAttribute(k_moe_gu, cudaFuncAttributeMaxDynamicSharedMemorySize, GSMEM_16);
        cudaFuncSetAttribute(k_moe_y, cudaFuncAttributeMaxDynamicSharedMemorySize, GSMEM_16);
        attrs_set = true;
    }

    // fork: MoE/shared weight conversions on side stream
    cudaEventRecord(g_si.evF, 0);
    cudaStreamWaitEvent(g_si.s2, g_si.evF, 0);
    k_split16i<<<dim3(H * 2048 / 8 / 256, 1, NE), 256, 0, g_si.s2>>>(w13, p_w13f);
    k_split16<<<((int)((size_t)NE * FDIM * H / 8) + 255) / 256, 256, 0, g_si.s2>>>(
        w2, p_w2f, (int)((size_t)NE * FDIM * H / 8));
    k_split16i<<<dim3(H * 2048 / 8 / 256, 1, 1), 256, 0, g_si.s2>>>(ws_gate_up, p_wsguf);
    k_split16<<<(FDIM * H / 8 + 255) / 256, 256, 0, g_si.s2>>>(ws_down, p_wsdf,
                                                               FDIM * H / 8);
    cudaEventRecord(g_si.evW, g_si.s2);

    // main: zero accumulation buffers + early weight conversions
    k_zero_buf<<<(T * H / 4 + 255) / 256, 256>>>(out_mlp, T * H / 4);
    k_zero_buf<<<(T * H / 4 + 255) / 256, 256>>>(p_ctxf, T * H / 4);
    k_split<<<(H * QKV_N / 8 + 255) / 256, 256>>>(qkv_w, p_wqkvh, p_wqkvl, H * QKV_N / 8);
    k_split<<<(H * H / 8 + 255) / 256, 256>>>(dense_w, p_wdh, p_wdl, H * H / 8);

    // 1. resid + ln1
    k_add_rms1<<<T, 256>>>(hs, res, ln1_w);
    // 2. qkv GEMM with fused V split
    k_qkv<<<dim3(QKV_N / 128, T / 128), 256, GSMEM_TR>>>();
    // 3. q/k norm + rope
    k_qknorm_rope<<<dim3(T, NH + NKV), 128>>>(pos, qnorm_w, knorm_w);
    // 4. attention
    k_scores<<<dim3(T / 128, T / 128, NH), 256, GSMEM_NT>>>();
    k_softmax<<<dim3(T, NH), 256>>>();
    k_ctx_chunk<<<dim3(T / 128, T / 128, NH), 256, GSMEM_TR>>>();
    k_ctx_split<<<(T * 1024 / 8 + 255) / 256, 256>>>();
    // 7. resid2 = ctx @ dense_w + resid
    k_gemm<<<dim3(H / 128, T / 128), 256, GSMEM_TR>>>(
        p_ch, p_cl, NH * HD, p_wdh, p_wdl, H, out_resid2, H, H / 16, p_resid);
    // 8. h2
    k_rms2<<<T, 256>>>(out_resid2, ln2_w);
    cudaEventRecord(g_si.evR, 0);

    // side stream: shared expert chain (needs h2 + wsgu/wsd; atomics into out_mlp)
    cudaStreamWaitEvent(g_si.s2, g_si.evR, 0);
    k_su<<<dim3(2048 / 128, T / 128), 256, GSMEM_16, g_si.s2>>>();
    k_sdown<<<dim3(H / 128, T / 128), 256, GSMEM_16, g_si.s2>>>(out_mlp);
    cudaEventRecord(g_si.evS, g_si.s2);

    // main: routing
    k_gate<<<T, 128>>>(gate_w);
    k_zero_cnt<<<1, 32>>>();
    k_route<<<T / 256, 256>>>(expert_bias);
    k_offsets<<<1, 32>>>();

    // join weight conversions, then routed experts
    cudaStreamWaitEvent(0, g_si.evW, 0);
    k_moe_gu<<<dim3(2048 / 128, T / 128, NE), 256, GSMEM_16>>>();
    k_moe_y<<<dim3(H / 128, T / 128, NE), 256, GSMEM_16>>>(out_mlp);

    // join shared-expert chain
    cudaStreamWaitEvent(0, g_si.evS, 0);

    (void)in_sizes; (void)n_in; (void)out_size;
}

// round 12
// speedup vs baseline: 1.4139x; 1.0448x over previous
#include <cuda_runtime.h>
#include <cuda_bf16.h>
#include <cuda_fp16.h>
#include <math.h>
#include <stdint.h>

#define T 2048
#define H 1024
#define NH 8
#define NKV 2
#define HD 128
#define NE 16
#define QKV_N 1536
#define FDIM 1024
#define PAD_ROWS 10240

typedef __nv_bfloat16 bf16;
typedef __nv_bfloat162 bf162;
typedef __half f16;

// ---------------- fp32 scratch ----------------------------------------------
__device__ float g_resid[T * H];
__device__ float g_h[T * H];
__device__ float g_qkv[T * QKV_N];
__device__ float g_scores[(size_t)NH * T * T];
__device__ float g_ctxf[T * NH * HD];
__device__ float g_logits[T * NE];
__device__ int   g_cnt[NE];
__device__ int   g_poff[NE];
__device__ int   g_ptok[NE * T];
__device__ float g_pw[NE * T];

// ---------------- bf16 hi/lo operand buffers (router-critical path) ----------
__device__ bf16 g_hh[T * H],  g_hl[T * H];
__device__ bf16 g_qh[T * NH * HD], g_ql[T * NH * HD];
__device__ bf16 g_kh[T * NKV * HD], g_kl[T * NKV * HD];
__device__ bf16 g_vh[T * NKV * HD], g_vl[T * NKV * HD];
__device__ bf16 g_ph[(size_t)NH * T * T], g_pl[(size_t)NH * T * T];
__device__ bf16 g_ch[T * 1024], g_cl[T * 1024];
__device__ bf16 g_wqkvh[H * QKV_N], g_wqkvl[H * QKV_N];
__device__ bf16 g_wdh[H * H], g_wdl[H * H];

// ---------------- fp16 operands (post-routing path) --------------------------
__device__ f16 g_h2h[T * H], g_h2l[T * H];
__device__ f16 g_ash[T * FDIM], g_asl[T * FDIM];
__device__ f16 g_amh[(size_t)PAD_ROWS * 1024], g_aml[(size_t)PAD_ROWS * 1024];
__device__ f16 g_w13f[(size_t)NE * H * 2048];   // interleaved [g0,u0,g1,u1,...]
__device__ f16 g_w2f[(size_t)NE * FDIM * H];
__device__ f16 g_wsguf[H * 2048];               // interleaved
__device__ f16 g_wsdf[FDIM * H];

// ---------------- helpers ----------------------------------------------------
__device__ __forceinline__ void split_bf(float v, bf16& h, bf16& l) {
    h = __float2bfloat16(v);
    l = __float2bfloat16(v - __bfloat162float(h));
}
__device__ __forceinline__ void split2(float a, float b, bf162& h2, bf162& l2) {
    bf16 ha, la, hb, lb;
    split_bf(a, ha, la);
    split_bf(b, hb, lb);
    h2 = bf162{ha, hb};
    l2 = bf162{la, lb};
}
__device__ __forceinline__ void split_f16(float v, f16& h, f16& l) {
    h = __float2half(v);
    l = __float2half(v - __half2float(h));
}
__device__ __forceinline__ float silu_f(float g) {
    return g / (1.f + expf(-g));
}
__device__ __forceinline__ void mma16816(float* c, const uint32_t* a,
                                         const uint32_t* b) {
    asm volatile(
        "mma.sync.aligned.m16n8k16.row.col.f32.bf16.bf16.f32 "
        "{%0,%1,%2,%3}, {%4,%5,%6,%7}, {%8,%9}, {%0,%1,%2,%3};\n"
        : "+f"(c[0]), "+f"(c[1]), "+f"(c[2]), "+f"(c[3])
        : "r"(a[0]), "r"(a[1]), "r"(a[2]), "r"(a[3]), "r"(b[0]), "r"(b[1]));
}
__device__ __forceinline__ void mma16816f(float* c, const uint32_t* a,
                                          const uint32_t* b) {
    asm volatile(
        "mma.sync.aligned.m16n8k16.row.col.f32.f16.f16.f32 "
        "{%0,%1,%2,%3}, {%4,%5,%6,%7}, {%8,%9}, {%0,%1,%2,%3};\n"
        : "+f"(c[0]), "+f"(c[1]), "+f"(c[2]), "+f"(c[3])
        : "r"(a[0]), "r"(a[1]), "r"(a[2]), "r"(a[3]), "r"(b[0]), "r"(b[1]));
}
template <int N> __device__ __forceinline__ void cp_wait() {
    asm volatile("cp.async.wait_group %0;\n" ::"n"(N));
}
__device__ __forceinline__ void cp16(const void* src, void* dst) {
    uint32_t d = (uint32_t)__cvta_generic_to_shared(dst);
    asm volatile("cp.async.ca.shared.global [%0], [%1], 16;\n" ::"r"(d),
                 "l"(src));
}
__device__ __forceinline__ void ldm4(uint32_t& r0, uint32_t& r1, uint32_t& r2,
                                     uint32_t& r3, uint32_t addr) {
    asm volatile(
        "ldmatrix.sync.aligned.m8n8.x4.shared.b16 {%0,%1,%2,%3}, [%4];\n"
        : "=r"(r0), "=r"(r1), "=r"(r2), "=r"(r3)
        : "r"(addr));
}
__device__ __forceinline__ void ldm4t(uint32_t& r0, uint32_t& r1, uint32_t& r2,
                                      uint32_t& r3, uint32_t addr) {
    asm volatile(
        "ldmatrix.sync.aligned.m8n8.x4.trans.shared.b16 {%0,%1,%2,%3}, [%4];\n"
        : "=r"(r0), "=r"(r1), "=r"(r2), "=r"(r3)
        : "r"(addr));
}

// -------- GEMM cores: 256 threads, 8 warps, warp tile 64x32, paired k-slabs ---
// 6 slab buffers = 3 pairs; ONE commit + ONE barrier per pair (2 slabs).
#define SROW 40
#define BROW 264
#define BROW16 136
#define NSTAGE 6
#define TA_HALVES (128 * SROW)
#define TBN_HALVES (128 * SROW)
#define TBT_HALVES (16 * BROW)
#define TBT16_HALVES (16 * BROW16)
#define GSMEM_NT ((NSTAGE * (TA_HALVES + TBN_HALVES)) * 2)
#define GSMEM_TR ((NSTAGE * (TA_HALVES + TBT_HALVES)) * 2)
#define GSMEM_16 ((NSTAGE * (TA_HALVES + TBT16_HALVES)) * 2)

// paired-pipeline driver (ktiles must be even; all call sites are)
#define PIPEP_RUN(STAGEP, COMPUTE, KTILES)                 \
    do {                                                   \
        int kp = (KTILES) >> 1;                            \
        STAGEP(0, 0);                                      \
        if (kp > 1) STAGEP(1, 1);                          \
        for (int p = 0; p < kp; p++) {                     \
            if (p + 2 <= kp) cp_wait<1>();                 \
            else cp_wait<0>();                             \
            __syncthreads();                               \
            if (p + 2 < kp) STAGEP(p + 2, (p + 2) % 3);    \
            int s0 = 2 * (p % 3);                          \
            COMPUTE(s0);                                   \
            COMPUTE(s0 + 1);                               \
        }                                                  \
    } while (0)

// ---- non-trans bf16 3-term core (k_scores) ----------------------------------
template <class FA, class FB>
__device__ __forceinline__ void gemm_core_nt(
    const bf16* __restrict__ Ah, const bf16* __restrict__ Al,
    const bf16* __restrict__ Bh, const bf16* __restrict__ Bl, FA rowA, FB rowB,
    int ktiles, float (&acc)[4][4][4]) {
    extern __shared__ __align__(16) bf16 smem[];
    bf16* sA = smem;
    bf16* sB = smem + NSTAGE * TA_HALVES;
    const int tid = threadIdx.x, lane = tid & 31, warp = tid >> 5;
    const int wm = (warp >> 2) * 64, wn = (warp & 3) * 32;

#pragma unroll
    for (int a = 0; a < 4; a++)
#pragma unroll
        for (int b = 0; b < 4; b++)
#pragma unroll
            for (int r = 0; r < 4; r++) acc[a][b][r] = 0.f;

    auto stage1 = [&](int kt, int s) {
        bf16* dA = sA + s * TA_HALVES;
        bf16* dB = sB + s * TBN_HALVES;
#pragma unroll
        for (int i = tid; i < 512; i += 256) {
            int row = i >> 2, c = i & 3;
            int koff = kt * 16 + (c & 1) * 8;
            cp16((c < 2 ? Ah : Al) + rowA(row) + koff, dA + row * SROW + c * 8);
            cp16((c < 2 ? Bh : Bl) + rowB(row) + koff, dB + row * SROW + c * 8);
        }
    };
    auto stagep = [&](int p, int bp) {
        stage1(2 * p, 2 * bp);
        stage1(2 * p + 1, 2 * bp + 1);
        asm volatile("cp.async.commit_group;\n");
    };

    const int arow = ((lane >> 3) & 1) * 8 + (lane & 7);
    const int acol = (lane >> 4) * 8;
    const int brow = ((lane >> 4) & 1) * 8 + (lane & 7);
    const int bcol = ((lane >> 3) & 1) * 8;

    auto compute = [&](int s) {
        const bf16* A = sA + s * TA_HALVES;
        const bf16* B = sB + s * TBN_HALVES;
        uint32_t fah[4][4], fal[4][4], fbh[4][2], fbl[4][2];
#pragma unroll
        for (int mt = 0; mt < 4; mt++) {
            uint32_t ad = (uint32_t)__cvta_generic_to_shared(
                A + (wm + mt * 16 + arow) * SROW + acol);
            ldm4(fah[mt][0], fah[mt][1], fah[mt][2], fah[mt][3], ad);
            ldm4(fal[mt][0], fal[mt][1], fal[mt][2], fal[mt][3], ad + 32);
        }
#pragma unroll
        for (int p = 0; p < 2; p++) {
            uint32_t bd = (uint32_t)__cvta_generic_to_shared(
                B + (wn + p * 16 + brow) * SROW + bcol);
            ldm4(fbh[2 * p][0], fbh[2 * p][1], fbh[2 * p + 1][0],
                 fbh[2 * p + 1][1], bd);
            ldm4(fbl[2 * p][0], fbl[2 * p][1], fbl[2 * p + 1][0],
                 fbl[2 * p + 1][1], bd + 32);
        }
#pragma unroll
        for (int nt = 0; nt < 4; nt++)
#pragma unroll
            for (int mt = 0; mt < 4; mt++) mma16816(acc[mt][nt], fah[mt], fbh[nt]);
#pragma unroll
        for (int nt = 0; nt < 4; nt++)
#pragma unroll
            for (int mt = 0; mt < 4; mt++) mma16816(acc[mt][nt], fal[mt], fbh[nt]);
#pragma unroll
        for (int nt = 0; nt < 4; nt++)
#pragma unroll
            for (int mt = 0; mt < 4; mt++) mma16816(acc[mt][nt], fah[mt], fbl[nt]);
    };

    PIPEP_RUN(stagep, compute, ktiles);
}

// ---- trans bf16 3-term core ----------------------------------------------------
template <class FA>
__device__ __forceinline__ void gemm_core_tr(
    const bf16* __restrict__ Ah, const bf16* __restrict__ Al, FA rowA,
    const bf16* __restrict__ Bh, const bf16* __restrict__ Bl, int ldb,
    int ktiles, float (&acc)[4][4][4]) {
    extern __shared__ __align__(16) bf16 smem[];
    bf16* sA = smem;
    bf16* sB = smem + NSTAGE * TA_HALVES;
    const int tid = threadIdx.x, lane = tid & 31, warp = tid >> 5;
    const int wm = (warp >> 2) * 64, wn = (warp & 3) * 32;

#pragma unroll
    for (int a = 0; a < 4; a++)
#pragma unroll
        for (int b = 0; b < 4; b++)
#pragma unroll
            for (int r = 0; r < 4; r++) acc[a][b][r] = 0.f;

    auto stage1 = [&](int kt, int s) {
        bf16* dA = sA + s * TA_HALVES;
        bf16* dB = sB + s * TBT_HALVES;
#pragma unroll
        for (int i = tid; i < 512; i += 256) {
            int row = i >> 2, c = i & 3;
            int koff = kt * 16 + (c & 1) * 8;
            cp16((c < 2 ? Ah : Al) + rowA(row) + koff, dA + row * SROW + c * 8);
            int brw = i >> 5, sub = i & 31;
            int half = sub >> 4, nseg = sub & 15;
            const bf16* bsrc =
                (half ? Bl : Bh) + (size_t)(kt * 16 + brw) * ldb + nseg * 8;
            cp16(bsrc, dB + brw * BROW + half * 128 + nseg * 8);
        }
    };
    auto stagep = [&](int p, int bp) {
        stage1(2 * p, 2 * bp);
        stage1(2 * p + 1, 2 * bp + 1);
        asm volatile("cp.async.commit_group;\n");
    };

    const int arow = ((lane >> 3) & 1) * 8 + (lane & 7);
    const int acol = (lane >> 4) * 8;
    const int tkrow = (lane & 7) + ((lane >> 3) & 1) * 8;
    const int tnoff = (lane >> 4) * 8;

    auto compute = [&](int s) {
        const bf16* A = sA + s * TA_HALVES;
        const bf16* B = sB + s * TBT_HALVES;
        uint32_t fah[4][4], fal[4][4], fbh[4][2], fbl[4][2];
#pragma unroll
        for (int mt = 0; mt < 4; mt++) {
            uint32_t ad = (uint32_t)__cvta_generic_to_shared(
                A + (wm + mt * 16 + arow) * SROW + acol);
            ldm4(fah[mt][0], fah[mt][1], fah[mt][2], fah[mt][3], ad);
            ldm4(fal[mt][0], fal[mt][1], fal[mt][2], fal[mt][3], ad + 32);
        }
#pragma unroll
        for (int p = 0; p < 2; p++) {
            uint32_t bd = (uint32_t)__cvta_generic_to_shared(
                B + tkrow * BROW + wn + p * 16 + tnoff);
            ldm4t(fbh[2 * p][0], fbh[2 * p][1], fbh[2 * p + 1][0],
                  fbh[2 * p + 1][1], bd);
            ldm4t(fbl[2 * p][0], fbl[2 * p][1], fbl[2 * p + 1][0],
                  fbl[2 * p + 1][1], bd + 256);
        }
#pragma unroll
        for (int nt = 0; nt < 4; nt++)
#pragma unroll
            for (int mt = 0; mt < 4; mt++) mma16816(acc[mt][nt], fah[mt], fbh[nt]);
#pragma unroll
        for (int nt = 0; nt < 4; nt++)
#pragma unroll
            for (int mt = 0; mt < 4; mt++) mma16816(acc[mt][nt], fal[mt], fbh[nt]);
#pragma unroll
        for (int nt = 0; nt < 4; nt++)
#pragma unroll
            for (int mt = 0; mt < 4; mt++) mma16816(acc[mt][nt], fah[mt], fbl[nt]);
    };

    PIPEP_RUN(stagep, compute, ktiles);
}

// ---- trans fp16 2-term core ------------------------------------------------------
template <class FA>
__device__ __forceinline__ void gemm_core_16(
    const f16* __restrict__ Ah, const f16* __restrict__ Al, FA rowA,
    const f16* __restrict__ Bf, int ldb, int ktiles, float (&acc)[4][4][4]) {
    extern __shared__ __align__(16) bf16 smem[];
    f16* sA = reinterpret_cast<f16*>(smem);
    f16* sB = sA + NSTAGE * TA_HALVES;
    const int tid = threadIdx.x, lane = tid & 31, warp = tid >> 5;
    const int wm = (warp >> 2) * 64, wn = (warp & 3) * 32;

#pragma unroll
    for (int a = 0; a < 4; a++)
#pragma unroll
        for (int b = 0; b < 4; b++)
#pragma unroll
            for (int r = 0; r < 4; r++) acc[a][b][r] = 0.f;

    auto stage1 = [&](int kt, int s) {
        f16* dA = sA + s * TA_HALVES;
        f16* dB = sB + s * TBT16_HALVES;
#pragma unroll
        for (int i = tid; i < 512; i += 256) {
            int row = i >> 2, c = i & 3;
            int koff = kt * 16 + (c & 1) * 8;
            cp16((c < 2 ? Ah : Al) + rowA(row) + koff, dA + row * SROW + c * 8);
        }
        {
            int i = tid;
            int brw = i >> 4, nseg = i & 15;
            const f16* bsrc = Bf + (size_t)(kt * 16 + brw) * ldb + nseg * 8;
            cp16(bsrc, dB + brw * BROW16 + nseg * 8);
        }
    };
    auto stagep = [&](int p, int bp) {
        stage1(2 * p, 2 * bp);
        stage1(2 * p + 1, 2 * bp + 1);
        asm volatile("cp.async.commit_group;\n");
    };

    const int arow = ((lane >> 3) & 1) * 8 + (lane & 7);
    const int acol = (lane >> 4) * 8;
    const int tkrow = (lane & 7) + ((lane >> 3) & 1) * 8;
    const int tnoff = (lane >> 4) * 8;

    auto compute = [&](int s) {
        const f16* A = sA + s * TA_HALVES;
        const f16* B = sB + s * TBT16_HALVES;
        uint32_t fah[4][4], fal[4][4], fb[4][2];
#pragma unroll
        for (int mt = 0; mt < 4; mt++) {
            uint32_t ad = (uint32_t)__cvta_generic_to_shared(
                A + (wm + mt * 16 + arow) * SROW + acol);
            ldm4(fah[mt][0], fah[mt][1], fah[mt][2], fah[mt][3], ad);
            ldm4(fal[mt][0], fal[mt][1], fal[mt][2], fal[mt][3], ad + 32);
        }
#pragma unroll
        for (int p = 0; p < 2; p++) {
            uint32_t bd = (uint32_t)__cvta_generic_to_shared(
                B + tkrow * BROW16 + wn + p * 16 + tnoff);
            ldm4t(fb[2 * p][0], fb[2 * p][1], fb[2 * p + 1][0],
                  fb[2 * p + 1][1], bd);
        }
#pragma unroll
        for (int nt = 0; nt < 4; nt++)
#pragma unroll
            for (int mt = 0; mt < 4; mt++) mma16816f(acc[mt][nt], fah[mt], fb[nt]);
#pragma unroll
        for (int nt = 0; nt < 4; nt++)
#pragma unroll
            for (int mt = 0; mt < 4; mt++) mma16816f(acc[mt][nt], fal[mt], fb[nt]);
    };

    PIPEP_RUN(stagep, compute, ktiles);
}

// ---- trans fp16 1-term core (A single fp16) — used by moe_y ----------------------
template <class FA>
__device__ __forceinline__ void gemm_core_16s(
    const f16* __restrict__ Af, FA rowA, const f16* __restrict__ Bf, int ldb,
    int ktiles, float (&acc)[4][4][4]) {
    extern __shared__ __align__(16) bf16 smem[];
    f16* sA = reinterpret_cast<f16*>(smem);
    f16* sB = sA + NSTAGE * TA_HALVES;
    const int tid = threadIdx.x, lane = tid & 31, warp = tid >> 5;
    const int wm = (warp >> 2) * 64, wn = (warp & 3) * 32;

#pragma unroll
    for (int a = 0; a < 4; a++)
#pragma unroll
        for (int b = 0; b < 4; b++)
#pragma unroll
            for (int r = 0; r < 4; r++) acc[a][b][r] = 0.f;

    auto stage1 = [&](int kt, int s) {
        f16* dA = sA + s * TA_HALVES;
        f16* dB = sB + s * TBT16_HALVES;
        {
            int i = tid;  // 256 A segs (hi only)
            int row = i >> 1, c = i & 1;
            int koff = kt * 16 + c * 8;
            cp16(Af + rowA(row) + koff, dA + row * SROW + c * 8);
        }
        {
            int i = tid;  // 256 B segs
            int brw = i >> 4, nseg = i & 15;
            const f16* bsrc = Bf + (size_t)(kt * 16 + brw) * ldb + nseg * 8;
            cp16(bsrc, dB + brw * BROW16 + nseg * 8);
        }
    };
    auto stagep = [&](int p, int bp) {
        stage1(2 * p, 2 * bp);
        stage1(2 * p + 1, 2 * bp + 1);
        asm volatile("cp.async.commit_group;\n");
    };

    const int arow = ((lane >> 3) & 1) * 8 + (lane & 7);
    const int acol = (lane >> 4) * 8;
    const int tkrow = (lane & 7) + ((lane >> 3) & 1) * 8;
    const int tnoff = (lane >> 4) * 8;

    auto compute = [&](int s) {
        const f16* A = sA + s * TA_HALVES;
        const f16* B = sB + s * TBT16_HALVES;
        uint32_t fah[4][4], fb[4][2];
#pragma unroll
        for (int mt = 0; mt < 4; mt++) {
            uint32_t ad = (uint32_t)__cvta_generic_to_shared(
                A + (wm + mt * 16 + arow) * SROW + acol);
            ldm4(fah[mt][0], fah[mt][1], fah[mt][2], fah[mt][3], ad);
        }
#pragma unroll
        for (int p = 0; p < 2; p++) {
            uint32_t bd = (uint32_t)__cvta_generic_to_shared(
                B + tkrow * BROW16 + wn + p * 16 + tnoff);
            ldm4t(fb[2 * p][0], fb[2 * p][1], fb[2 * p + 1][0],
                  fb[2 * p + 1][1], bd);
        }
#pragma unroll
        for (int nt = 0; nt < 4; nt++)
#pragma unroll
            for (int mt = 0; mt < 4; mt++) mma16816f(acc[mt][nt], fah[mt], fb[nt]);
    };

    PIPEP_RUN(stagep, compute, ktiles);
}

// epilogue iterator (8 warps, 64x32)
template <class F>
__device__ __forceinline__ void epi128(float (&acc)[4][4][4], F f) {
    const int lane = threadIdx.x & 31, warp = threadIdx.x >> 5;
    const int wm = (warp >> 2) * 64, wn = (warp & 3) * 32;
    const int gid = lane >> 2, tc = lane & 3;
#pragma unroll
    for (int mt = 0; mt < 4; mt++)
#pragma unroll
        for (int nt = 0; nt < 4; nt++)
#pragma unroll
            for (int r = 0; r < 4; r++) {
                int row = wm + mt * 16 + gid + ((r >> 1) << 3);
                int col = wn + nt * 8 + tc * 2 + (r & 1);
                f(row, col, acc[mt][nt][r]);
            }
}

// fused SiLU epilogue: interleaved [g,u] columns; f(row, act_col, act)
template <class F>
__device__ __forceinline__ void epi128_silu(float (&acc)[4][4][4], F f) {
    const int lane = threadIdx.x & 31, warp = threadIdx.x >> 5;
    const int wm = (warp >> 2) * 64, wn = (warp & 3) * 32;
    const int gid = lane >> 2, tc = lane & 3;
#pragma unroll
    for (int mt = 0; mt < 4; mt++)
#pragma unroll
        for (int nt = 0; nt < 4; nt++) {
            int acol = (wn >> 1) + nt * 4 + tc;
#pragma unroll
            for (int rr = 0; rr < 2; rr++) {
                int row = wm + mt * 16 + gid + rr * 8;
                float g = acc[mt][nt][rr * 2];
                float u = acc[mt][nt][rr * 2 + 1];
                f(row, acol, silu_f(g) * u);
            }
        }
}

// ---------------- streaming splits / zero --------------------------------------
__global__ void k_zero_buf(float* __restrict__ p, int n4) {
    int i = blockIdx.x * 256 + threadIdx.x;
    if (i < n4) reinterpret_cast<float4*>(p)[i] = float4{0.f, 0.f, 0.f, 0.f};
}

__global__ void k_split(const float* __restrict__ src, bf16* __restrict__ dh,
                        bf16* __restrict__ dl, int n8) {
    int i = blockIdx.x * 256 + threadIdx.x;
    if (i >= n8) return;
    const float4* s4 = reinterpret_cast<const float4*>(src) + i * 2;
    float4 a = s4[0], b = s4[1];
    bf16 hbuf[8], lbuf[8];
    split_bf(a.x, hbuf[0], lbuf[0]);
    split_bf(a.y, hbuf[1], lbuf[1]);
    split_bf(a.z, hbuf[2], lbuf[2]);
    split_bf(a.w, hbuf[3], lbuf[3]);
    split_bf(b.x, hbuf[4], lbuf[4]);
    split_bf(b.y, hbuf[5], lbuf[5]);
    split_bf(b.z, hbuf[6], lbuf[6]);
    split_bf(b.w, hbuf[7], lbuf[7]);
    reinterpret_cast<uint4*>(dh)[i] = *reinterpret_cast<uint4*>(hbuf);
    reinterpret_cast<uint4*>(dl)[i] = *reinterpret_cast<uint4*>(lbuf);
}

__global__ void k_split16(const float* __restrict__ src, f16* __restrict__ d,
                          int n8) {
    int i = blockIdx.x * 256 + threadIdx.x;
    if (i >= n8) return;
    const float4* s4 = reinterpret_cast<const float4*>(src) + i * 2;
    float4 a = s4[0], b = s4[1];
    f16 buf[8];
    buf[0] = __float2half(a.x);
    buf[1] = __float2half(a.y);
    buf[2] = __float2half(a.z);
    buf[3] = __float2half(a.w);
    buf[4] = __float2half(b.x);
    buf[5] = __float2half(b.y);
    buf[6] = __float2half(b.z);
    buf[7] = __float2half(b.w);
    reinterpret_cast<uint4*>(d)[i] = *reinterpret_cast<uint4*>(buf);
}

__global__ void k_split16i(const float* __restrict__ src, f16* __restrict__ dst) {
    const int K = H;
    src += (size_t)blockIdx.z * K * 2048;
    dst += (size_t)blockIdx.z * K * 2048;
    int i = blockIdx.x * 256 + threadIdx.x;
    int k = i >> 8, j = i & 255;
    float4 g4 = *reinterpret_cast<const float4*>(src + (size_t)k * 2048 + 4 * j);
    float4 u4 = *reinterpret_cast<const float4*>(src + (size_t)k * 2048 + 1024 + 4 * j);
    f16 buf[8];
    buf[0] = __float2half(g4.x); buf[1] = __float2half(u4.x);
    buf[2] = __float2half(g4.y); buf[3] = __float2half(u4.y);
    buf[4] = __float2half(g4.z); buf[5] = __float2half(u4.z);
    buf[6] = __float2half(g4.w); buf[7] = __float2half(u4.w);
    *reinterpret_cast<uint4*>(dst + (size_t)k * 2048 + 8 * j) =
        *reinterpret_cast<uint4*>(buf);
}

// ---------------- qkv GEMM with fused V split --------------------------------
__global__ __launch_bounds__(256) void k_qkv() {
    const int rb = blockIdx.y * 128, cb = blockIdx.x * 128;
    float acc[4][4][4];
    gemm_core_tr(
        g_hh, g_hl, [&](int m) { return (size_t)(rb + m) * H; }, g_wqkvh + cb,
        g_wqkvl + cb, QKV_N, H / 16, acc);
    epi128(acc, [&](int r, int c, float v) {
        g_qkv[(size_t)(rb + r) * QKV_N + cb + c] = v;
        int vc = cb + c - (NH + NKV) * HD;
        if (vc >= 0) {
            size_t o = (size_t)(rb + r) * (NKV * HD) + vc;
            split_bf(v, g_vh[o], g_vl[o]);
        }
    });
}

// ---------------- generic bf16 GEMM (trans-B) ----------------------------------
__global__ __launch_bounds__(256) void k_gemm(
    const bf16* __restrict__ Ah, const bf16* __restrict__ Al, int sa,
    const bf16* __restrict__ Bh, const bf16* __restrict__ Bl, int ldb,
    float* __restrict__ C, int ldc, int ktiles, const float* __restrict__ addm) {
    const int rb = blockIdx.y * 128, cb = blockIdx.x * 128;
    float acc[4][4][4];
    gemm_core_tr(
        Ah, Al, [&](int m) { return (size_t)(rb + m) * sa; }, Bh + cb, Bl + cb,
        ldb, ktiles, acc);
    epi128(acc, [&](int r, int c, float v) {
        size_t idx = (size_t)(rb + r) * ldc + cb + c;
        if (addm) v += addm[idx];
        C[idx] = v;
    });
}

// ---------------- shared-expert su GEMM + fused SiLU ----------------------------
__global__ __launch_bounds__(256) void k_su() {
    const int rb = blockIdx.y * 128, cb = blockIdx.x * 128;
    float acc[4][4][4];
    gemm_core_16(
        g_h2h, g_h2l, [&](int m) { return (size_t)(rb + m) * H; },
        g_wsguf + cb, 2048, H / 16, acc);
    const int ab = cb >> 1;
    epi128_silu(acc, [&](int r, int ac, float a) {
        size_t o = (size_t)(rb + r) * FDIM + ab + ac;
        split_f16(a, g_ash[o], g_asl[o]);
    });
}

// ---------------- shared-expert down proj, atomic into out ----------------------
__global__ __launch_bounds__(256) void k_sdown(float* __restrict__ outp) {
    const int rb = blockIdx.y * 128, cb = blockIdx.x * 128;
    float acc[4][4][4];
    gemm_core_16(
        g_ash, g_asl, [&](int m) { return (size_t)(rb + m) * FDIM; },
        g_wsdf + cb, H, FDIM / 16, acc);
    epi128(acc, [&](int r, int c, float v) {
        atomicAdd(&outp[(size_t)(rb + r) * H + cb + c], v);
    });
}

// ---------------- add + rmsnorm (ln1) ---------------------------------------------
__global__ void k_add_rms1(const float* __restrict__ hs,
                           const float* __restrict__ res,
                           const float* __restrict__ w) {
    const int t = blockIdx.x, tid = threadIdx.x;
    float2 x[2];
    float ss = 0.f;
#pragma unroll
    for (int i = 0; i < 2; i++) {
        int c = (tid + i * 256) * 2;
        float2 a = *reinterpret_cast<const float2*>(hs + (size_t)t * H + c);
        float2 b = *reinterpret_cast<const float2*>(res + (size_t)t * H + c);
        float2 v = {a.x + b.x, a.y + b.y};
        *reinterpret_cast<float2*>(g_resid + (size_t)t * H + c) = v;
        x[i] = v;
        ss += v.x * v.x + v.y * v.y;
    }
    __shared__ float red[256];
    red[tid] = ss;
    __syncthreads();
    for (int s = 128; s > 0; s >>= 1) {
        if (tid < s) red[tid] += red[tid + s];
        __syncthreads();
    }
    float r = rsqrtf(red[0] / (float)H + 1e-6f);
#pragma unroll
    for (int i = 0; i < 2; i++) {
        int c = (tid + i * 256) * 2;
        bf162 h2, l2;
        split2(x[i].x * r * w[c], x[i].y * r * w[c + 1], h2, l2);
        *reinterpret_cast<bf162*>(g_hh + (size_t)t * H + c) = h2;
        *reinterpret_cast<bf162*>(g_hl + (size_t)t * H + c) = l2;
    }
}

// ---------------- rmsnorm (ln2) -----------------------------------------------------
__global__ void k_rms2(const float* __restrict__ resid2,
                       const float* __restrict__ w) {
    const int t = blockIdx.x, tid = threadIdx.x;
    float2 x[2];
    float ss = 0.f;
#pragma unroll
    for (int i = 0; i < 2; i++) {
        int c = (tid + i * 256) * 2;
        float2 v = *reinterpret_cast<const float2*>(resid2 + (size_t)t * H + c);
        x[i] = v;
        ss += v.x * v.x + v.y * v.y;
    }
    __shared__ float red[256];
    red[tid] = ss;
    __syncthreads();
    for (int s = 128; s > 0; s >>= 1) {
        if (tid < s) red[tid] += red[tid + s];
        __syncthreads();
    }
    float r = rsqrtf(red[0] / (float)H + 1e-6f);
#pragma unroll
    for (int i = 0; i < 2; i++) {
        int c = (tid + i * 256) * 2;
        float v0 = x[i].x * r * w[c], v1 = x[i].y * r * w[c + 1];
        *reinterpret_cast<float2*>(g_h + (size_t)t * H + c) = float2{v0, v1};
        f16 h0, l0, h1, l1;
        split_f16(v0, h0, l0);
        split_f16(v1, h1, l1);
        *reinterpret_cast<__half2*>(g_h2h + (size_t)t * H + c) =
            __halves2half2(h0, h1);
        *reinterpret_cast<__half2*>(g_h2l + (size_t)t * H + c) =
            __halves2half2(l0, l1);
    }
}

// ---------------- per-head rmsnorm + rope -------------------------------------------
__global__ void k_qknorm_rope(const int* __restrict__ pos_ids,
                              const float* __restrict__ qnw,
                              const float* __restrict__ knw) {
    const int t = blockIdx.x, hh = blockIdx.y, d = threadIdx.x;
    const float* src;
    const float* w;
    bf16 *dh, *dl;
    if (hh < NH) {
        src = g_qkv + (size_t)t * QKV_N + hh * HD;
        w = qnw;
        dh = g_qh + ((size_t)t * NH + hh) * HD;
        dl = g_ql + ((size_t)t * NH + hh) * HD;
    } else {
        int kk = hh - NH;
        src = g_qkv + (size_t)t * QKV_N + NH * HD + kk * HD;
        w = knw;
        dh = g_kh + ((size_t)t * NKV + kk) * HD;
        dl = g_kl + ((size_t)t * NKV + kk) * HD;
    }
    float x = src[d];
    float ss = x * x;
#pragma unroll
    for (int o = 16; o > 0; o >>= 1) ss += __shfl_xor_sync(0xffffffffu, ss, o);
    __shared__ float wsum[4];
    if ((d & 31) == 0) wsum[d >> 5] = ss;
    __syncthreads();
    ss = wsum[0] + wsum[1] + wsum[2] + wsum[3];
    float xn = x * rsqrtf(ss / (float)HD + 1e-6f) * w[d];
    __shared__ float xb[HD];
    xb[d] = xn;
    __syncthreads();
    int p = pos_ids[t];
    if (d < 64) {
        float inv = powf(10000.f, -(float)d / 64.f);
        float ang = (float)p * inv;
        float c = cosf(ang), s = sinf(ang);
        float x1 = xb[d], x2 = xb[d + 64];
        split_bf(x1 * c - x2 * s, dh[d], dl[d]);
        split_bf(x2 * c + x1 * s, dh[d + 64], dl[d + 64]);
    }
}

// ---------------- attention scores ----------------------------------------------------
__global__ __launch_bounds__(256) void k_scores() {
    const int jt = blockIdx.x, it = blockIdx.y, h = blockIdx.z;
    if (jt > it) return;
    float acc[4][4][4];
    gemm_core_nt(
        g_qh, g_ql, g_kh, g_kl,
        [&](int m) { return ((size_t)(it * 128 + m) * NH + h) * HD; },
        [&](int n) { return ((size_t)(jt * 128 + n) * NKV + (h >> 2)) * HD; },
        HD / 16, acc);
    const float scale = 0.08838834764831845f;
    float* S = g_scores + (size_t)h * T * T;
    epi128(acc, [&](int r, int c, float v) {
        int i = it * 128 + r;
        int j = jt * 128 + c;
        S[(size_t)i * T + j] = (j <= i) ? v * scale : -3.0e38f;
    });
}

// ---------------- row softmax -> bf16 P -------------------------------------------------
__global__ void k_softmax() {
    const int i = blockIdx.x, h = blockIdx.y, tid = threadIdx.x;
    const float4* S4 =
        reinterpret_cast<const float4*>(g_scores + ((size_t)h * T + i) * T);
    bf162* Ph = reinterpret_cast<bf162*>(g_ph + ((size_t)h * T + i) * T);
    bf162* Pl = reinterpret_cast<bf162*>(g_pl + ((size_t)h * T + i) * T);
    const int n4 = (((i >> 7) + 1) << 7) >> 2;
    __shared__ float4 buf[T / 4];
    __shared__ float red[256];
    float mx = -3.4e38f;
    for (int j = tid; j < n4; j += 256) {
        float4 v = S4[j];
        buf[j] = v;
        mx = fmaxf(fmaxf(mx, fmaxf(v.x, v.y)), fmaxf(v.z, v.w));
    }
    red[tid] = mx;
    __syncthreads();
    for (int s = 128; s > 0; s >>= 1) {
        if (tid < s) red[tid] = fmaxf(red[tid], red[tid + s]);
        __syncthreads();
    }
    mx = red[0];
    __syncthreads();
    float sm = 0.f;
    for (int j = tid; j < n4; j += 256) {
        float4 v = buf[j];
        v.x = expf(v.x - mx);
        v.y = expf(v.y - mx);
        v.z = expf(v.z - mx);
        v.w = expf(v.w - mx);
        buf[j] = v;
        sm += v.x + v.y + v.z + v.w;
    }
    red[tid] = sm;
    __syncthreads();
    for (int s = 128; s > 0; s >>= 1) {
        if (tid < s) red[tid] += red[tid + s];
        __syncthreads();
    }
    float inv = 1.f / red[0];
    for (int j = tid; j < n4; j += 256) {
        float4 v = buf[j];
        bf162 h0, l0, h1, l1;
        split2(v.x * inv, v.y * inv, h0, l0);
        split2(v.z * inv, v.w * inv, h1, l1);
        Ph[j * 2] = h0;
        Ph[j * 2 + 1] = h1;
        Pl[j * 2] = l0;
        Pl[j * 2 + 1] = l1;
    }
}

// ---------------- ctx = P @ V, balanced chunked split-K -------------------------------
__global__ __launch_bounds__(256) void k_ctx_chunk() {
    const int ck = blockIdx.x, it = blockIdx.y, h = blockIdx.z;
    if (ck > it) return;
    float acc[4][4][4];
    const int cb = (h >> 2) * 128;
    const size_t koff = (size_t)ck * 128;
    gemm_core_tr(
        g_ph, g_pl,
        [&](int m) { return ((size_t)h * T + it * 128 + m) * T + koff; },
        g_vh + koff * (NKV * HD) + cb, g_vl + koff * (NKV * HD) + cb, NKV * HD,
        8, acc);
    epi128(acc, [&](int r, int c, float v) {
        atomicAdd(&g_ctxf[(size_t)(it * 128 + r) * (NH * HD) + h * HD + c], v);
    });
}

// fp32 ctx -> bf16 hi/lo
__global__ void k_ctx_split() {
    int i = blockIdx.x * 256 + threadIdx.x;
    if (i >= T * 1024 / 8) return;
    const float4* s4 = reinterpret_cast<const float4*>(g_ctxf) + i * 2;
    float4 a = s4[0], b = s4[1];
    bf16 hbuf[8], lbuf[8];
    split_bf(a.x, hbuf[0], lbuf[0]);
    split_bf(a.y, hbuf[1], lbuf[1]);
    split_bf(a.z, hbuf[2], lbuf[2]);
    split_bf(a.w, hbuf[3], lbuf[3]);
    split_bf(b.x, hbuf[4], lbuf[4]);
    split_bf(b.y, hbuf[5], lbuf[5]);
    split_bf(b.z, hbuf[6], lbuf[6]);
    split_bf(b.w, hbuf[7], lbuf[7]);
    reinterpret_cast<uint4*>(g_ch)[i] = *reinterpret_cast<uint4*>(hbuf);
    reinterpret_cast<uint4*>(g_cl)[i] = *reinterpret_cast<uint4*>(lbuf);
}

// ---------------- gate logits -------------------------------------------------------------
__global__ void k_gate(const float* __restrict__ gw) {
    const int t = blockIdx.x, tid = threadIdx.x;
    const int e = tid & 15, seg = tid >> 4;
    const float* hr = g_h + (size_t)t * H;
    float s = 0.f;
    for (int k = seg * 128; k < seg * 128 + 128; k++) s += hr[k] * gw[k * NE + e];
    __shared__ float red[128];
    red[tid] = s;
    __syncthreads();
    if (tid < NE) {
        float v = 0.f;
        for (int g = 0; g < 8; g++) v += red[g * 16 + tid];
        g_logits[t * NE + tid] = v;
    }
}

// ---------------- routing -------------------------------------------------------------------
__global__ void k_zero_cnt() {
    if (threadIdx.x < NE) g_cnt[threadIdx.x] = 0;
}

__global__ void k_route(const float* __restrict__ bias) {
    const int t = blockIdx.x * 256 + threadIdx.x;
    if (t >= T) return;
    float sig[NE], sfc[NE];
#pragma unroll
    for (int e = 0; e < NE; e++) {
        float l = g_logits[t * NE + e];
        sig[e] = 1.f / (1.f + expf(-l));
        sfc[e] = sig[e] + bias[e];
    }
    float gs[4];
#pragma unroll
    for (int g = 0; g < 4; g++) {
        float m1 = -3.4e38f, m2 = -3.4e38f;
#pragma unroll
        for (int i = 0; i < 4; i++) {
            float v = sfc[g * 4 + i];
            if (v > m1) { m2 = m1; m1 = v; }
            else if (v > m2) m2 = v;
        }
        gs[g] = m1 + m2;
    }
    int g1 = 0;
    for (int g = 1; g < 4; g++) if (gs[g] > gs[g1]) g1 = g;
    int g2 = -1;
    for (int g = 0; g < 4; g++) {
        if (g == g1) continue;
        if (g2 < 0 || gs[g] > gs[g2]) g2 = g;
    }
    bool allowed[NE];
#pragma unroll
    for (int e = 0; e < NE; e++) {
        int g = e >> 2;
        allowed[e] = (g == g1) || (g == g2);
    }
    int sel[4];
    bool picked[NE];
#pragma unroll
    for (int e = 0; e < NE; e++) picked[e] = false;
    float wsum = 0.f;
#pragma unroll
    for (int it = 0; it < 4; it++) {
        int bi = -1;
        float bv = -3.4e38f;
        for (int e = 0; e < NE; e++) {
            if (!allowed[e] || picked[e]) continue;
            if (sfc[e] > bv) { bv = sfc[e]; bi = e; }
        }
        picked[bi] = true;
        sel[it] = bi;
        wsum += sig[bi];
    }
    float inv = 1.f / (wsum + 1e-20f);
#pragma unroll
    for (int it = 0; it < 4; it++) {
        int e = sel[it];
        int pos = atomicAdd(&g_cnt[e], 1);
        g_ptok[e * T + pos] = t;
        g_pw[e * T + pos] = sig[e] * inv;
    }
}

__global__ void k_offsets() {
    if (threadIdx.x == 0) {
        int run = 0;
        for (int e = 0; e < NE; e++) {
            g_poff[e] = run;
            run += ((g_cnt[e] + 127) / 128) * 128;
        }
    }
}

// ---------------- MoE gu GEMM + fused SiLU -> fp16 act ------------------------------
__global__ __launch_bounds__(256) void k_moe_gu() {
    const int e = blockIdx.z, rt = blockIdx.y, bn = blockIdx.x;
    const int cnt = g_cnt[e];
    if (rt * 128 >= cnt) return;
    const int off = g_poff[e];
    const int* ptok = g_ptok + e * T;
    const int cb = bn * 128;
    float acc[4][4][4];
    gemm_core_16(
        g_h2h, g_h2l,
        [&](int m) {
            int lr = rt * 128 + m;
            int tok = ptok[lr < cnt ? lr : cnt - 1];
            return (size_t)tok * H;
        },
        g_w13f + (size_t)e * H * 2048 + cb, 2048, H / 16, acc);
    const int ab = bn * 64;
    epi128_silu(acc, [&](int r, int ac, float a) {
        size_t row = (size_t)off + rt * 128 + r;
        size_t o = row * FDIM + ab + ac;
        split_f16(a, g_amh[o], g_aml[o]);
    });
}

// ---------------- MoE y, scatter-add (fp16 1-term A) ---------------------------------
__global__ __launch_bounds__(256) void k_moe_y(float* __restrict__ outp) {
    const int e = blockIdx.z, rt = blockIdx.y, bn = blockIdx.x;
    const int cnt = g_cnt[e];
    if (rt * 128 >= cnt) return;
    const int off = g_poff[e];
    const int cb = bn * 128;
    float acc[4][4][4];
    gemm_core_16s(
        g_amh, [&](int m) { return ((size_t)off + rt * 128 + m) * FDIM; },
        g_w2f + (size_t)e * FDIM * H + cb, H, FDIM / 16, acc);
    epi128(acc, [&](int r, int c, float v) {
        int lr = rt * 128 + r;
        if (lr >= cnt) return;
        int tok = g_ptok[e * T + lr];
        float w = 2.0f * g_pw[e * T + lr];
        atomicAdd(&outp[(size_t)tok * H + cb + c], w * v);
    });
}

// ---------------- stream/event setup at static init (pre-checkpoint) ------------
struct StreamInit {
    cudaStream_t s2;
    cudaEvent_t evF, evW, evR, evS;
    StreamInit() {
        cudaStreamCreateWithFlags(&s2, cudaStreamNonBlocking);
        cudaEventCreateWithFlags(&evF, cudaEventDisableTiming);
        cudaEventCreateWithFlags(&evW, cudaEventDisableTiming);
        cudaEventCreateWithFlags(&evR, cudaEventDisableTiming);
        cudaEventCreateWithFlags(&evS, cudaEventDisableTiming);
    }
};
static StreamInit g_si;

// ---------------- launch -----------------------------------------------------------------
extern "C" void kernel_launch(void* const* d_in, const int* in_sizes, int n_in,
                              void* d_out, int out_size) {
    const float* hs = (const float*)d_in[0];
    const float* res = (const float*)d_in[1];
    const int* pos = (const int*)d_in[2];
    const float* ln1_w = (const float*)d_in[3];
    const float* qkv_w = (const float*)d_in[4];
    const float* qnorm_w = (const float*)d_in[5];
    const float* knorm_w = (const float*)d_in[6];
    const float* dense_w = (const float*)d_in[7];
    const float* ln2_w = (const float*)d_in[8];
    const float* gate_w = (const float*)d_in[9];
    const float* expert_bias = (const float*)d_in[10];
    const float* w13 = (const float*)d_in[11];
    const float* w2 = (const float*)d_in[12];
    const float* ws_gate_up = (const float*)d_in[13];
    const float* ws_down = (const float*)d_in[14];

    float* out_mlp = (float*)d_out;
    float* out_resid2 = (float*)d_out + (size_t)T * H;

    float* p_resid;  cudaGetSymbolAddress((void**)&p_resid, g_resid);
    float* p_ctxf;   cudaGetSymbolAddress((void**)&p_ctxf, g_ctxf);
    bf16 *p_wqkvh, *p_wqkvl, *p_wdh, *p_wdl, *p_ch, *p_cl;
    f16 *p_w13f, *p_w2f, *p_wsguf, *p_wsdf;
    cudaGetSymbolAddress((void**)&p_wqkvh, g_wqkvh);
    cudaGetSymbolAddress((void**)&p_wqkvl, g_wqkvl);
    cudaGetSymbolAddress((void**)&p_wdh, g_wdh);
    cudaGetSymbolAddress((void**)&p_wdl, g_wdl);
    cudaGetSymbolAddress((void**)&p_ch, g_ch);
    cudaGetSymbolAddress((void**)&p_cl, g_cl);
    cudaGetSymbolAddress((void**)&p_w13f, g_w13f);
    cudaGetSymbolAddress((void**)&p_w2f, g_w2f);
    cudaGetSymbolAddress((void**)&p_wsguf, g_wsguf);
    cudaGetSymbolAddress((void**)&p_wsdf, g_wsdf);

    static bool attrs_set = false;
    if (!attrs_set) {
        cudaFuncSetAttribute(k_qkv, cudaFuncAttributeMaxDynamicSharedMemorySize, GSMEM_TR);
        cudaFuncSetAttribute(k_gemm, cudaFuncAttributeMaxDynamicSharedMemorySize, GSMEM_TR);
        cudaFuncSetAttribute(k_scores, cudaFuncAttributeMaxDynamicSharedMemorySize, GSMEM_NT);
        cudaFuncSetAttribute(k_ctx_chunk, cudaFuncAttributeMaxDynamicSharedMemorySize, GSMEM_TR);
        cudaFuncSetAttribute(k_su, cudaFuncAttributeMaxDynamicSharedMemorySize, GSMEM_16);
        cudaFuncSetAttribute(k_sdown, cudaFuncAttributeMaxDynamicSharedMemorySize, GSMEM_16);
        cudaFuncSetAttribute(k_moe_gu, cudaFuncAttributeMaxDynamicSharedMemorySize, GSMEM_16);
        cudaFuncSetAttribute(k_moe_y, cudaFuncAttributeMaxDynamicSharedMemorySize, GSMEM_16);
        attrs_set = true;
    }

    // fork: MoE/shared weight conversions on side stream
    cudaEventRecord(g_si.evF, 0);
    cudaStreamWaitEvent(g_si.s2, g_si.evF, 0);
    k_split16i<<<dim3(H * 2048 / 8 / 256, 1, NE), 256, 0, g_si.s2>>>(w13, p_w13f);
    k_split16<<<((int)((size_t)NE * FDIM * H / 8) + 255) / 256, 256, 0, g_si.s2>>>(
        w2, p_w2f, (int)((size_t)NE * FDIM * H / 8));
    k_split16i<<<dim3(H * 2048 / 8 / 256, 1, 1), 256, 0, g_si.s2>>>(ws_gate_up, p_wsguf);
    k_split16<<<(FDIM * H / 8 + 255) / 256, 256, 0, g_si.s2>>>(ws_down, p_wsdf,
                                                               FDIM * H / 8);
    cudaEventRecord(g_si.evW, g_si.s2);

    // main: zero accumulation buffers + early weight conversions
    k_zero_buf<<<(T * H / 4 + 255) / 256, 256>>>(out_mlp, T * H / 4);
    k_zero_buf<<<(T * H / 4 + 255) / 256, 256>>>(p_ctxf, T * H / 4);
    k_split<<<(H * QKV_N / 8 + 255) / 256, 256>>>(qkv_w, p_wqkvh, p_wqkvl, H * QKV_N / 8);
    k_split<<<(H * H / 8 + 255) / 256, 256>>>(dense_w, p_wdh, p_wdl, H * H / 8);

    // 1. resid + ln1
    k_add_rms1<<<T, 256>>>(hs, res, ln1_w);
    // 2. qkv GEMM with fused V split
    k_qkv<<<dim3(QKV_N / 128, T / 128), 256, GSMEM_TR>>>();
    // 3. q/k norm + rope
    k_qknorm_rope<<<dim3(T, NH + NKV), 128>>>(pos, qnorm_w, knorm_w);
    // 4. attention
    k_scores<<<dim3(T / 128, T / 128, NH), 256, GSMEM_NT>>>();
    k_softmax<<<dim3(T, NH), 256>>>();
    k_ctx_chunk<<<dim3(T / 128, T / 128, NH), 256, GSMEM_TR>>>();
    k_ctx_split<<<(T * 1024 / 8 + 255) / 256, 256>>>();
    // 7. resid2 = ctx @ dense_w + resid
    k_gemm<<<dim3(H / 128, T / 128), 256, GSMEM_TR>>>(
        p_ch, p_cl, NH * HD, p_wdh, p_wdl, H, out_resid2, H, H / 16, p_resid);
    // 8. h2
    k_rms2<<<T, 256>>>(out_resid2, ln2_w);
    cudaEventRecord(g_si.evR, 0);

    // side stream: shared expert chain
    cudaStreamWaitEvent(g_si.s2, g_si.evR, 0);
    k_su<<<dim3(2048 / 128, T / 128), 256, GSMEM_16, g_si.s2>>>();
    k_sdown<<<dim3(H / 128, T / 128), 256, GSMEM_16, g_si.s2>>>(out_mlp);
    cudaEventRecord(g_si.evS, g_si.s2);

    // main: routing
    k_gate<<<T, 128>>>(gate_w);
    k_zero_cnt<<<1, 32>>>();
    k_route<<<T / 256, 256>>>(expert_bias);
    k_offsets<<<1, 32>>>();

    // join weight conversions, then routed experts
    cudaStreamWaitEvent(0, g_si.evW, 0);
    k_moe_gu<<<dim3(2048 / 128, T / 128, NE), 256, GSMEM_16>>>();
    k_moe_y<<<dim3(H / 128, T / 128, NE), 256, GSMEM_16>>>(out_mlp);

    // join shared-expert chain
    cudaStreamWaitEvent(0, g_si.evS, 0);

    (void)in_sizes; (void)n_in; (void)out_size;
}

// round 13
// speedup vs baseline: 1.6256x; 1.1497x over previous
#include <cuda_runtime.h>
#include <cuda_bf16.h>
#include <cuda_fp16.h>
#include <math.h>
#include <stdint.h>

#define T 2048
#define H 1024
#define NH 8
#define NKV 2
#define HD 128
#define NE 16
#define QKV_N 1536
#define FDIM 1024
#define PAD_ROWS 10240

typedef __nv_bfloat16 bf16;
typedef __nv_bfloat162 bf162;
typedef __half f16;

// ---------------- fp32 scratch ----------------------------------------------
__device__ float g_resid[T * H];
__device__ float g_h[T * H];
__device__ float g_qkv[T * QKV_N];
__device__ float g_scores[(size_t)NH * T * T];
__device__ float g_ctxf[T * NH * HD];
__device__ float g_logits[T * NE];
__device__ int   g_cnt[NE];
__device__ int   g_poff[NE];
__device__ int   g_ptok[NE * T];
__device__ float g_pw[NE * T];

// ---------------- bf16 hi/lo operand buffers (router-critical path) ----------
__device__ bf16 g_hh[T * H],  g_hl[T * H];
__device__ bf16 g_qh[T * NH * HD], g_ql[T * NH * HD];
__device__ bf16 g_kh[T * NKV * HD], g_kl[T * NKV * HD];
__device__ bf16 g_vh[T * NKV * HD], g_vl[T * NKV * HD];
__device__ bf16 g_ph[(size_t)NH * T * T], g_pl[(size_t)NH * T * T];
__device__ bf16 g_ch[T * 1024], g_cl[T * 1024];
__device__ bf16 g_wqkvh[H * QKV_N], g_wqkvl[H * QKV_N];
__device__ bf16 g_wdh[H * H], g_wdl[H * H];

// ---------------- fp16 operands (post-routing path) --------------------------
__device__ f16 g_h2h[T * H], g_h2l[T * H];
__device__ f16 g_ash[T * FDIM], g_asl[T * FDIM];
__device__ f16 g_amh[(size_t)PAD_ROWS * 1024], g_aml[(size_t)PAD_ROWS * 1024];
__device__ f16 g_w13f[(size_t)NE * H * 2048];   // interleaved [g0,u0,g1,u1,...]
__device__ f16 g_w2f[(size_t)NE * FDIM * H];
__device__ f16 g_wsguf[H * 2048];               // interleaved
__device__ f16 g_wsdf[FDIM * H];

// ---------------- helpers ----------------------------------------------------
__device__ __forceinline__ void split_bf(float v, bf16& h, bf16& l) {
    h = __float2bfloat16(v);
    l = __float2bfloat16(v - __bfloat162float(h));
}
__device__ __forceinline__ void split2(float a, float b, bf162& h2, bf162& l2) {
    bf16 ha, la, hb, lb;
    split_bf(a, ha, la);
    split_bf(b, hb, lb);
    h2 = bf162{ha, hb};
    l2 = bf162{la, lb};
}
__device__ __forceinline__ void split_f16(float v, f16& h, f16& l) {
    h = __float2half(v);
    l = __float2half(v - __half2float(h));
}
__device__ __forceinline__ float silu_f(float g) {
    return g / (1.f + expf(-g));
}
__device__ __forceinline__ void mma16816(float* c, const uint32_t* a,
                                         const uint32_t* b) {
    asm volatile(
        "mma.sync.aligned.m16n8k16.row.col.f32.bf16.bf16.f32 "
        "{%0,%1,%2,%3}, {%4,%5,%6,%7}, {%8,%9}, {%0,%1,%2,%3};\n"
        : "+f"(c[0]), "+f"(c[1]), "+f"(c[2]), "+f"(c[3])
        : "r"(a[0]), "r"(a[1]), "r"(a[2]), "r"(a[3]), "r"(b[0]), "r"(b[1]));
}
__device__ __forceinline__ void mma16816f(float* c, const uint32_t* a,
                                          const uint32_t* b) {
    asm volatile(
        "mma.sync.aligned.m16n8k16.row.col.f32.f16.f16.f32 "
        "{%0,%1,%2,%3}, {%4,%5,%6,%7}, {%8,%9}, {%0,%1,%2,%3};\n"
        : "+f"(c[0]), "+f"(c[1]), "+f"(c[2]), "+f"(c[3])
        : "r"(a[0]), "r"(a[1]), "r"(a[2]), "r"(a[3]), "r"(b[0]), "r"(b[1]));
}
template <int N> __device__ __forceinline__ void cp_wait() {
    asm volatile("cp.async.wait_group %0;\n" ::"n"(N));
}
__device__ __forceinline__ void cp16(const void* src, void* dst) {
    uint32_t d = (uint32_t)__cvta_generic_to_shared(dst);
    asm volatile("cp.async.ca.shared.global [%0], [%1], 16;\n" ::"r"(d),
                 "l"(src));
}
__device__ __forceinline__ void ldm4(uint32_t& r0, uint32_t& r1, uint32_t& r2,
                                     uint32_t& r3, uint32_t addr) {
    asm volatile(
        "ldmatrix.sync.aligned.m8n8.x4.shared.b16 {%0,%1,%2,%3}, [%4];\n"
        : "=r"(r0), "=r"(r1), "=r"(r2), "=r"(r3)
        : "r"(addr));
}
__device__ __forceinline__ void ldm4t(uint32_t& r0, uint32_t& r1, uint32_t& r2,
                                      uint32_t& r3, uint32_t addr) {
    asm volatile(
        "ldmatrix.sync.aligned.m8n8.x4.trans.shared.b16 {%0,%1,%2,%3}, [%4];\n"
        : "=r"(r0), "=r"(r1), "=r"(r2), "=r"(r3)
        : "r"(addr));
}

// -------- GEMM cores: 256 threads, 8 warps, warp tile 64x32, paired k-slabs ---
#define SROW 40
#define BROW 264
#define BROW16 136
#define NSTAGE 6
#define TA_HALVES (128 * SROW)
#define TBN_HALVES (128 * SROW)
#define TBT_HALVES (16 * BROW)
#define TBT16_HALVES (16 * BROW16)
#define GSMEM_NT ((NSTAGE * (TA_HALVES + TBN_HALVES)) * 2)
#define GSMEM_TR ((NSTAGE * (TA_HALVES + TBT_HALVES)) * 2)
#define GSMEM_16 ((NSTAGE * (TA_HALVES + TBT16_HALVES)) * 2)

#define PIPEP_RUN(STAGEP, COMPUTE, KTILES)                 \
    do {                                                   \
        int kp = (KTILES) >> 1;                            \
        STAGEP(0, 0);                                      \
        if (kp > 1) STAGEP(1, 1);                          \
        for (int p = 0; p < kp; p++) {                     \
            if (p + 2 <= kp) cp_wait<1>();                 \
            else cp_wait<0>();                             \
            __syncthreads();                               \
            if (p + 2 < kp) STAGEP(p + 2, (p + 2) % 3);    \
            int s0 = 2 * (p % 3);                          \
            COMPUTE(s0);                                   \
            COMPUTE(s0 + 1);                               \
        }                                                  \
    } while (0)

// ---- non-trans bf16 3-term core (k_scores) ----------------------------------
template <class FA, class FB>
__device__ __forceinline__ void gemm_core_nt(
    const bf16* __restrict__ Ah, const bf16* __restrict__ Al,
    const bf16* __restrict__ Bh, const bf16* __restrict__ Bl, FA rowA, FB rowB,
    int ktiles, float (&acc)[4][4][4]) {
    extern __shared__ __align__(16) bf16 smem[];
    bf16* sA = smem;
    bf16* sB = smem + NSTAGE * TA_HALVES;
    const int tid = threadIdx.x, lane = tid & 31, warp = tid >> 5;
    const int wm = (warp >> 2) * 64, wn = (warp & 3) * 32;

#pragma unroll
    for (int a = 0; a < 4; a++)
#pragma unroll
        for (int b = 0; b < 4; b++)
#pragma unroll
            for (int r = 0; r < 4; r++) acc[a][b][r] = 0.f;

    auto stage1 = [&](int kt, int s) {
        bf16* dA = sA + s * TA_HALVES;
        bf16* dB = sB + s * TBN_HALVES;
#pragma unroll
        for (int i = tid; i < 512; i += 256) {
            int row = i >> 2, c = i & 3;
            int koff = kt * 16 + (c & 1) * 8;
            cp16((c < 2 ? Ah : Al) + rowA(row) + koff, dA + row * SROW + c * 8);
            cp16((c < 2 ? Bh : Bl) + rowB(row) + koff, dB + row * SROW + c * 8);
        }
    };
    auto stagep = [&](int p, int bp) {
        stage1(2 * p, 2 * bp);
        stage1(2 * p + 1, 2 * bp + 1);
        asm volatile("cp.async.commit_group;\n");
    };

    const int arow = ((lane >> 3) & 1) * 8 + (lane & 7);
    const int acol = (lane >> 4) * 8;
    const int brow = ((lane >> 4) & 1) * 8 + (lane & 7);
    const int bcol = ((lane >> 3) & 1) * 8;

    auto compute = [&](int s) {
        const bf16* A = sA + s * TA_HALVES;
        const bf16* B = sB + s * TBN_HALVES;
        uint32_t fah[4][4], fal[4][4], fbh[4][2], fbl[4][2];
#pragma unroll
        for (int mt = 0; mt < 4; mt++) {
            uint32_t ad = (uint32_t)__cvta_generic_to_shared(
                A + (wm + mt * 16 + arow) * SROW + acol);
            ldm4(fah[mt][0], fah[mt][1], fah[mt][2], fah[mt][3], ad);
            ldm4(fal[mt][0], fal[mt][1], fal[mt][2], fal[mt][3], ad + 32);
        }
#pragma unroll
        for (int p = 0; p < 2; p++) {
            uint32_t bd = (uint32_t)__cvta_generic_to_shared(
                B + (wn + p * 16 + brow) * SROW + bcol);
            ldm4(fbh[2 * p][0], fbh[2 * p][1], fbh[2 * p + 1][0],
                 fbh[2 * p + 1][1], bd);
            ldm4(fbl[2 * p][0], fbl[2 * p][1], fbl[2 * p + 1][0],
                 fbl[2 * p + 1][1], bd + 32);
        }
#pragma unroll
        for (int nt = 0; nt < 4; nt++)
#pragma unroll
            for (int mt = 0; mt < 4; mt++) mma16816(acc[mt][nt], fah[mt], fbh[nt]);
#pragma unroll
        for (int nt = 0; nt < 4; nt++)
#pragma unroll
            for (int mt = 0; mt < 4; mt++) mma16816(acc[mt][nt], fal[mt], fbh[nt]);
#pragma unroll
        for (int nt = 0; nt < 4; nt++)
#pragma unroll
            for (int mt = 0; mt < 4; mt++) mma16816(acc[mt][nt], fah[mt], fbl[nt]);
    };

    PIPEP_RUN(stagep, compute, ktiles);
}

// ---- trans bf16 3-term core ----------------------------------------------------
template <class FA>
__device__ __forceinline__ void gemm_core_tr(
    const bf16* __restrict__ Ah, const bf16* __restrict__ Al, FA rowA,
    const bf16* __restrict__ Bh, const bf16* __restrict__ Bl, int ldb,
    int ktiles, float (&acc)[4][4][4]) {
    extern __shared__ __align__(16) bf16 smem[];
    bf16* sA = smem;
    bf16* sB = smem + NSTAGE * TA_HALVES;
    const int tid = threadIdx.x, lane = tid & 31, warp = tid >> 5;
    const int wm = (warp >> 2) * 64, wn = (warp & 3) * 32;

#pragma unroll
    for (int a = 0; a < 4; a++)
#pragma unroll
        for (int b = 0; b < 4; b++)
#pragma unroll
            for (int r = 0; r < 4; r++) acc[a][b][r] = 0.f;

    auto stage1 = [&](int kt, int s) {
        bf16* dA = sA + s * TA_HALVES;
        bf16* dB = sB + s * TBT_HALVES;
#pragma unroll
        for (int i = tid; i < 512; i += 256) {
            int row = i >> 2, c = i & 3;
            int koff = kt * 16 + (c & 1) * 8;
            cp16((c < 2 ? Ah : Al) + rowA(row) + koff, dA + row * SROW + c * 8);
            int brw = i >> 5, sub = i & 31;
            int half = sub >> 4, nseg = sub & 15;
            const bf16* bsrc =
                (half ? Bl : Bh) + (size_t)(kt * 16 + brw) * ldb + nseg * 8;
            cp16(bsrc, dB + brw * BROW + half * 128 + nseg * 8);
        }
    };
    auto stagep = [&](int p, int bp) {
        stage1(2 * p, 2 * bp);
        stage1(2 * p + 1, 2 * bp + 1);
        asm volatile("cp.async.commit_group;\n");
    };

    const int arow = ((lane >> 3) & 1) * 8 + (lane & 7);
    const int acol = (lane >> 4) * 8;
    const int tkrow = (lane & 7) + ((lane >> 3) & 1) * 8;
    const int tnoff = (lane >> 4) * 8;

    auto compute = [&](int s) {
        const bf16* A = sA + s * TA_HALVES;
        const bf16* B = sB + s * TBT_HALVES;
        uint32_t fah[4][4], fal[4][4], fbh[4][2], fbl[4][2];
#pragma unroll
        for (int mt = 0; mt < 4; mt++) {
            uint32_t ad = (uint32_t)__cvta_generic_to_shared(
                A + (wm + mt * 16 + arow) * SROW + acol);
            ldm4(fah[mt][0], fah[mt][1], fah[mt][2], fah[mt][3], ad);
            ldm4(fal[mt][0], fal[mt][1], fal[mt][2], fal[mt][3], ad + 32);
        }
#pragma unroll
        for (int p = 0; p < 2; p++) {
            uint32_t bd = (uint32_t)__cvta_generic_to_shared(
                B + tkrow * BROW + wn + p * 16 + tnoff);
            ldm4t(fbh[2 * p][0], fbh[2 * p][1], fbh[2 * p + 1][0],
                  fbh[2 * p + 1][1], bd);
            ldm4t(fbl[2 * p][0], fbl[2 * p][1], fbl[2 * p + 1][0],
                  fbl[2 * p + 1][1], bd + 256);
        }
#pragma unroll
        for (int nt = 0; nt < 4; nt++)
#pragma unroll
            for (int mt = 0; mt < 4; mt++) mma16816(acc[mt][nt], fah[mt], fbh[nt]);
#pragma unroll
        for (int nt = 0; nt < 4; nt++)
#pragma unroll
            for (int mt = 0; mt < 4; mt++) mma16816(acc[mt][nt], fal[mt], fbh[nt]);
#pragma unroll
        for (int nt = 0; nt < 4; nt++)
#pragma unroll
            for (int mt = 0; mt < 4; mt++) mma16816(acc[mt][nt], fah[mt], fbl[nt]);
    };

    PIPEP_RUN(stagep, compute, ktiles);
}

// ---- trans fp16 2-term core ------------------------------------------------------
template <class FA>
__device__ __forceinline__ void gemm_core_16(
    const f16* __restrict__ Ah, const f16* __restrict__ Al, FA rowA,
    const f16* __restrict__ Bf, int ldb, int ktiles, float (&acc)[4][4][4]) {
    extern __shared__ __align__(16) bf16 smem[];
    f16* sA = reinterpret_cast<f16*>(smem);
    f16* sB = sA + NSTAGE * TA_HALVES;
    const int tid = threadIdx.x, lane = tid & 31, warp = tid >> 5;
    const int wm = (warp >> 2) * 64, wn = (warp & 3) * 32;

#pragma unroll
    for (int a = 0; a < 4; a++)
#pragma unroll
        for (int b = 0; b < 4; b++)
#pragma unroll
            for (int r = 0; r < 4; r++) acc[a][b][r] = 0.f;

    auto stage1 = [&](int kt, int s) {
        f16* dA = sA + s * TA_HALVES;
        f16* dB = sB + s * TBT16_HALVES;
#pragma unroll
        for (int i = tid; i < 512; i += 256) {
            int row = i >> 2, c = i & 3;
            int koff = kt * 16 + (c & 1) * 8;
            cp16((c < 2 ? Ah : Al) + rowA(row) + koff, dA + row * SROW + c * 8);
        }
        {
            int i = tid;
            int brw = i >> 4, nseg = i & 15;
            const f16* bsrc = Bf + (size_t)(kt * 16 + brw) * ldb + nseg * 8;
            cp16(bsrc, dB + brw * BROW16 + nseg * 8);
        }
    };
    auto stagep = [&](int p, int bp) {
        stage1(2 * p, 2 * bp);
        stage1(2 * p + 1, 2 * bp + 1);
        asm volatile("cp.async.commit_group;\n");
    };

    const int arow = ((lane >> 3) & 1) * 8 + (lane & 7);
    const int acol = (lane >> 4) * 8;
    const int tkrow = (lane & 7) + ((lane >> 3) & 1) * 8;
    const int tnoff = (lane >> 4) * 8;

    auto compute = [&](int s) {
        const f16* A = sA + s * TA_HALVES;
        const f16* B = sB + s * TBT16_HALVES;
        uint32_t fah[4][4], fal[4][4], fb[4][2];
#pragma unroll
        for (int mt = 0; mt < 4; mt++) {
            uint32_t ad = (uint32_t)__cvta_generic_to_shared(
                A + (wm + mt * 16 + arow) * SROW + acol);
            ldm4(fah[mt][0], fah[mt][1], fah[mt][2], fah[mt][3], ad);
            ldm4(fal[mt][0], fal[mt][1], fal[mt][2], fal[mt][3], ad + 32);
        }
#pragma unroll
        for (int p = 0; p < 2; p++) {
            uint32_t bd = (uint32_t)__cvta_generic_to_shared(
                B + tkrow * BROW16 + wn + p * 16 + tnoff);
            ldm4t(fb[2 * p][0], fb[2 * p][1], fb[2 * p + 1][0],
                  fb[2 * p + 1][1], bd);
        }
#pragma unroll
        for (int nt = 0; nt < 4; nt++)
#pragma unroll
            for (int mt = 0; mt < 4; mt++) mma16816f(acc[mt][nt], fah[mt], fb[nt]);
#pragma unroll
        for (int nt = 0; nt < 4; nt++)
#pragma unroll
            for (int mt = 0; mt < 4; mt++) mma16816f(acc[mt][nt], fal[mt], fb[nt]);
    };

    PIPEP_RUN(stagep, compute, ktiles);
}

// ---- trans fp16 1-term core (A single fp16) — moe_gu / moe_y ----------------------
template <class FA>
__device__ __forceinline__ void gemm_core_16s(
    const f16* __restrict__ Af, FA rowA, const f16* __restrict__ Bf, int ldb,
    int ktiles, float (&acc)[4][4][4]) {
    extern __shared__ __align__(16) bf16 smem[];
    f16* sA = reinterpret_cast<f16*>(smem);
    f16* sB = sA + NSTAGE * TA_HALVES;
    const int tid = threadIdx.x, lane = tid & 31, warp = tid >> 5;
    const int wm = (warp >> 2) * 64, wn = (warp & 3) * 32;

#pragma unroll
    for (int a = 0; a < 4; a++)
#pragma unroll
        for (int b = 0; b < 4; b++)
#pragma unroll
            for (int r = 0; r < 4; r++) acc[a][b][r] = 0.f;

    auto stage1 = [&](int kt, int s) {
        f16* dA = sA + s * TA_HALVES;
        f16* dB = sB + s * TBT16_HALVES;
        {
            int i = tid;  // 256 A segs (hi only)
            int row = i >> 1, c = i & 1;
            int koff = kt * 16 + c * 8;
            cp16(Af + rowA(row) + koff, dA + row * SROW + c * 8);
        }
        {
            int i = tid;  // 256 B segs
            int brw = i >> 4, nseg = i & 15;
            const f16* bsrc = Bf + (size_t)(kt * 16 + brw) * ldb + nseg * 8;
            cp16(bsrc, dB + brw * BROW16 + nseg * 8);
        }
    };
    auto stagep = [&](int p, int bp) {
        stage1(2 * p, 2 * bp);
        stage1(2 * p + 1, 2 * bp + 1);
        asm volatile("cp.async.commit_group;\n");
    };

    const int arow = ((lane >> 3) & 1) * 8 + (lane & 7);
    const int acol = (lane >> 4) * 8;
    const int tkrow = (lane & 7) + ((lane >> 3) & 1) * 8;
    const int tnoff = (lane >> 4) * 8;

    auto compute = [&](int s) {
        const f16* A = sA + s * TA_HALVES;
        const f16* B = sB + s * TBT16_HALVES;
        uint32_t fah[4][4], fb[4][2];
#pragma unroll
        for (int mt = 0; mt < 4; mt++) {
            uint32_t ad = (uint32_t)__cvta_generic_to_shared(
                A + (wm + mt * 16 + arow) * SROW + acol);
            ldm4(fah[mt][0], fah[mt][1], fah[mt][2], fah[mt][3], ad);
        }
#pragma unroll
        for (int p = 0; p < 2; p++) {
            uint32_t bd = (uint32_t)__cvta_generic_to_shared(
                B + tkrow * BROW16 + wn + p * 16 + tnoff);
            ldm4t(fb[2 * p][0], fb[2 * p][1], fb[2 * p + 1][0],
                  fb[2 * p + 1][1], bd);
        }
#pragma unroll
        for (int nt = 0; nt < 4; nt++)
#pragma unroll
            for (int mt = 0; mt < 4; mt++) mma16816f(acc[mt][nt], fah[mt], fb[nt]);
    };

    PIPEP_RUN(stagep, compute, ktiles);
}

// epilogue iterator (8 warps, 64x32)
template <class F>
__device__ __forceinline__ void epi128(float (&acc)[4][4][4], F f) {
    const int lane = threadIdx.x & 31, warp = threadIdx.x >> 5;
    const int wm = (warp >> 2) * 64, wn = (warp & 3) * 32;
    const int gid = lane >> 2, tc = lane & 3;
#pragma unroll
    for (int mt = 0; mt < 4; mt++)
#pragma unroll
        for (int nt = 0; nt < 4; nt++)
#pragma unroll
            for (int r = 0; r < 4; r++) {
                int row = wm + mt * 16 + gid + ((r >> 1) << 3);
                int col = wn + nt * 8 + tc * 2 + (r & 1);
                f(row, col, acc[mt][nt][r]);
            }
}

// fused SiLU epilogue: interleaved [g,u] columns; f(row, act_col, act)
template <class F>
__device__ __forceinline__ void epi128_silu(float (&acc)[4][4][4], F f) {
    const int lane = threadIdx.x & 31, warp = threadIdx.x >> 5;
    const int wm = (warp >> 2) * 64, wn = (warp & 3) * 32;
    const int gid = lane >> 2, tc = lane & 3;
#pragma unroll
    for (int mt = 0; mt < 4; mt++)
#pragma unroll
        for (int nt = 0; nt < 4; nt++) {
            int acol = (wn >> 1) + nt * 4 + tc;
#pragma unroll
            for (int rr = 0; rr < 2; rr++) {
                int row = wm + mt * 16 + gid + rr * 8;
                float g = acc[mt][nt][rr * 2];
                float u = acc[mt][nt][rr * 2 + 1];
                f(row, acol, silu_f(g) * u);
            }
        }
}

// ---------------- streaming splits / zero --------------------------------------
__global__ void k_zero_buf(float* __restrict__ p, int n4) {
    int i = blockIdx.x * 256 + threadIdx.x;
    if (i < n4) reinterpret_cast<float4*>(p)[i] = float4{0.f, 0.f, 0.f, 0.f};
}

__global__ void k_split(const float* __restrict__ src, bf16* __restrict__ dh,
                        bf16* __restrict__ dl, int n8) {
    int i = blockIdx.x * 256 + threadIdx.x;
    if (i >= n8) return;
    const float4* s4 = reinterpret_cast<const float4*>(src) + i * 2;
    float4 a = s4[0], b = s4[1];
    bf16 hbuf[8], lbuf[8];
    split_bf(a.x, hbuf[0], lbuf[0]);
    split_bf(a.y, hbuf[1], lbuf[1]);
    split_bf(a.z, hbuf[2], lbuf[2]);
    split_bf(a.w, hbuf[3], lbuf[3]);
    split_bf(b.x, hbuf[4], lbuf[4]);
    split_bf(b.y, hbuf[5], lbuf[5]);
    split_bf(b.z, hbuf[6], lbuf[6]);
    split_bf(b.w, hbuf[7], lbuf[7]);
    reinterpret_cast<uint4*>(dh)[i] = *reinterpret_cast<uint4*>(hbuf);
    reinterpret_cast<uint4*>(dl)[i] = *reinterpret_cast<uint4*>(lbuf);
}

__global__ void k_split16(const float* __restrict__ src, f16* __restrict__ d,
                          int n8) {
    int i = blockIdx.x * 256 + threadIdx.x;
    if (i >= n8) return;
    const float4* s4 = reinterpret_cast<const float4*>(src) + i * 2;
    float4 a = s4[0], b = s4[1];
    f16 buf[8];
    buf[0] = __float2half(a.x);
    buf[1] = __float2half(a.y);
    buf[2] = __float2half(a.z);
    buf[3] = __float2half(a.w);
    buf[4] = __float2half(b.x);
    buf[5] = __float2half(b.y);
    buf[6] = __float2half(b.z);
    buf[7] = __float2half(b.w);
    reinterpret_cast<uint4*>(d)[i] = *reinterpret_cast<uint4*>(buf);
}

__global__ void k_split16i(const float* __restrict__ src, f16* __restrict__ dst) {
    const int K = H;
    src += (size_t)blockIdx.z * K * 2048;
    dst += (size_t)blockIdx.z * K * 2048;
    int i = blockIdx.x * 256 + threadIdx.x;
    int k = i >> 8, j = i & 255;
    float4 g4 = *reinterpret_cast<const float4*>(src + (size_t)k * 2048 + 4 * j);
    float4 u4 = *reinterpret_cast<const float4*>(src + (size_t)k * 2048 + 1024 + 4 * j);
    f16 buf[8];
    buf[0] = __float2half(g4.x); buf[1] = __float2half(u4.x);
    buf[2] = __float2half(g4.y); buf[3] = __float2half(u4.y);
    buf[4] = __float2half(g4.z); buf[5] = __float2half(u4.z);
    buf[6] = __float2half(g4.w); buf[7] = __float2half(u4.w);
    *reinterpret_cast<uint4*>(dst + (size_t)k * 2048 + 8 * j) =
        *reinterpret_cast<uint4*>(buf);
}

// ---------------- qkv GEMM with fused V split --------------------------------
__global__ __launch_bounds__(256) void k_qkv() {
    const int rb = blockIdx.y * 128, cb = blockIdx.x * 128;
    float acc[4][4][4];
    gemm_core_tr(
        g_hh, g_hl, [&](int m) { return (size_t)(rb + m) * H; }, g_wqkvh + cb,
        g_wqkvl + cb, QKV_N, H / 16, acc);
    epi128(acc, [&](int r, int c, float v) {
        g_qkv[(size_t)(rb + r) * QKV_N + cb + c] = v;
        int vc = cb + c - (NH + NKV) * HD;
        if (vc >= 0) {
            size_t o = (size_t)(rb + r) * (NKV * HD) + vc;
            split_bf(v, g_vh[o], g_vl[o]);
        }
    });
}

// ---------------- generic bf16 GEMM (trans-B) ----------------------------------
__global__ __launch_bounds__(256) void k_gemm(
    const bf16* __restrict__ Ah, const bf16* __restrict__ Al, int sa,
    const bf16* __restrict__ Bh, const bf16* __restrict__ Bl, int ldb,
    float* __restrict__ C, int ldc, int ktiles, const float* __restrict__ addm) {
    const int rb = blockIdx.y * 128, cb = blockIdx.x * 128;
    float acc[4][4][4];
    gemm_core_tr(
        Ah, Al, [&](int m) { return (size_t)(rb + m) * sa; }, Bh + cb, Bl + cb,
        ldb, ktiles, acc);
    epi128(acc, [&](int r, int c, float v) {
        size_t idx = (size_t)(rb + r) * ldc + cb + c;
        if (addm) v += addm[idx];
        C[idx] = v;
    });
}

// ---------------- shared-expert su GEMM + fused SiLU ----------------------------
__global__ __launch_bounds__(256) void k_su() {
    const int rb = blockIdx.y * 128, cb = blockIdx.x * 128;
    float acc[4][4][4];
    gemm_core_16(
        g_h2h, g_h2l, [&](int m) { return (size_t)(rb + m) * H; },
        g_wsguf + cb, 2048, H / 16, acc);
    const int ab = cb >> 1;
    epi128_silu(acc, [&](int r, int ac, float a) {
        size_t o = (size_t)(rb + r) * FDIM + ab + ac;
        split_f16(a, g_ash[o], g_asl[o]);
    });
}

// ---------------- shared-expert down proj, atomic into out ----------------------
__global__ __launch_bounds__(256) void k_sdown(float* __restrict__ outp) {
    const int rb = blockIdx.y * 128, cb = blockIdx.x * 128;
    float acc[4][4][4];
    gemm_core_16(
        g_ash, g_asl, [&](int m) { return (size_t)(rb + m) * FDIM; },
        g_wsdf + cb, H, FDIM / 16, acc);
    epi128(acc, [&](int r, int c, float v) {
        atomicAdd(&outp[(size_t)(rb + r) * H + cb + c], v);
    });
}

// ---------------- add + rmsnorm (ln1) ---------------------------------------------
__global__ void k_add_rms1(const float* __restrict__ hs,
                           const float* __restrict__ res,
                           const float* __restrict__ w) {
    const int t = blockIdx.x, tid = threadIdx.x;
    float2 x[2];
    float ss = 0.f;
#pragma unroll
    for (int i = 0; i < 2; i++) {
        int c = (tid + i * 256) * 2;
        float2 a = *reinterpret_cast<const float2*>(hs + (size_t)t * H + c);
        float2 b = *reinterpret_cast<const float2*>(res + (size_t)t * H + c);
        float2 v = {a.x + b.x, a.y + b.y};
        *reinterpret_cast<float2*>(g_resid + (size_t)t * H + c) = v;
        x[i] = v;
        ss += v.x * v.x + v.y * v.y;
    }
    __shared__ float red[256];
    red[tid] = ss;
    __syncthreads();
    for (int s = 128; s > 0; s >>= 1) {
        if (tid < s) red[tid] += red[tid + s];
        __syncthreads();
    }
    float r = rsqrtf(red[0] / (float)H + 1e-6f);
#pragma unroll
    for (int i = 0; i < 2; i++) {
        int c = (tid + i * 256) * 2;
        bf162 h2, l2;
        split2(x[i].x * r * w[c], x[i].y * r * w[c + 1], h2, l2);
        *reinterpret_cast<bf162*>(g_hh + (size_t)t * H + c) = h2;
        *reinterpret_cast<bf162*>(g_hl + (size_t)t * H + c) = l2;
    }
}

// ---------------- rmsnorm (ln2) -----------------------------------------------------
__global__ void k_rms2(const float* __restrict__ resid2,
                       const float* __restrict__ w) {
    const int t = blockIdx.x, tid = threadIdx.x;
    float2 x[2];
    float ss = 0.f;
#pragma unroll
    for (int i = 0; i < 2; i++) {
        int c = (tid + i * 256) * 2;
        float2 v = *reinterpret_cast<const float2*>(resid2 + (size_t)t * H + c);
        x[i] = v;
        ss += v.x * v.x + v.y * v.y;
    }
    __shared__ float red[256];
    red[tid] = ss;
    __syncthreads();
    for (int s = 128; s > 0; s >>= 1) {
        if (tid < s) red[tid] += red[tid + s];
        __syncthreads();
    }
    float r = rsqrtf(red[0] / (float)H + 1e-6f);
#pragma unroll
    for (int i = 0; i < 2; i++) {
        int c = (tid + i * 256) * 2;
        float v0 = x[i].x * r * w[c], v1 = x[i].y * r * w[c + 1];
        *reinterpret_cast<float2*>(g_h + (size_t)t * H + c) = float2{v0, v1};
        f16 h0, l0, h1, l1;
        split_f16(v0, h0, l0);
        split_f16(v1, h1, l1);
        *reinterpret_cast<__half2*>(g_h2h + (size_t)t * H + c) =
            __halves2half2(h0, h1);
        *reinterpret_cast<__half2*>(g_h2l + (size_t)t * H + c) =
            __halves2half2(l0, l1);
    }
}

// ---------------- per-head rmsnorm + rope -------------------------------------------
__global__ void k_qknorm_rope(const int* __restrict__ pos_ids,
                              const float* __restrict__ qnw,
                              const float* __restrict__ knw) {
    const int t = blockIdx.x, hh = blockIdx.y, d = threadIdx.x;
    const float* src;
    const float* w;
    bf16 *dh, *dl;
    if (hh < NH) {
        src = g_qkv + (size_t)t * QKV_N + hh * HD;
        w = qnw;
        dh = g_qh + ((size_t)t * NH + hh) * HD;
        dl = g_ql + ((size_t)t * NH + hh) * HD;
    } else {
        int kk = hh - NH;
        src = g_qkv + (size_t)t * QKV_N + NH * HD + kk * HD;
        w = knw;
        dh = g_kh + ((size_t)t * NKV + kk) * HD;
        dl = g_kl + ((size_t)t * NKV + kk) * HD;
    }
    float x = src[d];
    float ss = x * x;
#pragma unroll
    for (int o = 16; o > 0; o >>= 1) ss += __shfl_xor_sync(0xffffffffu, ss, o);
    __shared__ float wsum[4];
    if ((d & 31) == 0) wsum[d >> 5] = ss;
    __syncthreads();
    ss = wsum[0] + wsum[1] + wsum[2] + wsum[3];
    float xn = x * rsqrtf(ss / (float)HD + 1e-6f) * w[d];
    __shared__ float xb[HD];
    xb[d] = xn;
    __syncthreads();
    int p = pos_ids[t];
    if (d < 64) {
        float inv = powf(10000.f, -(float)d / 64.f);
        float ang = (float)p * inv;
        float c = cosf(ang), s = sinf(ang);
        float x1 = xb[d], x2 = xb[d + 64];
        split_bf(x1 * c - x2 * s, dh[d], dl[d]);
        split_bf(x2 * c + x1 * s, dh[d + 64], dl[d + 64]);
    }
}

// ---------------- attention scores ----------------------------------------------------
__global__ __launch_bounds__(256) void k_scores() {
    const int jt = blockIdx.x, it = blockIdx.y, h = blockIdx.z;
    if (jt > it) return;
    float acc[4][4][4];
    gemm_core_nt(
        g_qh, g_ql, g_kh, g_kl,
        [&](int m) { return ((size_t)(it * 128 + m) * NH + h) * HD; },
        [&](int n) { return ((size_t)(jt * 128 + n) * NKV + (h >> 2)) * HD; },
        HD / 16, acc);
    const float scale = 0.08838834764831845f;
    float* S = g_scores + (size_t)h * T * T;
    epi128(acc, [&](int r, int c, float v) {
        int i = it * 128 + r;
        int j = jt * 128 + c;
        S[(size_t)i * T + j] = (j <= i) ? v * scale : -3.0e38f;
    });
}

// ---------------- row softmax -> bf16 P -------------------------------------------------
__global__ void k_softmax() {
    const int i = blockIdx.x, h = blockIdx.y, tid = threadIdx.x;
    const float4* S4 =
        reinterpret_cast<const float4*>(g_scores + ((size_t)h * T + i) * T);
    bf162* Ph = reinterpret_cast<bf162*>(g_ph + ((size_t)h * T + i) * T);
    bf162* Pl = reinterpret_cast<bf162*>(g_pl + ((size_t)h * T + i) * T);
    const int n4 = (((i >> 7) + 1) << 7) >> 2;
    __shared__ float4 buf[T / 4];
    __shared__ float red[256];
    float mx = -3.4e38f;
    for (int j = tid; j < n4; j += 256) {
        float4 v = S4[j];
        buf[j] = v;
        mx = fmaxf(fmaxf(mx, fmaxf(v.x, v.y)), fmaxf(v.z, v.w));
    }
    red[tid] = mx;
    __syncthreads();
    for (int s = 128; s > 0; s >>= 1) {
        if (tid < s) red[tid] = fmaxf(red[tid], red[tid + s]);
        __syncthreads();
    }
    mx = red[0];
    __syncthreads();
    float sm = 0.f;
    for (int j = tid; j < n4; j += 256) {
        float4 v = buf[j];
        v.x = expf(v.x - mx);
        v.y = expf(v.y - mx);
        v.z = expf(v.z - mx);
        v.w = expf(v.w - mx);
        buf[j] = v;
        sm += v.x + v.y + v.z + v.w;
    }
    red[tid] = sm;
    __syncthreads();
    for (int s = 128; s > 0; s >>= 1) {
        if (tid < s) red[tid] += red[tid + s];
        __syncthreads();
    }
    float inv = 1.f / red[0];
    for (int j = tid; j < n4; j += 256) {
        float4 v = buf[j];
        bf162 h0, l0, h1, l1;
        split2(v.x * inv, v.y * inv, h0, l0);
        split2(v.z * inv, v.w * inv, h1, l1);
        Ph[j * 2] = h0;
        Ph[j * 2 + 1] = h1;
        Pl[j * 2] = l0;
        Pl[j * 2 + 1] = l1;
    }
}

// ---------------- ctx = P @ V, balanced chunked split-K -------------------------------
__global__ __launch_bounds__(256) void k_ctx_chunk() {
    const int ck = blockIdx.x, it = blockIdx.y, h = blockIdx.z;
    if (ck > it) return;
    float acc[4][4][4];
    const int cb = (h >> 2) * 128;
    const size_t koff = (size_t)ck * 128;
    gemm_core_tr(
        g_ph, g_pl,
        [&](int m) { return ((size_t)h * T + it * 128 + m) * T + koff; },
        g_vh + koff * (NKV * HD) + cb, g_vl + koff * (NKV * HD) + cb, NKV * HD,
        8, acc);
    epi128(acc, [&](int r, int c, float v) {
        atomicAdd(&g_ctxf[(size_t)(it * 128 + r) * (NH * HD) + h * HD + c], v);
    });
}

// fp32 ctx -> bf16 hi/lo
__global__ void k_ctx_split() {
    int i = blockIdx.x * 256 + threadIdx.x;
    if (i >= T * 1024 / 8) return;
    const float4* s4 = reinterpret_cast<const float4*>(g_ctxf) + i * 2;
    float4 a = s4[0], b = s4[1];
    bf16 hbuf[8], lbuf[8];
    split_bf(a.x, hbuf[0], lbuf[0]);
    split_bf(a.y, hbuf[1], lbuf[1]);
    split_bf(a.z, hbuf[2], lbuf[2]);
    split_bf(a.w, hbuf[3], lbuf[3]);
    split_bf(b.x, hbuf[4], lbuf[4]);
    split_bf(b.y, hbuf[5], lbuf[5]);
    split_bf(b.z, hbuf[6], lbuf[6]);
    split_bf(b.w, hbuf[7], lbuf[7]);
    reinterpret_cast<uint4*>(g_ch)[i] = *reinterpret_cast<uint4*>(hbuf);
    reinterpret_cast<uint4*>(g_cl)[i] = *reinterpret_cast<uint4*>(lbuf);
}

// ---------------- gate logits -------------------------------------------------------------
__global__ void k_gate(const float* __restrict__ gw) {
    const int t = blockIdx.x, tid = threadIdx.x;
    const int e = tid & 15, seg = tid >> 4;
    const float* hr = g_h + (size_t)t * H;
    float s = 0.f;
    for (int k = seg * 128; k < seg * 128 + 128; k++) s += hr[k] * gw[k * NE + e];
    __shared__ float red[128];
    red[tid] = s;
    __syncthreads();
    if (tid < NE) {
        float v = 0.f;
        for (int g = 0; g < 8; g++) v += red[g * 16 + tid];
        g_logits[t * NE + tid] = v;
    }
}

// ---------------- routing -------------------------------------------------------------------
__global__ void k_zero_cnt() {
    if (threadIdx.x < NE) g_cnt[threadIdx.x] = 0;
}

__global__ void k_route(const float* __restrict__ bias) {
    const int t = blockIdx.x * 256 + threadIdx.x;
    if (t >= T) return;
    float sig[NE], sfc[NE];
#pragma unroll
    for (int e = 0; e < NE; e++) {
        float l = g_logits[t * NE + e];
        sig[e] = 1.f / (1.f + expf(-l));
        sfc[e] = sig[e] + bias[e];
    }
    float gs[4];
#pragma unroll
    for (int g = 0; g < 4; g++) {
        float m1 = -3.4e38f, m2 = -3.4e38f;
#pragma unroll
        for (int i = 0; i < 4; i++) {
            float v = sfc[g * 4 + i];
            if (v > m1) { m2 = m1; m1 = v; }
            else if (v > m2) m2 = v;
        }
        gs[g] = m1 + m2;
    }
    int g1 = 0;
    for (int g = 1; g < 4; g++) if (gs[g] > gs[g1]) g1 = g;
    int g2 = -1;
    for (int g = 0; g < 4; g++) {
        if (g == g1) continue;
        if (g2 < 0 || gs[g] > gs[g2]) g2 = g;
    }
    bool allowed[NE];
#pragma unroll
    for (int e = 0; e < NE; e++) {
        int g = e >> 2;
        allowed[e] = (g == g1) || (g == g2);
    }
    int sel[4];
    bool picked[NE];
#pragma unroll
    for (int e = 0; e < NE; e++) picked[e] = false;
    float wsum = 0.f;
#pragma unroll
    for (int it = 0; it < 4; it++) {
        int bi = -1;
        float bv = -3.4e38f;
        for (int e = 0; e < NE; e++) {
            if (!allowed[e] || picked[e]) continue;
            if (sfc[e] > bv) { bv = sfc[e]; bi = e; }
        }
        picked[bi] = true;
        sel[it] = bi;
        wsum += sig[bi];
    }
    float inv = 1.f / (wsum + 1e-20f);
#pragma unroll
    for (int it = 0; it < 4; it++) {
        int e = sel[it];
        int pos = atomicAdd(&g_cnt[e], 1);
        g_ptok[e * T + pos] = t;
        g_pw[e * T + pos] = sig[e] * inv;
    }
}

__global__ void k_offsets() {
    if (threadIdx.x == 0) {
        int run = 0;
        for (int e = 0; e < NE; e++) {
            g_poff[e] = run;
            run += ((g_cnt[e] + 127) / 128) * 128;
        }
    }
}

// ---------------- MoE gu GEMM (fp16 1-term A) + fused SiLU -> fp16 act ---------------
__global__ __launch_bounds__(256) void k_moe_gu() {
    const int e = blockIdx.z, rt = blockIdx.y, bn = blockIdx.x;
    const int cnt = g_cnt[e];
    if (rt * 128 >= cnt) return;
    const int off = g_poff[e];
    const int* ptok = g_ptok + e * T;
    const int cb = bn * 128;
    float acc[4][4][4];
    gemm_core_16s(
        g_h2h,
        [&](int m) {
            int lr = rt * 128 + m;
            int tok = ptok[lr < cnt ? lr : cnt - 1];
            return (size_t)tok * H;
        },
        g_w13f + (size_t)e * H * 2048 + cb, 2048, H / 16, acc);
    const int ab = bn * 64;
    epi128_silu(acc, [&](int r, int ac, float a) {
        size_t row = (size_t)off + rt * 128 + r;
        size_t o = row * FDIM + ab + ac;
        split_f16(a, g_amh[o], g_aml[o]);
    });
}

// ---------------- MoE y, scatter-add (fp16 1-term A) ---------------------------------
__global__ __launch_bounds__(256) void k_moe_y(float* __restrict__ outp) {
    const int e = blockIdx.z, rt = blockIdx.y, bn = blockIdx.x;
    const int cnt = g_cnt[e];
    if (rt * 128 >= cnt) return;
    const int off = g_poff[e];
    const int cb = bn * 128;
    float acc[4][4][4];
    gemm_core_16s(
        g_amh, [&](int m) { return ((size_t)off + rt * 128 + m) * FDIM; },
        g_w2f + (size_t)e * FDIM * H + cb, H, FDIM / 16, acc);
    epi128(acc, [&](int r, int c, float v) {
        int lr = rt * 128 + r;
        if (lr >= cnt) return;
        int tok = g_ptok[e * T + lr];
        float w = 2.0f * g_pw[e * T + lr];
        atomicAdd(&outp[(size_t)tok * H + cb + c], w * v);
    });
}

// ---------------- stream/event setup at static init (pre-checkpoint) ------------
struct StreamInit {
    cudaStream_t s2;
    cudaEvent_t evF, evW, evR, evS;
    StreamInit() {
        cudaStreamCreateWithFlags(&s2, cudaStreamNonBlocking);
        cudaEventCreateWithFlags(&evF, cudaEventDisableTiming);
        cudaEventCreateWithFlags(&evW, cudaEventDisableTiming);
        cudaEventCreateWithFlags(&evR, cudaEventDisableTiming);
        cudaEventCreateWithFlags(&evS, cudaEventDisableTiming);
    }
};
static StreamInit g_si;

// ---------------- launch -----------------------------------------------------------------
extern "C" void kernel_launch(void* const* d_in, const int* in_sizes, int n_in,
                              void* d_out, int out_size) {
    const float* hs = (const float*)d_in[0];
    const float* res = (const float*)d_in[1];
    const int* pos = (const int*)d_in[2];
    const float* ln1_w = (const float*)d_in[3];
    const float* qkv_w = (const float*)d_in[4];
    const float* qnorm_w = (const float*)d_in[5];
    const float* knorm_w = (const float*)d_in[6];
    const float* dense_w = (const float*)d_in[7];
    const float* ln2_w = (const float*)d_in[8];
    const float* gate_w = (const float*)d_in[9];
    const float* expert_bias = (const float*)d_in[10];
    const float* w13 = (const float*)d_in[11];
    const float* w2 = (const float*)d_in[12];
    const float* ws_gate_up = (const float*)d_in[13];
    const float* ws_down = (const float*)d_in[14];

    float* out_mlp = (float*)d_out;
    float* out_resid2 = (float*)d_out + (size_t)T * H;

    float* p_resid;  cudaGetSymbolAddress((void**)&p_resid, g_resid);
    float* p_ctxf;   cudaGetSymbolAddress((void**)&p_ctxf, g_ctxf);
    bf16 *p_wqkvh, *p_wqkvl, *p_wdh, *p_wdl, *p_ch, *p_cl;
    f16 *p_w13f, *p_w2f, *p_wsguf, *p_wsdf;
    cudaGetSymbolAddress((void**)&p_wqkvh, g_wqkvh);
    cudaGetSymbolAddress((void**)&p_wqkvl, g_wqkvl);
    cudaGetSymbolAddress((void**)&p_wdh, g_wdh);
    cudaGetSymbolAddress((void**)&p_wdl, g_wdl);
    cudaGetSymbolAddress((void**)&p_ch, g_ch);
    cudaGetSymbolAddress((void**)&p_cl, g_cl);
    cudaGetSymbolAddress((void**)&p_w13f, g_w13f);
    cudaGetSymbolAddress((void**)&p_w2f, g_w2f);
    cudaGetSymbolAddress((void**)&p_wsguf, g_wsguf);
    cudaGetSymbolAddress((void**)&p_wsdf, g_wsdf);

    static bool attrs_set = false;
    if (!attrs_set) {
        cudaFuncSetAttribute(k_qkv, cudaFuncAttributeMaxDynamicSharedMemorySize, GSMEM_TR);
        cudaFuncSetAttribute(k_gemm, cudaFuncAttributeMaxDynamicSharedMemorySize, GSMEM_TR);
        cudaFuncSetAttribute(k_scores, cudaFuncAttributeMaxDynamicSharedMemorySize, GSMEM_NT);
        cudaFuncSetAttribute(k_ctx_chunk, cudaFuncAttributeMaxDynamicSharedMemorySize, GSMEM_TR);
        cudaFuncSetAttribute(k_su, cudaFuncAttributeMaxDynamicSharedMemorySize, GSMEM_16);
        cudaFuncSetAttribute(k_sdown, cudaFuncAttributeMaxDynamicSharedMemorySize, GSMEM_16);
        cudaFuncSetAttribute(k_moe_gu, cudaFuncAttributeMaxDynamicSharedMemorySize, GSMEM_16);
        cudaFuncSetAttribute(k_moe_y, cudaFuncAttributeMaxDynamicSharedMemorySize, GSMEM_16);
        attrs_set = true;
    }

    // fork: MoE/shared weight conversions on side stream
    cudaEventRecord(g_si.evF, 0);
    cudaStreamWaitEvent(g_si.s2, g_si.evF, 0);
    k_split16i<<<dim3(H * 2048 / 8 / 256, 1, NE), 256, 0, g_si.s2>>>(w13, p_w13f);
    k_split16<<<((int)((size_t)NE * FDIM * H / 8) + 255) / 256, 256, 0, g_si.s2>>>(
        w2, p_w2f, (int)((size_t)NE * FDIM * H / 8));
    k_split16i<<<dim3(H * 2048 / 8 / 256, 1, 1), 256, 0, g_si.s2>>>(ws_gate_up, p_wsguf);
    k_split16<<<(FDIM * H / 8 + 255) / 256, 256, 0, g_si.s2>>>(ws_down, p_wsdf,
                                                               FDIM * H / 8);
    cudaEventRecord(g_si.evW, g_si.s2);

    // main: zero accumulation buffers + early weight conversions
    k_zero_buf<<<(T * H / 4 + 255) / 256, 256>>>(out_mlp, T * H / 4);
    k_zero_buf<<<(T * H / 4 + 255) / 256, 256>>>(p_ctxf, T * H / 4);
    k_split<<<(H * QKV_N / 8 + 255) / 256, 256>>>(qkv_w, p_wqkvh, p_wqkvl, H * QKV_N / 8);
    k_split<<<(H * H / 8 + 255) / 256, 256>>>(dense_w, p_wdh, p_wdl, H * H / 8);

    // 1. resid + ln1
    k_add_rms1<<<T, 256>>>(hs, res, ln1_w);
    // 2. qkv GEMM with fused V split
    k_qkv<<<dim3(QKV_N / 128, T / 128), 256, GSMEM_TR>>>();
    // 3. q/k norm + rope
    k_qknorm_rope<<<dim3(T, NH + NKV), 128>>>(pos, qnorm_w, knorm_w);
    // 4. attention
    k_scores<<<dim3(T / 128, T / 128, NH), 256, GSMEM_NT>>>();
    k_softmax<<<dim3(T, NH), 256>>>();
    k_ctx_chunk<<<dim3(T / 128, T / 128, NH), 256, GSMEM_TR>>>();
    k_ctx_split<<<(T * 1024 / 8 + 255) / 256, 256>>>();
    // 7. resid2 = ctx @ dense_w + resid
    k_gemm<<<dim3(H / 128, T / 128), 256, GSMEM_TR>>>(
        p_ch, p_cl, NH * HD, p_wdh, p_wdl, H, out_resid2, H, H / 16, p_resid);
    // 8. h2
    k_rms2<<<T, 256>>>(out_resid2, ln2_w);
    cudaEventRecord(g_si.evR, 0);

    // side stream: shared expert chain
    cudaStreamWaitEvent(g_si.s2, g_si.evR, 0);
    k_su<<<dim3(2048 / 128, T / 128), 256, GSMEM_16, g_si.s2>>>();
    k_sdown<<<dim3(H / 128, T / 128), 256, GSMEM_16, g_si.s2>>>(out_mlp);
    cudaEventRecord(g_si.evS, g_si.s2);

    // main: routing
    k_gate<<<T, 128>>>(gate_w);
    k_zero_cnt<<<1, 32>>>();
    k_route<<<T / 256, 256>>>(expert_bias);
    k_offsets<<<1, 32>>>();

    // join weight conversions, then routed experts
    cudaStreamWaitEvent(0, g_si.evW, 0);
    k_moe_gu<<<dim3(2048 / 128, T / 128, NE), 256, GSMEM_16>>>();
    k_moe_y<<<dim3(H / 128, T / 128, NE), 256, GSMEM_16>>>(out_mlp);

    // join shared-expert chain
    cudaStreamWaitEvent(0, g_si.evS, 0);

    (void)in_sizes; (void)n_in; (void)out_size;
}